// round 2
// baseline (speedup 1.0000x reference)
#include <cuda_runtime.h>
#include <cuda_bf16.h>
#include <cstdint>

// Problem constants
#define BB 2
#define TT 2048
#define CC 1024
#define NH 16
#define NKV 8
#define HD 64
#define BT (BB*TT)          // 4096

// ---------------- scratch (device globals; no allocation allowed) ----------
__device__ float g_qbuf[BT * 1024];            // x @ Wq   [bt, 16*64]
__device__ float g_kbuf[BT * 512];             // x @ Wk   [bt, 8*64]
__device__ float g_vbuf[BT * 512];             // x @ Wv   [bt, 8*64]
__device__ float g_qattn[BB * NH  * TT * HD];  // [b,h,t,d]
__device__ float g_kattn[BB * NKV * TT * HD];  // [b,kh,t,d]
__device__ float g_vattn[BB * NKV * TT * HD];  // [b,kh,t,d]
__device__ float g_ybuf[BT * CC];              // attention out [b,t,h,d]

// ---------------- fp32 SGEMM: C[M,N] = A[M,K] @ B[K,N], all row-major -------
// 64x64 tile, BK=16, 256 threads, 4x4 per-thread microtile, float4 smem.
__global__ __launch_bounds__(256)
void sgemm64(const float* __restrict__ A, const float* __restrict__ Bm,
             float* __restrict__ C, int M, int N, int K)
{
    __shared__ float As[16][68];   // transposed, padded
    __shared__ float Bs[16][64];

    const int tid  = threadIdx.x;
    const int m0   = blockIdx.y * 64;
    const int n0   = blockIdx.x * 64;

    const int arow = tid >> 2, ac4 = tid & 3;     // A tile: 64 rows x 4 float4
    const int brow = tid >> 4, bc4 = tid & 15;    // B tile: 16 rows x 16 float4

    const int tm = (tid >> 4) * 4;
    const int tn = (tid & 15) * 4;

    float acc[4][4];
#pragma unroll
    for (int i = 0; i < 4; i++)
#pragma unroll
        for (int j = 0; j < 4; j++) acc[i][j] = 0.f;

    for (int k0 = 0; k0 < K; k0 += 16) {
        float4 av = *(const float4*)(A + (size_t)(m0 + arow) * K + k0 + ac4 * 4);
        float4 bv = *(const float4*)(Bm + (size_t)(k0 + brow) * N + n0 + bc4 * 4);
        __syncthreads();
        As[ac4 * 4 + 0][arow] = av.x;
        As[ac4 * 4 + 1][arow] = av.y;
        As[ac4 * 4 + 2][arow] = av.z;
        As[ac4 * 4 + 3][arow] = av.w;
        *(float4*)&Bs[brow][bc4 * 4] = bv;
        __syncthreads();
#pragma unroll
        for (int kk = 0; kk < 16; kk++) {
            float4 a = *(float4*)&As[kk][tm];
            float4 b = *(float4*)&Bs[kk][tn];
            acc[0][0] += a.x * b.x; acc[0][1] += a.x * b.y; acc[0][2] += a.x * b.z; acc[0][3] += a.x * b.w;
            acc[1][0] += a.y * b.x; acc[1][1] += a.y * b.y; acc[1][2] += a.y * b.z; acc[1][3] += a.y * b.w;
            acc[2][0] += a.z * b.x; acc[2][1] += a.z * b.y; acc[2][2] += a.z * b.z; acc[2][3] += a.z * b.w;
            acc[3][0] += a.w * b.x; acc[3][1] += a.w * b.y; acc[3][2] += a.w * b.z; acc[3][3] += a.w * b.w;
        }
    }
#pragma unroll
    for (int i = 0; i < 4; i++) {
        *(float4*)(C + (size_t)(m0 + tm + i) * N + n0 + tn) =
            make_float4(acc[i][0], acc[i][1], acc[i][2], acc[i][3]);
    }
}

// ---------------- postprocess: gate+ve, RoPE, rmsnorm, layout transpose -----
// one block (256 thr = 8 warps) per (b,t). warp w: q heads 2w,2w+1 and k head w.
__global__ __launch_bounds__(256)
void postproc(const float* __restrict__ x, const float* __restrict__ ve,
              const float* __restrict__ cosb, const float* __restrict__ sinb,
              const float* __restrict__ Wgate)
{
    const int bt = blockIdx.x;
    const int b = bt >> 11, t = bt & (TT - 1);
    const int tid = threadIdx.x;

    __shared__ float gate[NKV];
    if (tid < NKV) {
        float acc = 0.f;
        const float* xr = x + (size_t)bt * CC;
#pragma unroll
        for (int c = 0; c < 32; c++) acc += xr[c] * Wgate[c * NKV + tid];
        gate[tid] = 2.f / (1.f + expf(-acc));
    }
    __syncthreads();

    // v = v + gate*ve  -> [b,kh,t,d]
    for (int i = tid; i < NKV * HD; i += 256) {
        int h = i >> 6, d = i & 63;
        float vv = g_vbuf[(size_t)bt * 512 + i] + gate[h] * ve[(size_t)bt * 512 + i];
        g_vattn[(((size_t)b * NKV + h) * TT + t) * HD + d] = vv;
    }

    const int w = tid >> 5, lane = tid & 31;
    const float cs = cosb[t * 32 + lane];
    const float sn = sinb[t * 32 + lane];
    const float eps = 1.1920929e-07f;

    // q heads 2w, 2w+1
#pragma unroll
    for (int qi = 0; qi < 2; qi++) {
        int h = 2 * w + qi;
        const float* qr = g_qbuf + (size_t)bt * 1024 + h * HD;
        float x1 = qr[lane], x2 = qr[lane + 32];
        float r1 = x1 * cs + x2 * sn;
        float r2 = -x1 * sn + x2 * cs;
        float ss = r1 * r1 + r2 * r2;
#pragma unroll
        for (int o = 16; o; o >>= 1) ss += __shfl_xor_sync(0xffffffffu, ss, o);
        float sc = rsqrtf(ss * (1.f / 64.f) + eps);
        float* qo = g_qattn + (((size_t)b * NH + h) * TT + t) * HD;
        qo[lane] = r1 * sc;
        qo[lane + 32] = r2 * sc;
    }
    // k head w
    {
        const float* kr = g_kbuf + (size_t)bt * 512 + w * HD;
        float x1 = kr[lane], x2 = kr[lane + 32];
        float r1 = x1 * cs + x2 * sn;
        float r2 = -x1 * sn + x2 * cs;
        float ss = r1 * r1 + r2 * r2;
#pragma unroll
        for (int o = 16; o; o >>= 1) ss += __shfl_xor_sync(0xffffffffu, ss, o);
        float sc = rsqrtf(ss * (1.f / 64.f) + eps);
        float* ko = g_kattn + (((size_t)b * NKV + w) * TT + t) * HD;
        ko[lane] = r1 * sc;
        ko[lane + 32] = r2 * sc;
    }
}

// ---------------- flash attention, fp32, BM=64 q rows, BN=32 k cols ---------
// 128 threads: thread -> (row m = tid>>1, half = tid&1).
// S ownership: 16 cols each. O ownership: 32 dims each. Online softmax per row
// tracked redundantly (identically) by both threads of a pair.
__global__ __launch_bounds__(128)
void attn_kernel(const int* __restrict__ wptr)
{
    const int qt0 = blockIdx.x * 64;
    const int bh = blockIdx.y;
    const int b = bh >> 4, h = bh & 15;
    const int window = *wptr;
    const bool is_local = (h >= 8);
    const int kvh = is_local ? 4 + ((h - 8) >> 1) : (h >> 1);

    const float* qbase = g_qattn + (((size_t)b * NH + h) * TT) * HD;
    const float* kbase = g_kattn + (((size_t)b * NKV + kvh) * TT) * HD;
    const float* vbase = g_vattn + (((size_t)b * NKV + kvh) * TT) * HD;

    __shared__ float Qs[64][68];
    __shared__ float Ks[32][64];
    __shared__ float Vs[32][64];
    __shared__ float Ss[64][32];

    const int tid = threadIdx.x;
    const int m = tid >> 1;
    const int half = tid & 1;
    const int n0 = half * 16;
    const int d0 = half * 32;

    // load Q tile (64x64) as float4
    for (int i = tid; i < 64 * 16; i += 128) {
        int mm = i >> 4, c4 = i & 15;
        *(float4*)&Qs[mm][c4 * 4] =
            *(const float4*)(qbase + (size_t)(qt0 + mm) * HD + c4 * 4);
    }

    float o[32];
#pragma unroll
    for (int i = 0; i < 32; i++) o[i] = 0.f;
    float m_i = -1e30f, l_i = 0.f;

    int t0 = 0;
    if (is_local) {
        int s = qt0 - window;
        t0 = (s > 0 ? s : 0) & ~31;
    }
    const float scale = 0.125f;  // 1/sqrt(64)
    const int i_glob = qt0 + m;

    __syncthreads();

    // FIX: must cover key tiles up to qt0+32 so rows 32..63 see keys qt0+32..qt0+63
    for (int kt = t0; kt <= qt0 + 32; kt += 32) {
        // load K,V tiles 32x64
        for (int i = tid; i < 32 * 16; i += 128) {
            int n = i >> 4, c4 = i & 15;
            *(float4*)&Ks[n][c4 * 4] = *(const float4*)(kbase + (size_t)(kt + n) * HD + c4 * 4);
            *(float4*)&Vs[n][c4 * 4] = *(const float4*)(vbase + (size_t)(kt + n) * HD + c4 * 4);
        }
        __syncthreads();

        // S = Q K^T for this thread's 16 columns
        float acc[16];
#pragma unroll
        for (int i = 0; i < 16; i++) acc[i] = 0.f;
#pragma unroll 4
        for (int dc = 0; dc < 16; dc++) {
            float4 qv = *(float4*)&Qs[m][dc * 4];
#pragma unroll
            for (int n = 0; n < 16; n++) {
                float4 kv = *(float4*)&Ks[n0 + n][dc * 4];
                acc[n] += qv.x * kv.x + qv.y * kv.y + qv.z * kv.z + qv.w * kv.w;
            }
        }
#pragma unroll
        for (int n = 0; n < 16; n++) {
            int j = kt + n0 + n;
            bool ok = (j <= i_glob) && (!is_local || j >= i_glob - window);
            Ss[m][n0 + n] = ok ? acc[n] * scale : -1e30f;
        }
        __syncthreads();

        // online softmax + PV (both pair threads compute identical row stats)
        float tmax = -1e30f;
#pragma unroll
        for (int n = 0; n < 32; n++) tmax = fmaxf(tmax, Ss[m][n]);
        float mnew = fmaxf(m_i, tmax);
        float corr = __expf(m_i - mnew);
        m_i = mnew;
#pragma unroll
        for (int i = 0; i < 32; i++) o[i] *= corr;
        float psum = 0.f;
        for (int n = 0; n < 32; n++) {
            float p = __expf(Ss[m][n] - mnew);
            psum += p;
            const float* vr = &Vs[n][d0];
#pragma unroll
            for (int i = 0; i < 32; i += 4) {
                float4 vv = *(const float4*)&vr[i];
                o[i + 0] += p * vv.x;
                o[i + 1] += p * vv.y;
                o[i + 2] += p * vv.z;
                o[i + 3] += p * vv.w;
            }
        }
        l_i = l_i * corr + psum;
        __syncthreads();
    }

    // write out: y layout [b, t, h, d]
    float inv = 1.f / l_i;
    float* yo = g_ybuf + (((size_t)(b * TT + qt0 + m)) * NH + h) * HD + d0;
#pragma unroll
    for (int i = 0; i < 32; i += 4) {
        *(float4*)&yo[i] = make_float4(o[i] * inv, o[i + 1] * inv, o[i + 2] * inv, o[i + 3] * inv);
    }
}

// ---------------- launch --------------------------------------------------
extern "C" void kernel_launch(void* const* d_in, const int* in_sizes, int n_in,
                              void* d_out, int out_size)
{
    const float* x     = (const float*)d_in[0];
    const float* ve    = (const float*)d_in[1];
    const float* cosb  = (const float*)d_in[2];
    const float* sinb  = (const float*)d_in[3];
    const float* Wq    = (const float*)d_in[4];
    const float* Wk    = (const float*)d_in[5];
    const float* Wv    = (const float*)d_in[6];
    const float* Wproj = (const float*)d_in[7];
    const float* Wgate = (const float*)d_in[8];
    const int*   wptr  = (const int*)d_in[9];

    float *qbuf, *kbuf, *vbuf, *ybuf;
    cudaGetSymbolAddress((void**)&qbuf, g_qbuf);
    cudaGetSymbolAddress((void**)&kbuf, g_kbuf);
    cudaGetSymbolAddress((void**)&vbuf, g_vbuf);
    cudaGetSymbolAddress((void**)&ybuf, g_ybuf);

    // QKV projections
    sgemm64<<<dim3(1024 / 64, BT / 64), 256>>>(x, Wq, qbuf, BT, 1024, CC);
    sgemm64<<<dim3(512 / 64,  BT / 64), 256>>>(x, Wk, kbuf, BT, 512, CC);
    sgemm64<<<dim3(512 / 64,  BT / 64), 256>>>(x, Wv, vbuf, BT, 512, CC);

    // gate + ve, rope, rmsnorm, transpose
    postproc<<<BT, 256>>>(x, ve, cosb, sinb, Wgate);

    // attention: grid (q tiles, b*heads)
    attn_kernel<<<dim3(TT / 64, BB * NH), 128>>>(wptr);

    // output projection -> d_out
    sgemm64<<<dim3(1024 / 64, BT / 64), 256>>>(ybuf, Wproj, (float*)d_out, BT, 1024, CC);
}

// round 3
// speedup vs baseline: 1.1771x; 1.1771x over previous
#include <cuda_runtime.h>
#include <cuda_bf16.h>
#include <cstdint>

// Problem constants
#define BB 2
#define TT 2048
#define CC 1024
#define NH 16
#define NKV 8
#define HD 64
#define BT (BB*TT)          // 4096

// ---------------- scratch (device globals; no allocation allowed) ----------
__device__ float g_qbuf[BT * 1024];            // x @ Wq   [bt, 16*64]
__device__ float g_kbuf[BT * 512];             // x @ Wk   [bt, 8*64]
__device__ float g_vbuf[BT * 512];             // x @ Wv   [bt, 8*64]
__device__ float g_qattn[BB * NH  * TT * HD];  // [b,h,t,d]
__device__ float g_kattn[BB * NKV * TT * HD];  // [b,kh,t,d]
__device__ float g_vattn[BB * NKV * TT * HD];  // [b,kh,t,d]
__device__ float g_ybuf[BT * CC];              // attention out [b,t,h,d]

// ---------------- tensor-core GEMM (split-bf16, 3 MMA, fp32 accurate) ------
// C[M,N] = A[M,K] @ B[K,N], row-major. BM=128 BN=128 BK=32, 256 thr, 8 warps.
// x = hi(bf16) + lo(bf16);  A*B ≈ Ahi*Bhi + Alo*Bhi + Ahi*Blo  (fp32 accum)

#define LDSM4(r0,r1,r2,r3,addr) \
    asm volatile("ldmatrix.sync.aligned.m8n8.x4.shared.b16 {%0,%1,%2,%3}, [%4];" \
                 : "=r"(r0),"=r"(r1),"=r"(r2),"=r"(r3) : "r"(addr))
#define LDSM4T(r0,r1,r2,r3,addr) \
    asm volatile("ldmatrix.sync.aligned.m8n8.x4.trans.shared.b16 {%0,%1,%2,%3}, [%4];" \
                 : "=r"(r0),"=r"(r1),"=r"(r2),"=r"(r3) : "r"(addr))
#define MMA16816(d, a, b0, b1) \
    asm volatile("mma.sync.aligned.m16n8k16.row.col.f32.bf16.bf16.f32 " \
                 "{%0,%1,%2,%3}, {%4,%5,%6,%7}, {%8,%9}, {%0,%1,%2,%3};" \
                 : "+f"(d[0]),"+f"(d[1]),"+f"(d[2]),"+f"(d[3]) \
                 : "r"(a[0]),"r"(a[1]),"r"(a[2]),"r"(a[3]), "r"(b0),"r"(b1))

__device__ __forceinline__ uint32_t bpack(__nv_bfloat16 e0, __nv_bfloat16 e1) {
    return ((uint32_t)__bfloat16_as_ushort(e1) << 16) | (uint32_t)__bfloat16_as_ushort(e0);
}

__global__ __launch_bounds__(256)
void gemm_split_bf16(const float* __restrict__ A, const float* __restrict__ Bm,
                     float* __restrict__ C, int M, int N, int K)
{
    __shared__ __nv_bfloat16 Ah[128][40];   // rows padded to 40 (80B) -> conflict-free ldmatrix
    __shared__ __nv_bfloat16 Al[128][40];
    __shared__ __nv_bfloat16 Bh[32][136];   // rows padded to 136 (272B)
    __shared__ __nv_bfloat16 Bl[32][136];

    const int tid = threadIdx.x;
    const int wid = tid >> 5, lane = tid & 31;
    const int warp_m = wid & 1, warp_n = wid >> 1;   // 2 x 4 warps
    const int gid = lane >> 2, tig = lane & 3;
    const int lane15 = lane & 15, lhi8 = (lane >> 4) * 8;
    const int m0 = blockIdx.y * 128, n0 = blockIdx.x * 128;

    const uint32_t sAh = (uint32_t)__cvta_generic_to_shared(&Ah[0][0]);
    const uint32_t sAl = (uint32_t)__cvta_generic_to_shared(&Al[0][0]);
    const uint32_t sBh = (uint32_t)__cvta_generic_to_shared(&Bh[0][0]);
    const uint32_t sBl = (uint32_t)__cvta_generic_to_shared(&Bl[0][0]);

    // global->smem mapping
    const int lm  = tid >> 1;          // A row 0..127
    const int lkh = tid & 1;           // which 16-float k-half
    const int bk  = tid >> 3;          // B row 0..31
    const int bn16 = (tid & 7) * 16;   // B col group

    float acc[4][4][4];
#pragma unroll
    for (int i = 0; i < 4; i++)
#pragma unroll
        for (int j = 0; j < 4; j++)
#pragma unroll
            for (int r = 0; r < 4; r++) acc[i][j][r] = 0.f;

    for (int k0 = 0; k0 < K; k0 += 32) {
        // ---- prefetch to regs
        const float* aptr = A + (size_t)(m0 + lm) * K + k0 + lkh * 16;
        float4 av0 = ((const float4*)aptr)[0];
        float4 av1 = ((const float4*)aptr)[1];
        float4 av2 = ((const float4*)aptr)[2];
        float4 av3 = ((const float4*)aptr)[3];
        const float* bptr = Bm + (size_t)(k0 + bk) * N + n0 + bn16;
        float4 bv0 = ((const float4*)bptr)[0];
        float4 bv1 = ((const float4*)bptr)[1];
        float4 bv2 = ((const float4*)bptr)[2];
        float4 bv3 = ((const float4*)bptr)[3];

        __syncthreads();

        // ---- convert + store A
        {
            float v[16] = {av0.x,av0.y,av0.z,av0.w, av1.x,av1.y,av1.z,av1.w,
                           av2.x,av2.y,av2.z,av2.w, av3.x,av3.y,av3.z,av3.w};
            uint32_t ph[8], pl[8];
#pragma unroll
            for (int j = 0; j < 8; j++) {
                float x0 = v[2*j], x1 = v[2*j+1];
                __nv_bfloat16 h0 = __float2bfloat16(x0), h1 = __float2bfloat16(x1);
                __nv_bfloat16 l0 = __float2bfloat16(x0 - __bfloat162float(h0));
                __nv_bfloat16 l1 = __float2bfloat16(x1 - __bfloat162float(h1));
                ph[j] = bpack(h0, h1); pl[j] = bpack(l0, l1);
            }
            uint4* dh = (uint4*)&Ah[lm][lkh * 16];
            dh[0] = make_uint4(ph[0],ph[1],ph[2],ph[3]);
            dh[1] = make_uint4(ph[4],ph[5],ph[6],ph[7]);
            uint4* dl = (uint4*)&Al[lm][lkh * 16];
            dl[0] = make_uint4(pl[0],pl[1],pl[2],pl[3]);
            dl[1] = make_uint4(pl[4],pl[5],pl[6],pl[7]);
        }
        // ---- convert + store B
        {
            float v[16] = {bv0.x,bv0.y,bv0.z,bv0.w, bv1.x,bv1.y,bv1.z,bv1.w,
                           bv2.x,bv2.y,bv2.z,bv2.w, bv3.x,bv3.y,bv3.z,bv3.w};
            uint32_t ph[8], pl[8];
#pragma unroll
            for (int j = 0; j < 8; j++) {
                float x0 = v[2*j], x1 = v[2*j+1];
                __nv_bfloat16 h0 = __float2bfloat16(x0), h1 = __float2bfloat16(x1);
                __nv_bfloat16 l0 = __float2bfloat16(x0 - __bfloat162float(h0));
                __nv_bfloat16 l1 = __float2bfloat16(x1 - __bfloat162float(h1));
                ph[j] = bpack(h0, h1); pl[j] = bpack(l0, l1);
            }
            uint4* dh = (uint4*)&Bh[bk][bn16];
            dh[0] = make_uint4(ph[0],ph[1],ph[2],ph[3]);
            dh[1] = make_uint4(ph[4],ph[5],ph[6],ph[7]);
            uint4* dl = (uint4*)&Bl[bk][bn16];
            dl[0] = make_uint4(pl[0],pl[1],pl[2],pl[3]);
            dl[1] = make_uint4(pl[4],pl[5],pl[6],pl[7]);
        }
        __syncthreads();

        // ---- compute: 2 k16 steps
#pragma unroll
        for (int ks = 0; ks < 2; ks++) {
            const uint32_t a_off = (uint32_t)((warp_m * 64 + lane15) * 80 + (ks * 16 + lhi8) * 2);
            const uint32_t b_off = (uint32_t)((ks * 16 + lane15) * 272 + (warp_n * 32 + lhi8) * 2);

            uint32_t a[4][4];
            uint32_t bh[2][4], bl[2][4];
#pragma unroll
            for (int mf = 0; mf < 4; mf++)
                LDSM4(a[mf][0],a[mf][1],a[mf][2],a[mf][3], sAh + a_off + (uint32_t)(mf * 16 * 80));
#pragma unroll
            for (int p = 0; p < 2; p++) {
                LDSM4T(bh[p][0],bh[p][1],bh[p][2],bh[p][3], sBh + b_off + (uint32_t)(p * 32));
                LDSM4T(bl[p][0],bl[p][1],bl[p][2],bl[p][3], sBl + b_off + (uint32_t)(p * 32));
            }
            // hi*hi and hi*lo
#pragma unroll
            for (int mf = 0; mf < 4; mf++)
#pragma unroll
                for (int nf = 0; nf < 4; nf++) {
                    const int p = nf >> 1, q = (nf & 1) * 2;
                    MMA16816(acc[mf][nf], a[mf], bh[p][q], bh[p][q+1]);
                    MMA16816(acc[mf][nf], a[mf], bl[p][q], bl[p][q+1]);
                }
            // lo*hi (reload a from Al)
#pragma unroll
            for (int mf = 0; mf < 4; mf++)
                LDSM4(a[mf][0],a[mf][1],a[mf][2],a[mf][3], sAl + a_off + (uint32_t)(mf * 16 * 80));
#pragma unroll
            for (int mf = 0; mf < 4; mf++)
#pragma unroll
                for (int nf = 0; nf < 4; nf++) {
                    const int p = nf >> 1, q = (nf & 1) * 2;
                    MMA16816(acc[mf][nf], a[mf], bh[p][q], bh[p][q+1]);
                }
        }
    }

    // ---- epilogue
#pragma unroll
    for (int mf = 0; mf < 4; mf++) {
#pragma unroll
        for (int nf = 0; nf < 4; nf++) {
            const int row = m0 + warp_m * 64 + mf * 16 + gid;
            const int col = n0 + warp_n * 32 + nf * 8 + tig * 2;
            *(float2*)&C[(size_t)row * N + col] =
                make_float2(acc[mf][nf][0], acc[mf][nf][1]);
            *(float2*)&C[(size_t)(row + 8) * N + col] =
                make_float2(acc[mf][nf][2], acc[mf][nf][3]);
        }
    }
}

// ---------------- postprocess: gate+ve, RoPE, rmsnorm, layout transpose -----
__global__ __launch_bounds__(256)
void postproc(const float* __restrict__ x, const float* __restrict__ ve,
              const float* __restrict__ cosb, const float* __restrict__ sinb,
              const float* __restrict__ Wgate)
{
    const int bt = blockIdx.x;
    const int b = bt >> 11, t = bt & (TT - 1);
    const int tid = threadIdx.x;

    __shared__ float gate[NKV];
    if (tid < NKV) {
        float acc = 0.f;
        const float* xr = x + (size_t)bt * CC;
#pragma unroll
        for (int c = 0; c < 32; c++) acc += xr[c] * Wgate[c * NKV + tid];
        gate[tid] = 2.f / (1.f + expf(-acc));
    }
    __syncthreads();

    for (int i = tid; i < NKV * HD; i += 256) {
        int h = i >> 6, d = i & 63;
        float vv = g_vbuf[(size_t)bt * 512 + i] + gate[h] * ve[(size_t)bt * 512 + i];
        g_vattn[(((size_t)b * NKV + h) * TT + t) * HD + d] = vv;
    }

    const int w = tid >> 5, lane = tid & 31;
    const float cs = cosb[t * 32 + lane];
    const float sn = sinb[t * 32 + lane];
    const float eps = 1.1920929e-07f;

#pragma unroll
    for (int qi = 0; qi < 2; qi++) {
        int h = 2 * w + qi;
        const float* qr = g_qbuf + (size_t)bt * 1024 + h * HD;
        float x1 = qr[lane], x2 = qr[lane + 32];
        float r1 = x1 * cs + x2 * sn;
        float r2 = -x1 * sn + x2 * cs;
        float ss = r1 * r1 + r2 * r2;
#pragma unroll
        for (int o = 16; o; o >>= 1) ss += __shfl_xor_sync(0xffffffffu, ss, o);
        float sc = rsqrtf(ss * (1.f / 64.f) + eps);
        float* qo = g_qattn + (((size_t)b * NH + h) * TT + t) * HD;
        qo[lane] = r1 * sc;
        qo[lane + 32] = r2 * sc;
    }
    {
        const float* kr = g_kbuf + (size_t)bt * 512 + w * HD;
        float x1 = kr[lane], x2 = kr[lane + 32];
        float r1 = x1 * cs + x2 * sn;
        float r2 = -x1 * sn + x2 * cs;
        float ss = r1 * r1 + r2 * r2;
#pragma unroll
        for (int o = 16; o; o >>= 1) ss += __shfl_xor_sync(0xffffffffu, ss, o);
        float sc = rsqrtf(ss * (1.f / 64.f) + eps);
        float* ko = g_kattn + (((size_t)b * NKV + w) * TT + t) * HD;
        ko[lane] = r1 * sc;
        ko[lane + 32] = r2 * sc;
    }
}

// ---------------- flash attention, fp32, BM=64 q rows, BN=32 k cols ---------
__global__ __launch_bounds__(128)
void attn_kernel(const int* __restrict__ wptr)
{
    const int qt0 = blockIdx.x * 64;
    const int bh = blockIdx.y;
    const int b = bh >> 4, h = bh & 15;
    const int window = *wptr;
    const bool is_local = (h >= 8);
    const int kvh = is_local ? 4 + ((h - 8) >> 1) : (h >> 1);

    const float* qbase = g_qattn + (((size_t)b * NH + h) * TT) * HD;
    const float* kbase = g_kattn + (((size_t)b * NKV + kvh) * TT) * HD;
    const float* vbase = g_vattn + (((size_t)b * NKV + kvh) * TT) * HD;

    __shared__ float Qs[64][68];
    __shared__ float Ks[32][64];
    __shared__ float Vs[32][64];
    __shared__ float Ss[64][32];

    const int tid = threadIdx.x;
    const int m = tid >> 1;
    const int half = tid & 1;
    const int n0 = half * 16;
    const int d0 = half * 32;

    for (int i = tid; i < 64 * 16; i += 128) {
        int mm = i >> 4, c4 = i & 15;
        *(float4*)&Qs[mm][c4 * 4] =
            *(const float4*)(qbase + (size_t)(qt0 + mm) * HD + c4 * 4);
    }

    float o[32];
#pragma unroll
    for (int i = 0; i < 32; i++) o[i] = 0.f;
    float m_i = -1e30f, l_i = 0.f;

    int t0 = 0;
    if (is_local) {
        int s = qt0 - window;
        t0 = (s > 0 ? s : 0) & ~31;
    }
    const float scale = 0.125f;
    const int i_glob = qt0 + m;

    __syncthreads();

    for (int kt = t0; kt <= qt0 + 32; kt += 32) {
        for (int i = tid; i < 32 * 16; i += 128) {
            int n = i >> 4, c4 = i & 15;
            *(float4*)&Ks[n][c4 * 4] = *(const float4*)(kbase + (size_t)(kt + n) * HD + c4 * 4);
            *(float4*)&Vs[n][c4 * 4] = *(const float4*)(vbase + (size_t)(kt + n) * HD + c4 * 4);
        }
        __syncthreads();

        float acc[16];
#pragma unroll
        for (int i = 0; i < 16; i++) acc[i] = 0.f;
#pragma unroll 4
        for (int dc = 0; dc < 16; dc++) {
            float4 qv = *(float4*)&Qs[m][dc * 4];
#pragma unroll
            for (int n = 0; n < 16; n++) {
                float4 kv = *(float4*)&Ks[n0 + n][dc * 4];
                acc[n] += qv.x * kv.x + qv.y * kv.y + qv.z * kv.z + qv.w * kv.w;
            }
        }
#pragma unroll
        for (int n = 0; n < 16; n++) {
            int j = kt + n0 + n;
            bool ok = (j <= i_glob) && (!is_local || j >= i_glob - window);
            Ss[m][n0 + n] = ok ? acc[n] * scale : -1e30f;
        }
        __syncthreads();

        float tmax = -1e30f;
#pragma unroll
        for (int n = 0; n < 32; n++) tmax = fmaxf(tmax, Ss[m][n]);
        float mnew = fmaxf(m_i, tmax);
        float corr = __expf(m_i - mnew);
        m_i = mnew;
#pragma unroll
        for (int i = 0; i < 32; i++) o[i] *= corr;
        float psum = 0.f;
        for (int n = 0; n < 32; n++) {
            float p = __expf(Ss[m][n] - mnew);
            psum += p;
            const float* vr = &Vs[n][d0];
#pragma unroll
            for (int i = 0; i < 32; i += 4) {
                float4 vv = *(const float4*)&vr[i];
                o[i + 0] += p * vv.x;
                o[i + 1] += p * vv.y;
                o[i + 2] += p * vv.z;
                o[i + 3] += p * vv.w;
            }
        }
        l_i = l_i * corr + psum;
        __syncthreads();
    }

    float inv = 1.f / l_i;
    float* yo = g_ybuf + (((size_t)(b * TT + qt0 + m)) * NH + h) * HD + d0;
#pragma unroll
    for (int i = 0; i < 32; i += 4) {
        *(float4*)&yo[i] = make_float4(o[i] * inv, o[i + 1] * inv, o[i + 2] * inv, o[i + 3] * inv);
    }
}

// ---------------- launch --------------------------------------------------
extern "C" void kernel_launch(void* const* d_in, const int* in_sizes, int n_in,
                              void* d_out, int out_size)
{
    const float* x     = (const float*)d_in[0];
    const float* ve    = (const float*)d_in[1];
    const float* cosb  = (const float*)d_in[2];
    const float* sinb  = (const float*)d_in[3];
    const float* Wq    = (const float*)d_in[4];
    const float* Wk    = (const float*)d_in[5];
    const float* Wv    = (const float*)d_in[6];
    const float* Wproj = (const float*)d_in[7];
    const float* Wgate = (const float*)d_in[8];
    const int*   wptr  = (const int*)d_in[9];

    float *qbuf, *kbuf, *vbuf, *ybuf;
    cudaGetSymbolAddress((void**)&qbuf, g_qbuf);
    cudaGetSymbolAddress((void**)&kbuf, g_kbuf);
    cudaGetSymbolAddress((void**)&vbuf, g_vbuf);
    cudaGetSymbolAddress((void**)&ybuf, g_ybuf);

    // QKV projections (tensor core, split-bf16)
    gemm_split_bf16<<<dim3(1024 / 128, BT / 128), 256>>>(x, Wq, qbuf, BT, 1024, CC);
    gemm_split_bf16<<<dim3(512 / 128,  BT / 128), 256>>>(x, Wk, kbuf, BT, 512, CC);
    gemm_split_bf16<<<dim3(512 / 128,  BT / 128), 256>>>(x, Wv, vbuf, BT, 512, CC);

    // gate + ve, rope, rmsnorm, transpose
    postproc<<<BT, 256>>>(x, ve, cosb, sinb, Wgate);

    // attention
    attn_kernel<<<dim3(TT / 64, BB * NH), 128>>>(wptr);

    // output projection -> d_out
    gemm_split_bf16<<<dim3(1024 / 128, BT / 128), 256>>>(ybuf, Wproj, (float*)d_out, BT, 1024, CC);
}

// round 4
// speedup vs baseline: 3.8895x; 3.3044x over previous
#include <cuda_runtime.h>
#include <cuda_bf16.h>
#include <cstdint>

// Problem constants
#define BB 2
#define TT 2048
#define CC 1024
#define NH 16
#define NKV 8
#define HD 64
#define BT (BB*TT)          // 4096

// ---------------- scratch (device globals; no allocation allowed) ----------
__device__ float g_qbuf[BT * 1024];            // x @ Wq   fp32
__device__ float g_kbuf[BT * 512];
__device__ float g_vbuf[BT * 512];

__device__ __nv_bfloat16 g_xh[BT * CC],  g_xl[BT * CC];
__device__ __nv_bfloat16 g_wqh[CC * 1024], g_wql[CC * 1024];
__device__ __nv_bfloat16 g_wkh[CC * 512],  g_wkl[CC * 512];
__device__ __nv_bfloat16 g_wvh[CC * 512],  g_wvl[CC * 512];
__device__ __nv_bfloat16 g_wph[CC * CC],   g_wpl[CC * CC];

__device__ __nv_bfloat16 g_qh[BB*NH*TT*HD],  g_ql[BB*NH*TT*HD];    // [b,h,t,d]
__device__ __nv_bfloat16 g_kh[BB*NKV*TT*HD], g_kl[BB*NKV*TT*HD];   // [b,kh,t,d]
__device__ __nv_bfloat16 g_vh[BB*NKV*TT*HD], g_vl[BB*NKV*TT*HD];
__device__ __nv_bfloat16 g_yh[BT * CC], g_yl[BT * CC];             // attn out [bt, h*d]

// ---------------- PTX helpers ----------------------------------------------
#define LDSM4(r0,r1,r2,r3,addr) \
    asm volatile("ldmatrix.sync.aligned.m8n8.x4.shared.b16 {%0,%1,%2,%3}, [%4];" \
                 : "=r"(r0),"=r"(r1),"=r"(r2),"=r"(r3) : "r"(addr))
#define LDSM4T(r0,r1,r2,r3,addr) \
    asm volatile("ldmatrix.sync.aligned.m8n8.x4.trans.shared.b16 {%0,%1,%2,%3}, [%4];" \
                 : "=r"(r0),"=r"(r1),"=r"(r2),"=r"(r3) : "r"(addr))
#define MMA16816(d, a, b0, b1) \
    asm volatile("mma.sync.aligned.m16n8k16.row.col.f32.bf16.bf16.f32 " \
                 "{%0,%1,%2,%3}, {%4,%5,%6,%7}, {%8,%9}, {%0,%1,%2,%3};" \
                 : "+f"(d[0]),"+f"(d[1]),"+f"(d[2]),"+f"(d[3]) \
                 : "r"(a[0]),"r"(a[1]),"r"(a[2]),"r"(a[3]), "r"(b0),"r"(b1))
#define CP16(dst, src) \
    asm volatile("cp.async.cg.shared.global [%0], [%1], 16;" :: "r"(dst), "l"(src))
#define CP_COMMIT asm volatile("cp.async.commit_group;")
#define CP_WAIT(N) asm volatile("cp.async.wait_group %0;" :: "n"(N))

__device__ __forceinline__ uint32_t bpack(__nv_bfloat16 e0, __nv_bfloat16 e1) {
    return ((uint32_t)__bfloat16_as_ushort(e1) << 16) | (uint32_t)__bfloat16_as_ushort(e0);
}
__device__ __forceinline__ void split2(float x0, float x1, uint32_t& h, uint32_t& l) {
    __nv_bfloat16 h0 = __float2bfloat16(x0), h1 = __float2bfloat16(x1);
    h = bpack(h0, h1);
    l = bpack(__float2bfloat16(x0 - __bfloat162float(h0)),
              __float2bfloat16(x1 - __bfloat162float(h1)));
}

// ---------------- split conversion: float -> (hi, lo) bf16 ------------------
__global__ __launch_bounds__(256)
void split_convert(const float* __restrict__ src, __nv_bfloat16* __restrict__ hi,
                   __nv_bfloat16* __restrict__ lo, int n)
{
    int step = gridDim.x * blockDim.x * 4;
    for (int i = (blockIdx.x * blockDim.x + threadIdx.x) * 4; i < n; i += step) {
        float4 v = *(const float4*)(src + i);
        uint32_t h0, l0, h1, l1;
        split2(v.x, v.y, h0, l0);
        split2(v.z, v.w, h1, l1);
        *(uint2*)(hi + i) = make_uint2(h0, h1);
        *(uint2*)(lo + i) = make_uint2(l0, l1);
    }
}

// ---------------- GEMM (pre-split bf16 in, fp32 out) ------------------------
// C[M,N] = (Ah+Al)(Bh+Bl) ~ Ah*Bh + Al*Bh + Ah*Bl.  BM=128 BN=128 BK=32.
// cp.async double-buffered.  256 threads, 8 warps (2x4), warp tile 64x32.
#define GSTAGE 37888
// stage layout: Ah @0 (128x40x2=10240), Al @10240, Bh @20480 (32x136x2=8704), Bl @29184

__global__ __launch_bounds__(256)
void gemm_bf16split(const __nv_bfloat16* __restrict__ Ahg, const __nv_bfloat16* __restrict__ Alg,
                    const __nv_bfloat16* __restrict__ Bhg, const __nv_bfloat16* __restrict__ Blg,
                    float* __restrict__ C, int M, int N, int K)
{
    extern __shared__ char sm[];
    const int tid = threadIdx.x;
    const int lane = tid & 31, wid = tid >> 5;
    const int warp_m = wid & 1, warp_n = wid >> 1;
    const int gid = lane >> 2, tig = lane & 3;
    const int lane15 = lane & 15, lhi8 = (lane >> 4) * 8;
    const int m0 = blockIdx.y * 128, n0 = blockIdx.x * 128;
    const uint32_t sb = (uint32_t)__cvta_generic_to_shared(sm);

    const int cc0 = tid * 2;
    const int ar = cc0 >> 2, ac = cc0 & 3;    // A: row, 16B-chunk (4/row)
    const int br = cc0 >> 4, bc = cc0 & 15;   // B: row, 16B-chunk (16/row)

    float acc[4][4][4];
#pragma unroll
    for (int i = 0; i < 4; i++)
#pragma unroll
        for (int j = 0; j < 4; j++)
#pragma unroll
            for (int r = 0; r < 4; r++) acc[i][j][r] = 0.f;

#define GEMM_LOAD(stg, k0) do { \
    uint32_t s_ = sb + (stg) * GSTAGE; \
    const __nv_bfloat16* p_; \
    p_ = Ahg + (size_t)(m0 + ar) * K + (k0) + ac * 8; \
    CP16(s_ + ar*80 + ac*16, p_); CP16(s_ + ar*80 + ac*16 + 16, p_ + 8); \
    p_ = Alg + (size_t)(m0 + ar) * K + (k0) + ac * 8; \
    CP16(s_ + 10240 + ar*80 + ac*16, p_); CP16(s_ + 10240 + ar*80 + ac*16 + 16, p_ + 8); \
    p_ = Bhg + (size_t)((k0) + br) * N + n0 + bc * 8; \
    CP16(s_ + 20480 + br*272 + bc*16, p_); CP16(s_ + 20480 + br*272 + bc*16 + 16, p_ + 8); \
    p_ = Blg + (size_t)((k0) + br) * N + n0 + bc * 8; \
    CP16(s_ + 29184 + br*272 + bc*16, p_); CP16(s_ + 29184 + br*272 + bc*16 + 16, p_ + 8); \
    CP_COMMIT; \
} while (0)

    const int ktiles = K >> 5;
    GEMM_LOAD(0, 0);

    for (int t = 0; t < ktiles; t++) {
        const int buf = t & 1;
        if (t + 1 < ktiles) { GEMM_LOAD(buf ^ 1, (t + 1) * 32); CP_WAIT(1); }
        else                { CP_WAIT(0); }
        __syncthreads();

        const uint32_t sAh = sb + buf * GSTAGE;
        const uint32_t sAl = sAh + 10240;
        const uint32_t sBh = sAh + 20480;
        const uint32_t sBl = sAh + 29184;

#pragma unroll
        for (int ks = 0; ks < 2; ks++) {
            const uint32_t a_off = (uint32_t)((warp_m * 64 + lane15) * 80 + (ks * 16 + lhi8) * 2);
            const uint32_t b_off = (uint32_t)((ks * 16 + lane15) * 272 + (warp_n * 32 + lhi8) * 2);

            uint32_t a[4][4];
            uint32_t bh[2][4], bl[2][4];
#pragma unroll
            for (int mf = 0; mf < 4; mf++)
                LDSM4(a[mf][0],a[mf][1],a[mf][2],a[mf][3], sAh + a_off + (uint32_t)(mf * 16 * 80));
#pragma unroll
            for (int p = 0; p < 2; p++) {
                LDSM4T(bh[p][0],bh[p][1],bh[p][2],bh[p][3], sBh + b_off + (uint32_t)(p * 32));
                LDSM4T(bl[p][0],bl[p][1],bl[p][2],bl[p][3], sBl + b_off + (uint32_t)(p * 32));
            }
#pragma unroll
            for (int mf = 0; mf < 4; mf++)
#pragma unroll
                for (int nf = 0; nf < 4; nf++) {
                    const int p = nf >> 1, q = (nf & 1) * 2;
                    MMA16816(acc[mf][nf], a[mf], bh[p][q], bh[p][q+1]);
                    MMA16816(acc[mf][nf], a[mf], bl[p][q], bl[p][q+1]);
                }
#pragma unroll
            for (int mf = 0; mf < 4; mf++)
                LDSM4(a[mf][0],a[mf][1],a[mf][2],a[mf][3], sAl + a_off + (uint32_t)(mf * 16 * 80));
#pragma unroll
            for (int mf = 0; mf < 4; mf++)
#pragma unroll
                for (int nf = 0; nf < 4; nf++) {
                    const int p = nf >> 1, q = (nf & 1) * 2;
                    MMA16816(acc[mf][nf], a[mf], bh[p][q], bh[p][q+1]);
                }
        }
        __syncthreads();
    }

#pragma unroll
    for (int mf = 0; mf < 4; mf++) {
#pragma unroll
        for (int nf = 0; nf < 4; nf++) {
            const int row = m0 + warp_m * 64 + mf * 16 + gid;
            const int col = n0 + warp_n * 32 + nf * 8 + tig * 2;
            *(float2*)&C[(size_t)row * N + col] = make_float2(acc[mf][nf][0], acc[mf][nf][1]);
            *(float2*)&C[(size_t)(row + 8) * N + col] = make_float2(acc[mf][nf][2], acc[mf][nf][3]);
        }
    }
}

// ---------------- postprocess: gate+ve, RoPE, rmsnorm, split-bf16 out -------
__global__ __launch_bounds__(256)
void postproc(const float* __restrict__ x, const float* __restrict__ ve,
              const float* __restrict__ cosb, const float* __restrict__ sinb,
              const float* __restrict__ Wgate)
{
    const int bt = blockIdx.x;
    const int b = bt >> 11, t = bt & (TT - 1);
    const int tid = threadIdx.x;

    __shared__ float gate[NKV];
    if (tid < NKV) {
        float acc = 0.f;
        const float* xr = x + (size_t)bt * CC;
#pragma unroll
        for (int c = 0; c < 32; c++) acc += xr[c] * Wgate[c * NKV + tid];
        gate[tid] = 2.f / (1.f + expf(-acc));
    }
    __syncthreads();

    for (int i = tid; i < NKV * HD; i += 256) {
        int hh = i >> 6, d = i & 63;
        float vv = g_vbuf[(size_t)bt * 512 + i] + gate[hh] * ve[(size_t)bt * 512 + i];
        size_t idx = (((size_t)b * NKV + hh) * TT + t) * HD + d;
        __nv_bfloat16 hb = __float2bfloat16(vv);
        g_vh[idx] = hb;
        g_vl[idx] = __float2bfloat16(vv - __bfloat162float(hb));
    }

    const int w = tid >> 5, lane = tid & 31;
    const float cs = cosb[t * 32 + lane];
    const float sn = sinb[t * 32 + lane];
    const float eps = 1.1920929e-07f;

#pragma unroll
    for (int qi = 0; qi < 2; qi++) {
        int h = 2 * w + qi;
        const float* qr = g_qbuf + (size_t)bt * 1024 + h * HD;
        float x1 = qr[lane], x2 = qr[lane + 32];
        float r1 = x1 * cs + x2 * sn;
        float r2 = -x1 * sn + x2 * cs;
        float ss = r1 * r1 + r2 * r2;
#pragma unroll
        for (int o = 16; o; o >>= 1) ss += __shfl_xor_sync(0xffffffffu, ss, o);
        float sc = rsqrtf(ss * (1.f / 64.f) + eps);
        size_t idx = (((size_t)b * NH + h) * TT + t) * HD;
        float v1 = r1 * sc, v2 = r2 * sc;
        __nv_bfloat16 h1 = __float2bfloat16(v1), h2 = __float2bfloat16(v2);
        g_qh[idx + lane] = h1;       g_ql[idx + lane] = __float2bfloat16(v1 - __bfloat162float(h1));
        g_qh[idx + lane + 32] = h2;  g_ql[idx + lane + 32] = __float2bfloat16(v2 - __bfloat162float(h2));
    }
    {
        const float* kr = g_kbuf + (size_t)bt * 512 + w * HD;
        float x1 = kr[lane], x2 = kr[lane + 32];
        float r1 = x1 * cs + x2 * sn;
        float r2 = -x1 * sn + x2 * cs;
        float ss = r1 * r1 + r2 * r2;
#pragma unroll
        for (int o = 16; o; o >>= 1) ss += __shfl_xor_sync(0xffffffffu, ss, o);
        float sc = rsqrtf(ss * (1.f / 64.f) + eps);
        size_t idx = (((size_t)b * NKV + w) * TT + t) * HD;
        float v1 = r1 * sc, v2 = r2 * sc;
        __nv_bfloat16 h1 = __float2bfloat16(v1), h2 = __float2bfloat16(v2);
        g_kh[idx + lane] = h1;       g_kl[idx + lane] = __float2bfloat16(v1 - __bfloat162float(h1));
        g_kh[idx + lane + 32] = h2;  g_kl[idx + lane + 32] = __float2bfloat16(v2 - __bfloat162float(h2));
    }
}

// ---------------- tensor-core flash attention (split-bf16) ------------------
// BM=64, BN=64, 4 warps (16 q-rows each).  Scores & PV each: 3 MMAs (hi/lo).
#define ASTAGE 9216    // 64 rows x 72 bf16
// smem: Qh 0, Ql 9216, Kh 18432, Kl 27648, Vh 36864, Vl 46080  (total 55296)

__global__ __launch_bounds__(128)
void attn_mma(const int* __restrict__ wptr)
{
    extern __shared__ char sm[];
    const uint32_t sb = (uint32_t)__cvta_generic_to_shared(sm);
    const uint32_t sQh = sb, sQl = sb + 9216, sKh = sb + 18432, sKl = sb + 27648,
                   sVh = sb + 36864, sVl = sb + 46080;

    const int qt0 = blockIdx.x * 64;
    const int bh = blockIdx.y;
    const int b = bh >> 4, h = bh & 15;
    const int window = *wptr;
    const bool is_local = (h >= 8);
    const int kvh = is_local ? 4 + ((h - 8) >> 1) : (h >> 1);

    const __nv_bfloat16* qhb = g_qh + ((size_t)(b * NH + h) * TT) * HD;
    const __nv_bfloat16* qlb = g_ql + ((size_t)(b * NH + h) * TT) * HD;
    const __nv_bfloat16* khb = g_kh + ((size_t)(b * NKV + kvh) * TT) * HD;
    const __nv_bfloat16* klb = g_kl + ((size_t)(b * NKV + kvh) * TT) * HD;
    const __nv_bfloat16* vhb = g_vh + ((size_t)(b * NKV + kvh) * TT) * HD;
    const __nv_bfloat16* vlb = g_vl + ((size_t)(b * NKV + kvh) * TT) * HD;

    const int tid = threadIdx.x;
    const int lane = tid & 31, wid = tid >> 5;
    const int gid = lane >> 2, tig = lane & 3;
    const int lane15 = lane & 15, lhi8 = (lane >> 4) * 8;
    const int krow = (lane & 7) | ((lane & 16) >> 1);
    const int kc8 = lane & 8;

    // ---- load Q tiles (hi/lo)
    for (int c = tid; c < 512; c += 128) {
        int row = c >> 3, c8 = c & 7;
        size_t g = (size_t)(qt0 + row) * HD + c8 * 8;
        CP16(sQh + row * 144 + c8 * 16, qhb + g);
        CP16(sQl + row * 144 + c8 * 16, qlb + g);
    }
    CP_COMMIT; CP_WAIT(0);
    __syncthreads();

    // ---- Q fragments (resident)
    uint32_t qhf[4][4], qlf[4][4];
    {
        const uint32_t qa = (uint32_t)((wid * 16 + lane15) * 144 + lhi8 * 2);
#pragma unroll
        for (int ks = 0; ks < 4; ks++) {
            LDSM4(qhf[ks][0],qhf[ks][1],qhf[ks][2],qhf[ks][3], sQh + qa + ks * 32);
            LDSM4(qlf[ks][0],qlf[ks][1],qlf[ks][2],qlf[ks][3], sQl + qa + ks * 32);
        }
    }
    __syncthreads();

    float o[8][4];
#pragma unroll
    for (int nf = 0; nf < 8; nf++)
#pragma unroll
        for (int r = 0; r < 4; r++) o[nf][r] = 0.f;
    float m0r = -1e30f, m1r = -1e30f, l0r = 0.f, l1r = 0.f;

    int t0 = 0;
    if (is_local) { int s = qt0 - window; t0 = (s > 0 ? s : 0) & ~63; }
    const float scale = 0.125f;
    const int i0 = qt0 + wid * 16 + gid, i1 = i0 + 8;

    for (int kt = t0; kt <= qt0; kt += 64) {
        // ---- load K,V tiles (hi/lo)
        for (int c = tid; c < 512; c += 128) {
            int row = c >> 3, c8 = c & 7;
            size_t g = (size_t)(kt + row) * HD + c8 * 8;
            uint32_t d = row * 144 + c8 * 16;
            CP16(sKh + d, khb + g);
            CP16(sKl + d, klb + g);
            CP16(sVh + d, vhb + g);
            CP16(sVl + d, vlb + g);
        }
        CP_COMMIT; CP_WAIT(0);
        __syncthreads();

        // ---- S = Q K^T (split)
        float s[8][4];
#pragma unroll
        for (int nf = 0; nf < 8; nf++)
#pragma unroll
            for (int r = 0; r < 4; r++) s[nf][r] = 0.f;
#pragma unroll
        for (int ks = 0; ks < 4; ks++) {
#pragma unroll
            for (int g = 0; g < 4; g++) {
                const uint32_t ka = (uint32_t)((g * 16 + krow) * 144 + (ks * 16 + kc8) * 2);
                uint32_t b0,b1,b2,b3, c0,c1,c2,c3;
                LDSM4(b0,b1,b2,b3, sKh + ka);
                LDSM4(c0,c1,c2,c3, sKl + ka);
                MMA16816(s[2*g],   qhf[ks], b0, b1);
                MMA16816(s[2*g],   qlf[ks], b0, b1);
                MMA16816(s[2*g],   qhf[ks], c0, c1);
                MMA16816(s[2*g+1], qhf[ks], b2, b3);
                MMA16816(s[2*g+1], qlf[ks], b2, b3);
                MMA16816(s[2*g+1], qhf[ks], c2, c3);
            }
        }

        // ---- mask + scale
#pragma unroll
        for (int nf = 0; nf < 8; nf++) {
            int j0 = kt + nf * 8 + tig * 2, j1 = j0 + 1;
            bool k00 = (j0 <= i0) && (!is_local || j0 >= i0 - window);
            bool k01 = (j1 <= i0) && (!is_local || j1 >= i0 - window);
            bool k10 = (j0 <= i1) && (!is_local || j0 >= i1 - window);
            bool k11 = (j1 <= i1) && (!is_local || j1 >= i1 - window);
            s[nf][0] = k00 ? s[nf][0] * scale : -1e30f;
            s[nf][1] = k01 ? s[nf][1] * scale : -1e30f;
            s[nf][2] = k10 ? s[nf][2] * scale : -1e30f;
            s[nf][3] = k11 ? s[nf][3] * scale : -1e30f;
        }

        // ---- online softmax
        float t0m = -1e30f, t1m = -1e30f;
#pragma unroll
        for (int nf = 0; nf < 8; nf++) {
            t0m = fmaxf(t0m, fmaxf(s[nf][0], s[nf][1]));
            t1m = fmaxf(t1m, fmaxf(s[nf][2], s[nf][3]));
        }
        t0m = fmaxf(t0m, __shfl_xor_sync(0xffffffffu, t0m, 1));
        t0m = fmaxf(t0m, __shfl_xor_sync(0xffffffffu, t0m, 2));
        t1m = fmaxf(t1m, __shfl_xor_sync(0xffffffffu, t1m, 1));
        t1m = fmaxf(t1m, __shfl_xor_sync(0xffffffffu, t1m, 2));
        float mn0 = fmaxf(m0r, t0m), mn1 = fmaxf(m1r, t1m);
        float cr0 = __expf(m0r - mn0), cr1 = __expf(m1r - mn1);
        m0r = mn0; m1r = mn1;

        float ps0 = 0.f, ps1 = 0.f;
#pragma unroll
        for (int nf = 0; nf < 8; nf++) {
            float e0 = __expf(s[nf][0] - mn0), e1 = __expf(s[nf][1] - mn0);
            float e2 = __expf(s[nf][2] - mn1), e3 = __expf(s[nf][3] - mn1);
            ps0 += e0 + e1; ps1 += e2 + e3;
            s[nf][0] = e0; s[nf][1] = e1; s[nf][2] = e2; s[nf][3] = e3;
            o[nf][0] *= cr0; o[nf][1] *= cr0; o[nf][2] *= cr1; o[nf][3] *= cr1;
        }
        ps0 += __shfl_xor_sync(0xffffffffu, ps0, 1);
        ps0 += __shfl_xor_sync(0xffffffffu, ps0, 2);
        ps1 += __shfl_xor_sync(0xffffffffu, ps1, 1);
        ps1 += __shfl_xor_sync(0xffffffffu, ps1, 2);
        l0r = l0r * cr0 + ps0;
        l1r = l1r * cr1 + ps1;

        // ---- pack P (hi/lo) as A fragments
        uint32_t ph[4][4], pl[4][4];
#pragma unroll
        for (int ks = 0; ks < 4; ks++) {
            split2(s[2*ks][0],   s[2*ks][1],   ph[ks][0], pl[ks][0]);
            split2(s[2*ks][2],   s[2*ks][3],   ph[ks][1], pl[ks][1]);
            split2(s[2*ks+1][0], s[2*ks+1][1], ph[ks][2], pl[ks][2]);
            split2(s[2*ks+1][2], s[2*ks+1][3], ph[ks][3], pl[ks][3]);
        }

        // ---- O += P V (split)
#pragma unroll
        for (int ks = 0; ks < 4; ks++) {
#pragma unroll
            for (int g = 0; g < 4; g++) {
                const uint32_t va = (uint32_t)((ks * 16 + lane15) * 144 + (g * 16 + lhi8) * 2);
                uint32_t v0,v1,v2,v3, w0,w1,w2,w3;
                LDSM4T(v0,v1,v2,v3, sVh + va);
                LDSM4T(w0,w1,w2,w3, sVl + va);
                MMA16816(o[2*g],   ph[ks], v0, v1);
                MMA16816(o[2*g],   pl[ks], v0, v1);
                MMA16816(o[2*g],   ph[ks], w0, w1);
                MMA16816(o[2*g+1], ph[ks], v2, v3);
                MMA16816(o[2*g+1], pl[ks], v2, v3);
                MMA16816(o[2*g+1], ph[ks], w2, w3);
            }
        }
        __syncthreads();
    }

    // ---- epilogue: y = O / l, split-bf16, layout [bt, h*64+d]
    const float inv0 = 1.f / l0r, inv1 = 1.f / l1r;
    const int row0 = qt0 + wid * 16 + gid;
#pragma unroll
    for (int nf = 0; nf < 8; nf++) {
        const int col = h * 64 + nf * 8 + tig * 2;
        uint32_t hh, ll;
        split2(o[nf][0] * inv0, o[nf][1] * inv0, hh, ll);
        *(uint32_t*)(g_yh + (size_t)(b * TT + row0) * CC + col) = hh;
        *(uint32_t*)(g_yl + (size_t)(b * TT + row0) * CC + col) = ll;
        split2(o[nf][2] * inv1, o[nf][3] * inv1, hh, ll);
        *(uint32_t*)(g_yh + (size_t)(b * TT + row0 + 8) * CC + col) = hh;
        *(uint32_t*)(g_yl + (size_t)(b * TT + row0 + 8) * CC + col) = ll;
    }
}

// ---------------- launch ----------------------------------------------------
extern "C" void kernel_launch(void* const* d_in, const int* in_sizes, int n_in,
                              void* d_out, int out_size)
{
    const float* x     = (const float*)d_in[0];
    const float* ve    = (const float*)d_in[1];
    const float* cosb  = (const float*)d_in[2];
    const float* sinb  = (const float*)d_in[3];
    const float* Wq    = (const float*)d_in[4];
    const float* Wk    = (const float*)d_in[5];
    const float* Wv    = (const float*)d_in[6];
    const float* Wproj = (const float*)d_in[7];
    const float* Wgate = (const float*)d_in[8];
    const int*   wptr  = (const int*)d_in[9];

    float *qbuf, *kbuf, *vbuf;
    cudaGetSymbolAddress((void**)&qbuf, g_qbuf);
    cudaGetSymbolAddress((void**)&kbuf, g_kbuf);
    cudaGetSymbolAddress((void**)&vbuf, g_vbuf);
    __nv_bfloat16 *xh,*xl,*wqh,*wql,*wkh,*wkl,*wvh,*wvl,*wph,*wpl,*yh,*yl;
    cudaGetSymbolAddress((void**)&xh, g_xh);   cudaGetSymbolAddress((void**)&xl, g_xl);
    cudaGetSymbolAddress((void**)&wqh, g_wqh); cudaGetSymbolAddress((void**)&wql, g_wql);
    cudaGetSymbolAddress((void**)&wkh, g_wkh); cudaGetSymbolAddress((void**)&wkl, g_wkl);
    cudaGetSymbolAddress((void**)&wvh, g_wvh); cudaGetSymbolAddress((void**)&wvl, g_wvl);
    cudaGetSymbolAddress((void**)&wph, g_wph); cudaGetSymbolAddress((void**)&wpl, g_wpl);
    cudaGetSymbolAddress((void**)&yh, g_yh);   cudaGetSymbolAddress((void**)&yl, g_yl);

    cudaFuncSetAttribute(gemm_bf16split, cudaFuncAttributeMaxDynamicSharedMemorySize, 2 * GSTAGE);
    cudaFuncSetAttribute(attn_mma, cudaFuncAttributeMaxDynamicSharedMemorySize, 6 * ASTAGE);

    // split conversions
    split_convert<<<2048, 256>>>(x, xh, xl, BT * CC);
    split_convert<<<1024, 256>>>(Wq, wqh, wql, CC * 1024);
    split_convert<<<512, 256>>>(Wk, wkh, wkl, CC * 512);
    split_convert<<<512, 256>>>(Wv, wvh, wvl, CC * 512);
    split_convert<<<1024, 256>>>(Wproj, wph, wpl, CC * CC);

    // QKV projections
    gemm_bf16split<<<dim3(8, 32), 256, 2 * GSTAGE>>>(xh, xl, wqh, wql, qbuf, BT, 1024, CC);
    gemm_bf16split<<<dim3(4, 32), 256, 2 * GSTAGE>>>(xh, xl, wkh, wkl, kbuf, BT, 512, CC);
    gemm_bf16split<<<dim3(4, 32), 256, 2 * GSTAGE>>>(xh, xl, wvh, wvl, vbuf, BT, 512, CC);

    // gate + ve, rope, rmsnorm -> split-bf16 q/k/v
    postproc<<<BT, 256>>>(x, ve, cosb, sinb, Wgate);

    // attention -> split-bf16 y
    attn_mma<<<dim3(TT / 64, BB * NH), 128, 6 * ASTAGE>>>(wptr);

    // output projection -> d_out
    gemm_bf16split<<<dim3(8, 32), 256, 2 * GSTAGE>>>(yh, yl, wph, wpl, (float*)d_out, BT, 1024, CC);
}

// round 5
// speedup vs baseline: 3.9431x; 1.0138x over previous
#include <cuda_runtime.h>
#include <cuda_bf16.h>
#include <cstdint>

// Problem constants
#define BB 2
#define TT 2048
#define CC 1024
#define NH 16
#define NKV 8
#define HD 64
#define BT (BB*TT)          // 4096

// ---------------- scratch (device globals) ----------------------------------
__device__ float g_qkvbuf[BT * 2048];          // fused [q(1024)|k(512)|v(512)]

__device__ __nv_bfloat16 g_xh[BT * CC],   g_xl[BT * CC];
__device__ __nv_bfloat16 g_wch[CC * 2048], g_wcl[CC * 2048];   // Wq|Wk|Wv combined
__device__ __nv_bfloat16 g_wph[CC * CC],   g_wpl[CC * CC];

__device__ __nv_bfloat16 g_qh[BB*NH*TT*HD],  g_ql[BB*NH*TT*HD];    // [b,h,t,d]
__device__ __nv_bfloat16 g_kh[BB*NKV*TT*HD], g_kl[BB*NKV*TT*HD];   // [b,kh,t,d]
__device__ __nv_bfloat16 g_vh[BB*NKV*TT*HD], g_vl[BB*NKV*TT*HD];
__device__ __nv_bfloat16 g_yh[BT * CC], g_yl[BT * CC];             // attn out [bt, h*d]

// ---------------- PTX helpers ------------------------------------------------
#define LDSM4(r0,r1,r2,r3,addr) \
    asm volatile("ldmatrix.sync.aligned.m8n8.x4.shared.b16 {%0,%1,%2,%3}, [%4];" \
                 : "=r"(r0),"=r"(r1),"=r"(r2),"=r"(r3) : "r"(addr))
#define LDSM4T(r0,r1,r2,r3,addr) \
    asm volatile("ldmatrix.sync.aligned.m8n8.x4.trans.shared.b16 {%0,%1,%2,%3}, [%4];" \
                 : "=r"(r0),"=r"(r1),"=r"(r2),"=r"(r3) : "r"(addr))
#define MMA16816(d, a, b0, b1) \
    asm volatile("mma.sync.aligned.m16n8k16.row.col.f32.bf16.bf16.f32 " \
                 "{%0,%1,%2,%3}, {%4,%5,%6,%7}, {%8,%9}, {%0,%1,%2,%3};" \
                 : "+f"(d[0]),"+f"(d[1]),"+f"(d[2]),"+f"(d[3]) \
                 : "r"(a[0]),"r"(a[1]),"r"(a[2]),"r"(a[3]), "r"(b0),"r"(b1))
#define CP16(dst, src) \
    asm volatile("cp.async.cg.shared.global [%0], [%1], 16;" :: "r"(dst), "l"(src))
#define CP_COMMIT asm volatile("cp.async.commit_group;")
#define CP_WAIT(N) asm volatile("cp.async.wait_group %0;" :: "n"(N))

__device__ __forceinline__ uint32_t bpack(__nv_bfloat16 e0, __nv_bfloat16 e1) {
    return ((uint32_t)__bfloat16_as_ushort(e1) << 16) | (uint32_t)__bfloat16_as_ushort(e0);
}
__device__ __forceinline__ void split2(float x0, float x1, uint32_t& h, uint32_t& l) {
    __nv_bfloat16 h0 = __float2bfloat16(x0), h1 = __float2bfloat16(x1);
    h = bpack(h0, h1);
    l = bpack(__float2bfloat16(x0 - __bfloat162float(h0)),
              __float2bfloat16(x1 - __bfloat162float(h1)));
}

// ---------------- split conversion: float -> (hi, lo) bf16 -------------------
__global__ __launch_bounds__(256)
void split_convert(const float* __restrict__ src, __nv_bfloat16* __restrict__ hi,
                   __nv_bfloat16* __restrict__ lo, int n)
{
    int step = gridDim.x * blockDim.x * 4;
    for (int i = (blockIdx.x * blockDim.x + threadIdx.x) * 4; i < n; i += step) {
        float4 v = *(const float4*)(src + i);
        uint32_t h0, l0, h1, l1;
        split2(v.x, v.y, h0, l0);
        split2(v.z, v.w, h1, l1);
        *(uint2*)(hi + i) = make_uint2(h0, h1);
        *(uint2*)(lo + i) = make_uint2(l0, l1);
    }
}

// strided variant: src [rows, cols] -> dst [rows, dst_stride] at col_off
__global__ __launch_bounds__(256)
void split_convert_str(const float* __restrict__ src, __nv_bfloat16* __restrict__ hi,
                       __nv_bfloat16* __restrict__ lo, int n, int cols,
                       int dst_stride, int col_off)
{
    int step = gridDim.x * blockDim.x * 4;
    for (int i = (blockIdx.x * blockDim.x + threadIdx.x) * 4; i < n; i += step) {
        float4 v = *(const float4*)(src + i);
        uint32_t h0, l0, h1, l1;
        split2(v.x, v.y, h0, l0);
        split2(v.z, v.w, h1, l1);
        int r = i / cols, c = i - r * cols;
        size_t d = (size_t)r * dst_stride + col_off + c;
        *(uint2*)(hi + d) = make_uint2(h0, h1);
        *(uint2*)(lo + d) = make_uint2(l0, l1);
    }
}

// ---------------- GEMM (pre-split bf16 in, fp32 out) -------------------------
// C = Ah*Bh + Al*Bh + Ah*Bl.  BM=128 BN=128 BK=32.  3-stage cp.async pipeline.
#define GSTAGE 37888
// stage: Ah@0 (128x40x2), Al@10240, Bh@20480 (32x136x2), Bl@29184

__global__ __launch_bounds__(256)
void gemm_bf16split(const __nv_bfloat16* __restrict__ Ahg, const __nv_bfloat16* __restrict__ Alg,
                    const __nv_bfloat16* __restrict__ Bhg, const __nv_bfloat16* __restrict__ Blg,
                    float* __restrict__ C, int M, int N, int K)
{
    extern __shared__ char sm[];
    const int tid = threadIdx.x;
    const int lane = tid & 31, wid = tid >> 5;
    const int warp_m = wid & 1, warp_n = wid >> 1;
    const int gid = lane >> 2, tig = lane & 3;
    const int lane15 = lane & 15, lhi8 = (lane >> 4) * 8;
    const int m0 = blockIdx.y * 128, n0 = blockIdx.x * 128;
    const uint32_t sb = (uint32_t)__cvta_generic_to_shared(sm);

    const int cc0 = tid * 2;
    const int ar = cc0 >> 2, ac = cc0 & 3;
    const int br = cc0 >> 4, bc = cc0 & 15;

    float acc[4][4][4];
#pragma unroll
    for (int i = 0; i < 4; i++)
#pragma unroll
        for (int j = 0; j < 4; j++)
#pragma unroll
            for (int r = 0; r < 4; r++) acc[i][j][r] = 0.f;

#define GEMM_LOAD(stg, k0) do { \
    uint32_t s_ = sb + (stg) * GSTAGE; \
    const __nv_bfloat16* p_; \
    p_ = Ahg + (size_t)(m0 + ar) * K + (k0) + ac * 8; \
    CP16(s_ + ar*80 + ac*16, p_); CP16(s_ + ar*80 + ac*16 + 16, p_ + 8); \
    p_ = Alg + (size_t)(m0 + ar) * K + (k0) + ac * 8; \
    CP16(s_ + 10240 + ar*80 + ac*16, p_); CP16(s_ + 10240 + ar*80 + ac*16 + 16, p_ + 8); \
    p_ = Bhg + (size_t)((k0) + br) * N + n0 + bc * 8; \
    CP16(s_ + 20480 + br*272 + bc*16, p_); CP16(s_ + 20480 + br*272 + bc*16 + 16, p_ + 8); \
    p_ = Blg + (size_t)((k0) + br) * N + n0 + bc * 8; \
    CP16(s_ + 29184 + br*272 + bc*16, p_); CP16(s_ + 29184 + br*272 + bc*16 + 16, p_ + 8); \
    CP_COMMIT; \
} while (0)

    const int ktiles = K >> 5;
    GEMM_LOAD(0, 0);
    GEMM_LOAD(1, 32);

    int stg = 0;
    for (int t = 0; t < ktiles; t++) {
        if (t + 1 < ktiles) CP_WAIT(1); else CP_WAIT(0);
        __syncthreads();
        if (t + 2 < ktiles) {
            int ns = stg + 2; if (ns >= 3) ns -= 3;
            GEMM_LOAD(ns, (t + 2) * 32);
        }

        const uint32_t sAh = sb + stg * GSTAGE;
        const uint32_t sAl = sAh + 10240;
        const uint32_t sBh = sAh + 20480;
        const uint32_t sBl = sAh + 29184;

#pragma unroll
        for (int ks = 0; ks < 2; ks++) {
            const uint32_t a_off = (uint32_t)((warp_m * 64 + lane15) * 80 + (ks * 16 + lhi8) * 2);
            const uint32_t b_off = (uint32_t)((ks * 16 + lane15) * 272 + (warp_n * 32 + lhi8) * 2);

            uint32_t a[4][4];
            uint32_t bh[2][4], bl[2][4];
#pragma unroll
            for (int mf = 0; mf < 4; mf++)
                LDSM4(a[mf][0],a[mf][1],a[mf][2],a[mf][3], sAh + a_off + (uint32_t)(mf * 16 * 80));
#pragma unroll
            for (int p = 0; p < 2; p++) {
                LDSM4T(bh[p][0],bh[p][1],bh[p][2],bh[p][3], sBh + b_off + (uint32_t)(p * 32));
                LDSM4T(bl[p][0],bl[p][1],bl[p][2],bl[p][3], sBl + b_off + (uint32_t)(p * 32));
            }
#pragma unroll
            for (int mf = 0; mf < 4; mf++)
#pragma unroll
                for (int nf = 0; nf < 4; nf++) {
                    const int p = nf >> 1, q = (nf & 1) * 2;
                    MMA16816(acc[mf][nf], a[mf], bh[p][q], bh[p][q+1]);
                    MMA16816(acc[mf][nf], a[mf], bl[p][q], bl[p][q+1]);
                }
#pragma unroll
            for (int mf = 0; mf < 4; mf++)
                LDSM4(a[mf][0],a[mf][1],a[mf][2],a[mf][3], sAl + a_off + (uint32_t)(mf * 16 * 80));
#pragma unroll
            for (int mf = 0; mf < 4; mf++)
#pragma unroll
                for (int nf = 0; nf < 4; nf++) {
                    const int p = nf >> 1, q = (nf & 1) * 2;
                    MMA16816(acc[mf][nf], a[mf], bh[p][q], bh[p][q+1]);
                }
        }
        stg++; if (stg == 3) stg = 0;
    }

#pragma unroll
    for (int mf = 0; mf < 4; mf++) {
#pragma unroll
        for (int nf = 0; nf < 4; nf++) {
            const int row = m0 + warp_m * 64 + mf * 16 + gid;
            const int col = n0 + warp_n * 32 + nf * 8 + tig * 2;
            *(float2*)&C[(size_t)row * N + col] = make_float2(acc[mf][nf][0], acc[mf][nf][1]);
            *(float2*)&C[(size_t)(row + 8) * N + col] = make_float2(acc[mf][nf][2], acc[mf][nf][3]);
        }
    }
}

// ---------------- postprocess: gate+ve, RoPE, rmsnorm, split-bf16 out --------
__global__ __launch_bounds__(256)
void postproc(const float* __restrict__ x, const float* __restrict__ ve,
              const float* __restrict__ cosb, const float* __restrict__ sinb,
              const float* __restrict__ Wgate)
{
    const int bt = blockIdx.x;
    const int b = bt >> 11, t = bt & (TT - 1);
    const int tid = threadIdx.x;
    const float* qkv = g_qkvbuf + (size_t)bt * 2048;

    __shared__ float gate[NKV];
    if (tid < NKV) {
        float acc = 0.f;
        const float* xr = x + (size_t)bt * CC;
#pragma unroll
        for (int c = 0; c < 32; c++) acc += xr[c] * Wgate[c * NKV + tid];
        gate[tid] = 2.f / (1.f + expf(-acc));
    }
    __syncthreads();

    for (int i = tid; i < NKV * HD; i += 256) {
        int hh = i >> 6, d = i & 63;
        float vv = qkv[1536 + i] + gate[hh] * ve[(size_t)bt * 512 + i];
        size_t idx = (((size_t)b * NKV + hh) * TT + t) * HD + d;
        __nv_bfloat16 hb = __float2bfloat16(vv);
        g_vh[idx] = hb;
        g_vl[idx] = __float2bfloat16(vv - __bfloat162float(hb));
    }

    const int w = tid >> 5, lane = tid & 31;
    const float cs = cosb[t * 32 + lane];
    const float sn = sinb[t * 32 + lane];
    const float eps = 1.1920929e-07f;

#pragma unroll
    for (int qi = 0; qi < 2; qi++) {
        int h = 2 * w + qi;
        const float* qr = qkv + h * HD;
        float x1 = qr[lane], x2 = qr[lane + 32];
        float r1 = x1 * cs + x2 * sn;
        float r2 = -x1 * sn + x2 * cs;
        float ss = r1 * r1 + r2 * r2;
#pragma unroll
        for (int o = 16; o; o >>= 1) ss += __shfl_xor_sync(0xffffffffu, ss, o);
        float sc = rsqrtf(ss * (1.f / 64.f) + eps);
        size_t idx = (((size_t)b * NH + h) * TT + t) * HD;
        float v1 = r1 * sc, v2 = r2 * sc;
        __nv_bfloat16 h1 = __float2bfloat16(v1), h2 = __float2bfloat16(v2);
        g_qh[idx + lane] = h1;       g_ql[idx + lane] = __float2bfloat16(v1 - __bfloat162float(h1));
        g_qh[idx + lane + 32] = h2;  g_ql[idx + lane + 32] = __float2bfloat16(v2 - __bfloat162float(h2));
    }
    {
        const float* kr = qkv + 1024 + w * HD;
        float x1 = kr[lane], x2 = kr[lane + 32];
        float r1 = x1 * cs + x2 * sn;
        float r2 = -x1 * sn + x2 * cs;
        float ss = r1 * r1 + r2 * r2;
#pragma unroll
        for (int o = 16; o; o >>= 1) ss += __shfl_xor_sync(0xffffffffu, ss, o);
        float sc = rsqrtf(ss * (1.f / 64.f) + eps);
        size_t idx = (((size_t)b * NKV + w) * TT + t) * HD;
        float v1 = r1 * sc, v2 = r2 * sc;
        __nv_bfloat16 h1 = __float2bfloat16(v1), h2 = __float2bfloat16(v2);
        g_kh[idx + lane] = h1;       g_kl[idx + lane] = __float2bfloat16(v1 - __bfloat162float(h1));
        g_kh[idx + lane + 32] = h2;  g_kl[idx + lane + 32] = __float2bfloat16(v2 - __bfloat162float(h2));
    }
}

// ---------------- tensor-core flash attention (split-bf16, pipelined) --------
// BM=64, BN=64, 4 warps. smem: Qh@0, Ql@9216, then 2 stages of {Kh,Kl,Vh,Vl}
// each 9216 at 18432 + stg*36864.  Total 92160.
__global__ __launch_bounds__(128)
void attn_mma(const int* __restrict__ wptr)
{
    extern __shared__ char sm[];
    const uint32_t sb = (uint32_t)__cvta_generic_to_shared(sm);
    const uint32_t sQh = sb, sQl = sb + 9216;

    const int qt0 = (int)(gridDim.x - 1 - blockIdx.x) * 64;   // heavy blocks first
    const int bh = blockIdx.y;
    const int b = bh >> 4, h = bh & 15;
    const int window = *wptr;
    const bool is_local = (h >= 8);
    const int kvh = is_local ? 4 + ((h - 8) >> 1) : (h >> 1);

    const __nv_bfloat16* qhb = g_qh + ((size_t)(b * NH + h) * TT) * HD;
    const __nv_bfloat16* qlb = g_ql + ((size_t)(b * NH + h) * TT) * HD;
    const __nv_bfloat16* khb = g_kh + ((size_t)(b * NKV + kvh) * TT) * HD;
    const __nv_bfloat16* klb = g_kl + ((size_t)(b * NKV + kvh) * TT) * HD;
    const __nv_bfloat16* vhb = g_vh + ((size_t)(b * NKV + kvh) * TT) * HD;
    const __nv_bfloat16* vlb = g_vl + ((size_t)(b * NKV + kvh) * TT) * HD;

    const int tid = threadIdx.x;
    const int lane = tid & 31, wid = tid >> 5;
    const int gid = lane >> 2, tig = lane & 3;
    const int lane15 = lane & 15, lhi8 = (lane >> 4) * 8;
    const int krow = (lane & 7) | ((lane & 16) >> 1);
    const int kc8 = lane & 8;

#define ATT_LOAD(stg, ktv) do { \
    uint32_t base_ = sb + 18432 + (stg) * 36864; \
    for (int c = tid; c < 512; c += 128) { \
        int row_ = c >> 3, c8_ = c & 7; \
        size_t g_ = (size_t)((ktv) + row_) * HD + c8_ * 8; \
        uint32_t d_ = base_ + row_ * 144 + c8_ * 16; \
        CP16(d_, khb + g_); CP16(d_ + 9216, klb + g_); \
        CP16(d_ + 18432, vhb + g_); CP16(d_ + 27648, vlb + g_); \
    } CP_COMMIT; \
} while (0)

    int t0 = 0;
    if (is_local) { int s = qt0 - window; t0 = (s > 0 ? s : 0) & ~63; }
    const int nt = (qt0 - t0) / 64 + 1;

    // Q load + first KV tile
    for (int c = tid; c < 512; c += 128) {
        int row = c >> 3, c8 = c & 7;
        size_t g = (size_t)(qt0 + row) * HD + c8 * 8;
        CP16(sQh + row * 144 + c8 * 16, qhb + g);
        CP16(sQl + row * 144 + c8 * 16, qlb + g);
    }
    CP_COMMIT;
    ATT_LOAD(0, t0);
    CP_WAIT(1);     // Q group done
    __syncthreads();

    uint32_t qhf[4][4], qlf[4][4];
    {
        const uint32_t qa = (uint32_t)((wid * 16 + lane15) * 144 + lhi8 * 2);
#pragma unroll
        for (int ks = 0; ks < 4; ks++) {
            LDSM4(qhf[ks][0],qhf[ks][1],qhf[ks][2],qhf[ks][3], sQh + qa + ks * 32);
            LDSM4(qlf[ks][0],qlf[ks][1],qlf[ks][2],qlf[ks][3], sQl + qa + ks * 32);
        }
    }

    float o[8][4];
#pragma unroll
    for (int nf = 0; nf < 8; nf++)
#pragma unroll
        for (int r = 0; r < 4; r++) o[nf][r] = 0.f;
    float m0r = -1e30f, m1r = -1e30f, l0r = 0.f, l1r = 0.f;

    const float scale = 0.125f;
    const int i0 = qt0 + wid * 16 + gid, i1 = i0 + 8;

    for (int it = 0; it < nt; it++) {
        const int kt = t0 + it * 64;
        const int stg = it & 1;
        if (it + 1 < nt) { ATT_LOAD(stg ^ 1, kt + 64); CP_WAIT(1); }
        else             { CP_WAIT(0); }
        __syncthreads();

        const uint32_t sKh = sb + 18432 + stg * 36864;
        const uint32_t sKl = sKh + 9216;
        const uint32_t sVh = sKh + 18432;
        const uint32_t sVl = sKh + 27648;

        // ---- S = Q K^T (split)
        float s[8][4];
#pragma unroll
        for (int nf = 0; nf < 8; nf++)
#pragma unroll
            for (int r = 0; r < 4; r++) s[nf][r] = 0.f;
#pragma unroll
        for (int ks = 0; ks < 4; ks++) {
#pragma unroll
            for (int g = 0; g < 4; g++) {
                const uint32_t ka = (uint32_t)((g * 16 + krow) * 144 + (ks * 16 + kc8) * 2);
                uint32_t b0,b1,b2,b3, c0,c1,c2,c3;
                LDSM4(b0,b1,b2,b3, sKh + ka);
                LDSM4(c0,c1,c2,c3, sKl + ka);
                MMA16816(s[2*g],   qhf[ks], b0, b1);
                MMA16816(s[2*g],   qlf[ks], b0, b1);
                MMA16816(s[2*g],   qhf[ks], c0, c1);
                MMA16816(s[2*g+1], qhf[ks], b2, b3);
                MMA16816(s[2*g+1], qlf[ks], b2, b3);
                MMA16816(s[2*g+1], qhf[ks], c2, c3);
            }
        }

        // ---- mask + scale
#pragma unroll
        for (int nf = 0; nf < 8; nf++) {
            int j0 = kt + nf * 8 + tig * 2, j1 = j0 + 1;
            bool k00 = (j0 <= i0) && (!is_local || j0 >= i0 - window);
            bool k01 = (j1 <= i0) && (!is_local || j1 >= i0 - window);
            bool k10 = (j0 <= i1) && (!is_local || j0 >= i1 - window);
            bool k11 = (j1 <= i1) && (!is_local || j1 >= i1 - window);
            s[nf][0] = k00 ? s[nf][0] * scale : -1e30f;
            s[nf][1] = k01 ? s[nf][1] * scale : -1e30f;
            s[nf][2] = k10 ? s[nf][2] * scale : -1e30f;
            s[nf][3] = k11 ? s[nf][3] * scale : -1e30f;
        }

        // ---- online softmax
        float t0m = -1e30f, t1m = -1e30f;
#pragma unroll
        for (int nf = 0; nf < 8; nf++) {
            t0m = fmaxf(t0m, fmaxf(s[nf][0], s[nf][1]));
            t1m = fmaxf(t1m, fmaxf(s[nf][2], s[nf][3]));
        }
        t0m = fmaxf(t0m, __shfl_xor_sync(0xffffffffu, t0m, 1));
        t0m = fmaxf(t0m, __shfl_xor_sync(0xffffffffu, t0m, 2));
        t1m = fmaxf(t1m, __shfl_xor_sync(0xffffffffu, t1m, 1));
        t1m = fmaxf(t1m, __shfl_xor_sync(0xffffffffu, t1m, 2));
        float mn0 = fmaxf(m0r, t0m), mn1 = fmaxf(m1r, t1m);
        float cr0 = __expf(m0r - mn0), cr1 = __expf(m1r - mn1);
        m0r = mn0; m1r = mn1;

        float ps0 = 0.f, ps1 = 0.f;
#pragma unroll
        for (int nf = 0; nf < 8; nf++) {
            float e0 = __expf(s[nf][0] - mn0), e1 = __expf(s[nf][1] - mn0);
            float e2 = __expf(s[nf][2] - mn1), e3 = __expf(s[nf][3] - mn1);
            ps0 += e0 + e1; ps1 += e2 + e3;
            s[nf][0] = e0; s[nf][1] = e1; s[nf][2] = e2; s[nf][3] = e3;
            o[nf][0] *= cr0; o[nf][1] *= cr0; o[nf][2] *= cr1; o[nf][3] *= cr1;
        }
        ps0 += __shfl_xor_sync(0xffffffffu, ps0, 1);
        ps0 += __shfl_xor_sync(0xffffffffu, ps0, 2);
        ps1 += __shfl_xor_sync(0xffffffffu, ps1, 1);
        ps1 += __shfl_xor_sync(0xffffffffu, ps1, 2);
        l0r = l0r * cr0 + ps0;
        l1r = l1r * cr1 + ps1;

        // ---- pack P (hi/lo)
        uint32_t ph[4][4], pl[4][4];
#pragma unroll
        for (int ks = 0; ks < 4; ks++) {
            split2(s[2*ks][0],   s[2*ks][1],   ph[ks][0], pl[ks][0]);
            split2(s[2*ks][2],   s[2*ks][3],   ph[ks][1], pl[ks][1]);
            split2(s[2*ks+1][0], s[2*ks+1][1], ph[ks][2], pl[ks][2]);
            split2(s[2*ks+1][2], s[2*ks+1][3], ph[ks][3], pl[ks][3]);
        }

        // ---- O += P V (split)
#pragma unroll
        for (int ks = 0; ks < 4; ks++) {
#pragma unroll
            for (int g = 0; g < 4; g++) {
                const uint32_t va = (uint32_t)((ks * 16 + lane15) * 144 + (g * 16 + lhi8) * 2);
                uint32_t v0,v1,v2,v3, w0,w1,w2,w3;
                LDSM4T(v0,v1,v2,v3, sVh + va);
                LDSM4T(w0,w1,w2,w3, sVl + va);
                MMA16816(o[2*g],   ph[ks], v0, v1);
                MMA16816(o[2*g],   pl[ks], v0, v1);
                MMA16816(o[2*g],   ph[ks], w0, w1);
                MMA16816(o[2*g+1], ph[ks], v2, v3);
                MMA16816(o[2*g+1], pl[ks], v2, v3);
                MMA16816(o[2*g+1], ph[ks], w2, w3);
            }
        }
        __syncthreads();
    }

    // ---- epilogue
    const float inv0 = 1.f / l0r, inv1 = 1.f / l1r;
    const int row0 = qt0 + wid * 16 + gid;
#pragma unroll
    for (int nf = 0; nf < 8; nf++) {
        const int col = h * 64 + nf * 8 + tig * 2;
        uint32_t hh, ll;
        split2(o[nf][0] * inv0, o[nf][1] * inv0, hh, ll);
        *(uint32_t*)(g_yh + (size_t)(b * TT + row0) * CC + col) = hh;
        *(uint32_t*)(g_yl + (size_t)(b * TT + row0) * CC + col) = ll;
        split2(o[nf][2] * inv1, o[nf][3] * inv1, hh, ll);
        *(uint32_t*)(g_yh + (size_t)(b * TT + row0 + 8) * CC + col) = hh;
        *(uint32_t*)(g_yl + (size_t)(b * TT + row0 + 8) * CC + col) = ll;
    }
}

// ---------------- launch ------------------------------------------------------
extern "C" void kernel_launch(void* const* d_in, const int* in_sizes, int n_in,
                              void* d_out, int out_size)
{
    const float* x     = (const float*)d_in[0];
    const float* ve    = (const float*)d_in[1];
    const float* cosb  = (const float*)d_in[2];
    const float* sinb  = (const float*)d_in[3];
    const float* Wq    = (const float*)d_in[4];
    const float* Wk    = (const float*)d_in[5];
    const float* Wv    = (const float*)d_in[6];
    const float* Wproj = (const float*)d_in[7];
    const float* Wgate = (const float*)d_in[8];
    const int*   wptr  = (const int*)d_in[9];

    float* qkvbuf;
    cudaGetSymbolAddress((void**)&qkvbuf, g_qkvbuf);
    __nv_bfloat16 *xh,*xl,*wch,*wcl,*wph,*wpl,*yh,*yl;
    cudaGetSymbolAddress((void**)&xh, g_xh);   cudaGetSymbolAddress((void**)&xl, g_xl);
    cudaGetSymbolAddress((void**)&wch, g_wch); cudaGetSymbolAddress((void**)&wcl, g_wcl);
    cudaGetSymbolAddress((void**)&wph, g_wph); cudaGetSymbolAddress((void**)&wpl, g_wpl);
    cudaGetSymbolAddress((void**)&yh, g_yh);   cudaGetSymbolAddress((void**)&yl, g_yl);

    cudaFuncSetAttribute(gemm_bf16split, cudaFuncAttributeMaxDynamicSharedMemorySize, 3 * GSTAGE);
    cudaFuncSetAttribute(attn_mma, cudaFuncAttributeMaxDynamicSharedMemorySize, 92160);

    // split conversions
    split_convert<<<1024, 256>>>(x, xh, xl, BT * CC);
    split_convert_str<<<512, 256>>>(Wq, wch, wcl, CC * 1024, 1024, 2048, 0);
    split_convert_str<<<256, 256>>>(Wk, wch, wcl, CC * 512, 512, 2048, 1024);
    split_convert_str<<<256, 256>>>(Wv, wch, wcl, CC * 512, 512, 2048, 1536);
    split_convert<<<512, 256>>>(Wproj, wph, wpl, CC * CC);

    // fused QKV projection
    gemm_bf16split<<<dim3(16, 32), 256, 3 * GSTAGE>>>(xh, xl, wch, wcl, qkvbuf, BT, 2048, CC);

    // gate + ve, rope, rmsnorm -> split-bf16 q/k/v
    postproc<<<BT, 256>>>(x, ve, cosb, sinb, Wgate);

    // attention -> split-bf16 y
    attn_mma<<<dim3(TT / 64, BB * NH), 128, 92160>>>(wptr);

    // output projection -> d_out
    gemm_bf16split<<<dim3(8, 32), 256, 3 * GSTAGE>>>(yh, yl, wph, wpl, (float*)d_out, BT, 1024, CC);
}

// round 7
// speedup vs baseline: 4.6016x; 1.1670x over previous
#include <cuda_runtime.h>
#include <cuda_bf16.h>
#include <cuda_fp16.h>
#include <cstdint>

// Problem constants
#define BB 2
#define TT 2048
#define CC 1024
#define NH 16
#define NKV 8
#define HD 64
#define BT (BB*TT)          // 4096

// ---------------- scratch (device globals) ----------------------------------
__device__ float g_qkvbuf[BT * 2048];          // fused [q(1024)|k(512)|v(512)]

__device__ __half g_xh[BT * CC],  g_xl[BT * CC];       // x split fp16
__device__ __half g_wch[CC * 2048];                    // Wq|Wk|Wv fp16 [K,2048]
__device__ __half g_wph[CC * CC];                      // Wproj fp16 [K,N]

__device__ __nv_bfloat16 g_qh[BB*NH*TT*HD],  g_ql[BB*NH*TT*HD];    // [b,h,t,d]
__device__ __nv_bfloat16 g_kh[BB*NKV*TT*HD], g_kl[BB*NKV*TT*HD];   // [b,kh,t,d]
__device__ __nv_bfloat16 g_vh[BB*NKV*TT*HD], g_vl[BB*NKV*TT*HD];
__device__ __half g_yh[BT * CC], g_yl[BT * CC];        // attn out split fp16 [bt, h*d]

// ---------------- PTX helpers ------------------------------------------------
#define LDSM4(r0,r1,r2,r3,addr) \
    asm volatile("ldmatrix.sync.aligned.m8n8.x4.shared.b16 {%0,%1,%2,%3}, [%4];" \
                 : "=r"(r0),"=r"(r1),"=r"(r2),"=r"(r3) : "r"(addr))
#define LDSM4T(r0,r1,r2,r3,addr) \
    asm volatile("ldmatrix.sync.aligned.m8n8.x4.trans.shared.b16 {%0,%1,%2,%3}, [%4];" \
                 : "=r"(r0),"=r"(r1),"=r"(r2),"=r"(r3) : "r"(addr))
// bf16 mma (attention)
#define MMA16816(d, a, b0, b1) \
    asm volatile("mma.sync.aligned.m16n8k16.row.col.f32.bf16.bf16.f32 " \
                 "{%0,%1,%2,%3}, {%4,%5,%6,%7}, {%8,%9}, {%0,%1,%2,%3};" \
                 : "+f"(d[0]),"+f"(d[1]),"+f"(d[2]),"+f"(d[3]) \
                 : "r"(a[0]),"r"(a[1]),"r"(a[2]),"r"(a[3]), "r"(b0),"r"(b1))
// fp16 mma (projections)
#define MMA16816H(d, a, b0, b1) \
    asm volatile("mma.sync.aligned.m16n8k16.row.col.f32.f16.f16.f32 " \
                 "{%0,%1,%2,%3}, {%4,%5,%6,%7}, {%8,%9}, {%0,%1,%2,%3};" \
                 : "+f"(d[0]),"+f"(d[1]),"+f"(d[2]),"+f"(d[3]) \
                 : "r"(a[0]),"r"(a[1]),"r"(a[2]),"r"(a[3]), "r"(b0),"r"(b1))
#define CP16(dst, src) \
    asm volatile("cp.async.cg.shared.global [%0], [%1], 16;" :: "r"(dst), "l"(src))
#define CP_COMMIT asm volatile("cp.async.commit_group;")
#define CP_WAIT(N) asm volatile("cp.async.wait_group %0;" :: "n"(N))

__device__ __forceinline__ uint32_t bpack(__nv_bfloat16 e0, __nv_bfloat16 e1) {
    return ((uint32_t)__bfloat16_as_ushort(e1) << 16) | (uint32_t)__bfloat16_as_ushort(e0);
}
__device__ __forceinline__ void split2(float x0, float x1, uint32_t& h, uint32_t& l) {
    __nv_bfloat16 h0 = __float2bfloat16(x0), h1 = __float2bfloat16(x1);
    h = bpack(h0, h1);
    l = bpack(__float2bfloat16(x0 - __bfloat162float(h0)),
              __float2bfloat16(x1 - __bfloat162float(h1)));
}
__device__ __forceinline__ uint32_t hpack(__half e0, __half e1) {
    return ((uint32_t)__half_as_ushort(e1) << 16) | (uint32_t)__half_as_ushort(e0);
}
__device__ __forceinline__ void split2h(float x0, float x1, uint32_t& h, uint32_t& l) {
    __half h0 = __float2half(x0), h1 = __float2half(x1);
    h = hpack(h0, h1);
    l = hpack(__float2half(x0 - __half2float(h0)),
              __float2half(x1 - __half2float(h1)));
}

// ---------------- conversions ------------------------------------------------
// fp32 -> (hi, lo) fp16
__global__ __launch_bounds__(256)
void split_convert_h(const float* __restrict__ src, __half* __restrict__ hi,
                     __half* __restrict__ lo, int n)
{
    int step = gridDim.x * blockDim.x * 4;
    for (int i = (blockIdx.x * blockDim.x + threadIdx.x) * 4; i < n; i += step) {
        float4 v = *(const float4*)(src + i);
        uint32_t h0, l0, h1, l1;
        split2h(v.x, v.y, h0, l0);
        split2h(v.z, v.w, h1, l1);
        *(uint2*)(hi + i) = make_uint2(h0, h1);
        *(uint2*)(lo + i) = make_uint2(l0, l1);
    }
}

// fp32 [rows, cols] -> fp16 single into [rows, dst_stride] at col_off
__global__ __launch_bounds__(256)
void convert_h_str(const float* __restrict__ src, __half* __restrict__ dst,
                   int n, int cols, int dst_stride, int col_off)
{
    int step = gridDim.x * blockDim.x * 4;
    for (int i = (blockIdx.x * blockDim.x + threadIdx.x) * 4; i < n; i += step) {
        float4 v = *(const float4*)(src + i);
        uint32_t p0 = hpack(__float2half(v.x), __float2half(v.y));
        uint32_t p1 = hpack(__float2half(v.z), __float2half(v.w));
        int r = i / cols, c = i - r * cols;
        *(uint2*)(dst + (size_t)r * dst_stride + col_off + c) = make_uint2(p0, p1);
    }
}

// ---------------- GEMM: C = (Ah+Al) @ B, fp16 2-term, fp32 out ---------------
// BM=128 BN=128 BK=32.  3-stage cp.async pipeline. 256 thr, 8 warps (2x4).
#define GSTAGE 29184
// stage: Ah@0 (128x40x2=10240), Al@10240, Bh@20480 (32x136x2=8704)

__global__ __launch_bounds__(256)
void gemm_f16_2t(const __half* __restrict__ Ahg, const __half* __restrict__ Alg,
                 const __half* __restrict__ Bhg,
                 float* __restrict__ C, int M, int N, int K)
{
    extern __shared__ char sm[];
    const int tid = threadIdx.x;
    const int lane = tid & 31, wid = tid >> 5;
    const int warp_m = wid & 1, warp_n = wid >> 1;
    const int gid = lane >> 2, tig = lane & 3;
    const int lane15 = lane & 15, lhi8 = (lane >> 4) * 8;
    const int m0 = blockIdx.y * 128, n0 = blockIdx.x * 128;
    const uint32_t sb = (uint32_t)__cvta_generic_to_shared(sm);

    const int cc0 = tid * 2;
    const int ar = cc0 >> 2, ac = cc0 & 3;
    const int br = cc0 >> 4, bc = cc0 & 15;

    float acc[4][4][4];
#pragma unroll
    for (int i = 0; i < 4; i++)
#pragma unroll
        for (int j = 0; j < 4; j++)
#pragma unroll
            for (int r = 0; r < 4; r++) acc[i][j][r] = 0.f;

#define GEMM_LOAD(stg, k0) do { \
    uint32_t s_ = sb + (stg) * GSTAGE; \
    const __half* p_; \
    p_ = Ahg + (size_t)(m0 + ar) * K + (k0) + ac * 8; \
    CP16(s_ + ar*80 + ac*16, p_); CP16(s_ + ar*80 + ac*16 + 16, p_ + 8); \
    p_ = Alg + (size_t)(m0 + ar) * K + (k0) + ac * 8; \
    CP16(s_ + 10240 + ar*80 + ac*16, p_); CP16(s_ + 10240 + ar*80 + ac*16 + 16, p_ + 8); \
    p_ = Bhg + (size_t)((k0) + br) * N + n0 + bc * 8; \
    CP16(s_ + 20480 + br*272 + bc*16, p_); CP16(s_ + 20480 + br*272 + bc*16 + 16, p_ + 8); \
    CP_COMMIT; \
} while (0)

    const int ktiles = K >> 5;
    GEMM_LOAD(0, 0);
    GEMM_LOAD(1, 32);

    int stg = 0;
    for (int t = 0; t < ktiles; t++) {
        if (t + 1 < ktiles) CP_WAIT(1); else CP_WAIT(0);
        __syncthreads();
        if (t + 2 < ktiles) {
            int ns = stg + 2; if (ns >= 3) ns -= 3;
            GEMM_LOAD(ns, (t + 2) * 32);
        }

        const uint32_t sAh = sb + stg * GSTAGE;
        const uint32_t sAl = sAh + 10240;
        const uint32_t sBh = sAh + 20480;

#pragma unroll
        for (int ks = 0; ks < 2; ks++) {
            const uint32_t a_off = (uint32_t)((warp_m * 64 + lane15) * 80 + (ks * 16 + lhi8) * 2);
            const uint32_t b_off = (uint32_t)((ks * 16 + lane15) * 272 + (warp_n * 32 + lhi8) * 2);

            uint32_t a[4][4];
            uint32_t bh[2][4];
#pragma unroll
            for (int mf = 0; mf < 4; mf++)
                LDSM4(a[mf][0],a[mf][1],a[mf][2],a[mf][3], sAh + a_off + (uint32_t)(mf * 16 * 80));
#pragma unroll
            for (int p = 0; p < 2; p++)
                LDSM4T(bh[p][0],bh[p][1],bh[p][2],bh[p][3], sBh + b_off + (uint32_t)(p * 32));
#pragma unroll
            for (int mf = 0; mf < 4; mf++)
#pragma unroll
                for (int nf = 0; nf < 4; nf++) {
                    const int p = nf >> 1, q = (nf & 1) * 2;
                    MMA16816H(acc[mf][nf], a[mf], bh[p][q], bh[p][q+1]);
                }
#pragma unroll
            for (int mf = 0; mf < 4; mf++)
                LDSM4(a[mf][0],a[mf][1],a[mf][2],a[mf][3], sAl + a_off + (uint32_t)(mf * 16 * 80));
#pragma unroll
            for (int mf = 0; mf < 4; mf++)
#pragma unroll
                for (int nf = 0; nf < 4; nf++) {
                    const int p = nf >> 1, q = (nf & 1) * 2;
                    MMA16816H(acc[mf][nf], a[mf], bh[p][q], bh[p][q+1]);
                }
        }
        stg++; if (stg == 3) stg = 0;
    }

#pragma unroll
    for (int mf = 0; mf < 4; mf++) {
#pragma unroll
        for (int nf = 0; nf < 4; nf++) {
            const int row = m0 + warp_m * 64 + mf * 16 + gid;
            const int col = n0 + warp_n * 32 + nf * 8 + tig * 2;
            *(float2*)&C[(size_t)row * N + col] = make_float2(acc[mf][nf][0], acc[mf][nf][1]);
            *(float2*)&C[(size_t)(row + 8) * N + col] = make_float2(acc[mf][nf][2], acc[mf][nf][3]);
        }
    }
}

// ---------------- postprocess: gate+ve, RoPE, rmsnorm, split-bf16 out --------
__global__ __launch_bounds__(256)
void postproc(const float* __restrict__ x, const float* __restrict__ ve,
              const float* __restrict__ cosb, const float* __restrict__ sinb,
              const float* __restrict__ Wgate)
{
    const int bt = blockIdx.x;
    const int b = bt >> 11, t = bt & (TT - 1);
    const int tid = threadIdx.x;
    const float* qkv = g_qkvbuf + (size_t)bt * 2048;

    __shared__ float gate[NKV];
    if (tid < NKV) {
        float acc = 0.f;
        const float* xr = x + (size_t)bt * CC;
#pragma unroll
        for (int c = 0; c < 32; c++) acc += xr[c] * Wgate[c * NKV + tid];
        gate[tid] = 2.f / (1.f + expf(-acc));
    }
    __syncthreads();

    for (int i = tid; i < NKV * HD; i += 256) {
        int hh = i >> 6, d = i & 63;
        float vv = qkv[1536 + i] + gate[hh] * ve[(size_t)bt * 512 + i];
        size_t idx = (((size_t)b * NKV + hh) * TT + t) * HD + d;
        __nv_bfloat16 hb = __float2bfloat16(vv);
        g_vh[idx] = hb;
        g_vl[idx] = __float2bfloat16(vv - __bfloat162float(hb));
    }

    const int w = tid >> 5, lane = tid & 31;
    const float cs = cosb[t * 32 + lane];
    const float sn = sinb[t * 32 + lane];
    const float eps = 1.1920929e-07f;

#pragma unroll
    for (int qi = 0; qi < 2; qi++) {
        int h = 2 * w + qi;
        const float* qr = qkv + h * HD;
        float x1 = qr[lane], x2 = qr[lane + 32];
        float r1 = x1 * cs + x2 * sn;
        float r2 = -x1 * sn + x2 * cs;
        float ss = r1 * r1 + r2 * r2;
#pragma unroll
        for (int o = 16; o; o >>= 1) ss += __shfl_xor_sync(0xffffffffu, ss, o);
        float sc = rsqrtf(ss * (1.f / 64.f) + eps);
        size_t idx = (((size_t)b * NH + h) * TT + t) * HD;
        float v1 = r1 * sc, v2 = r2 * sc;
        __nv_bfloat16 h1 = __float2bfloat16(v1), h2 = __float2bfloat16(v2);
        g_qh[idx + lane] = h1;       g_ql[idx + lane] = __float2bfloat16(v1 - __bfloat162float(h1));
        g_qh[idx + lane + 32] = h2;  g_ql[idx + lane + 32] = __float2bfloat16(v2 - __bfloat162float(h2));
    }
    {
        const float* kr = qkv + 1024 + w * HD;
        float x1 = kr[lane], x2 = kr[lane + 32];
        float r1 = x1 * cs + x2 * sn;
        float r2 = -x1 * sn + x2 * cs;
        float ss = r1 * r1 + r2 * r2;
#pragma unroll
        for (int o = 16; o; o >>= 1) ss += __shfl_xor_sync(0xffffffffu, ss, o);
        float sc = rsqrtf(ss * (1.f / 64.f) + eps);
        size_t idx = (((size_t)b * NKV + w) * TT + t) * HD;
        float v1 = r1 * sc, v2 = r2 * sc;
        __nv_bfloat16 h1 = __float2bfloat16(v1), h2 = __float2bfloat16(v2);
        g_kh[idx + lane] = h1;       g_kl[idx + lane] = __float2bfloat16(v1 - __bfloat162float(h1));
        g_kh[idx + lane + 32] = h2;  g_kl[idx + lane + 32] = __float2bfloat16(v2 - __bfloat162float(h2));
    }
}

// ---------------- tensor-core flash attention (split-bf16, pipelined) --------
// BM=64, BN=64, 4 warps. smem: Qh@0, Ql@9216, then 2 stages of {Kh,Kl,Vh,Vl}
// each 9216 at 18432 + stg*36864.  Total 92160.
__global__ __launch_bounds__(128)
void attn_mma(const int* __restrict__ wptr)
{
    extern __shared__ char sm[];
    const uint32_t sb = (uint32_t)__cvta_generic_to_shared(sm);
    const uint32_t sQh = sb, sQl = sb + 9216;

    const int qt0 = (int)(gridDim.x - 1 - blockIdx.x) * 64;   // heavy blocks first
    const int bh = blockIdx.y;
    const int b = bh >> 4, h = bh & 15;
    const int window = *wptr;
    const bool is_local = (h >= 8);
    const int kvh = is_local ? 4 + ((h - 8) >> 1) : (h >> 1);

    const __nv_bfloat16* qhb = g_qh + ((size_t)(b * NH + h) * TT) * HD;
    const __nv_bfloat16* qlb = g_ql + ((size_t)(b * NH + h) * TT) * HD;
    const __nv_bfloat16* khb = g_kh + ((size_t)(b * NKV + kvh) * TT) * HD;
    const __nv_bfloat16* klb = g_kl + ((size_t)(b * NKV + kvh) * TT) * HD;
    const __nv_bfloat16* vhb = g_vh + ((size_t)(b * NKV + kvh) * TT) * HD;
    const __nv_bfloat16* vlb = g_vl + ((size_t)(b * NKV + kvh) * TT) * HD;

    const int tid = threadIdx.x;
    const int lane = tid & 31, wid = tid >> 5;
    const int gid = lane >> 2, tig = lane & 3;
    const int lane15 = lane & 15, lhi8 = (lane >> 4) * 8;
    const int krow = (lane & 7) | ((lane & 16) >> 1);
    const int kc8 = lane & 8;

#define ATT_LOAD(stg, ktv) do { \
    uint32_t base_ = sb + 18432 + (stg) * 36864; \
    for (int c = tid; c < 512; c += 128) { \
        int row_ = c >> 3, c8_ = c & 7; \
        size_t g_ = (size_t)((ktv) + row_) * HD + c8_ * 8; \
        uint32_t d_ = base_ + row_ * 144 + c8_ * 16; \
        CP16(d_, khb + g_); CP16(d_ + 9216, klb + g_); \
        CP16(d_ + 18432, vhb + g_); CP16(d_ + 27648, vlb + g_); \
    } CP_COMMIT; \
} while (0)

    int t0 = 0;
    if (is_local) { int s = qt0 - window; t0 = (s > 0 ? s : 0) & ~63; }
    const int nt = (qt0 - t0) / 64 + 1;

    for (int c = tid; c < 512; c += 128) {
        int row = c >> 3, c8 = c & 7;
        size_t g = (size_t)(qt0 + row) * HD + c8 * 8;
        CP16(sQh + row * 144 + c8 * 16, qhb + g);
        CP16(sQl + row * 144 + c8 * 16, qlb + g);
    }
    CP_COMMIT;
    ATT_LOAD(0, t0);
    CP_WAIT(1);
    __syncthreads();

    uint32_t qhf[4][4], qlf[4][4];
    {
        const uint32_t qa = (uint32_t)((wid * 16 + lane15) * 144 + lhi8 * 2);
#pragma unroll
        for (int ks = 0; ks < 4; ks++) {
            LDSM4(qhf[ks][0],qhf[ks][1],qhf[ks][2],qhf[ks][3], sQh + qa + ks * 32);
            LDSM4(qlf[ks][0],qlf[ks][1],qlf[ks][2],qlf[ks][3], sQl + qa + ks * 32);
        }
    }

    float o[8][4];
#pragma unroll
    for (int nf = 0; nf < 8; nf++)
#pragma unroll
        for (int r = 0; r < 4; r++) o[nf][r] = 0.f;
    float m0r = -1e30f, m1r = -1e30f, l0r = 0.f, l1r = 0.f;

    const float scale = 0.125f;
    const int i0 = qt0 + wid * 16 + gid, i1 = i0 + 8;

    for (int it = 0; it < nt; it++) {
        const int kt = t0 + it * 64;
        const int stg = it & 1;
        if (it + 1 < nt) { ATT_LOAD(stg ^ 1, kt + 64); CP_WAIT(1); }
        else             { CP_WAIT(0); }
        __syncthreads();

        const uint32_t sKh = sb + 18432 + stg * 36864;
        const uint32_t sKl = sKh + 9216;
        const uint32_t sVh = sKh + 18432;
        const uint32_t sVl = sKh + 27648;

        float s[8][4];
#pragma unroll
        for (int nf = 0; nf < 8; nf++)
#pragma unroll
            for (int r = 0; r < 4; r++) s[nf][r] = 0.f;
#pragma unroll
        for (int ks = 0; ks < 4; ks++) {
#pragma unroll
            for (int g = 0; g < 4; g++) {
                const uint32_t ka = (uint32_t)((g * 16 + krow) * 144 + (ks * 16 + kc8) * 2);
                uint32_t b0,b1,b2,b3, c0,c1,c2,c3;
                LDSM4(b0,b1,b2,b3, sKh + ka);
                LDSM4(c0,c1,c2,c3, sKl + ka);
                MMA16816(s[2*g],   qhf[ks], b0, b1);
                MMA16816(s[2*g],   qlf[ks], b0, b1);
                MMA16816(s[2*g],   qhf[ks], c0, c1);
                MMA16816(s[2*g+1], qhf[ks], b2, b3);
                MMA16816(s[2*g+1], qlf[ks], b2, b3);
                MMA16816(s[2*g+1], qhf[ks], c2, c3);
            }
        }

#pragma unroll
        for (int nf = 0; nf < 8; nf++) {
            int j0 = kt + nf * 8 + tig * 2, j1 = j0 + 1;
            bool k00 = (j0 <= i0) && (!is_local || j0 >= i0 - window);
            bool k01 = (j1 <= i0) && (!is_local || j1 >= i0 - window);
            bool k10 = (j0 <= i1) && (!is_local || j0 >= i1 - window);
            bool k11 = (j1 <= i1) && (!is_local || j1 >= i1 - window);
            s[nf][0] = k00 ? s[nf][0] * scale : -1e30f;
            s[nf][1] = k01 ? s[nf][1] * scale : -1e30f;
            s[nf][2] = k10 ? s[nf][2] * scale : -1e30f;
            s[nf][3] = k11 ? s[nf][3] * scale : -1e30f;
        }

        float t0m = -1e30f, t1m = -1e30f;
#pragma unroll
        for (int nf = 0; nf < 8; nf++) {
            t0m = fmaxf(t0m, fmaxf(s[nf][0], s[nf][1]));
            t1m = fmaxf(t1m, fmaxf(s[nf][2], s[nf][3]));
        }
        t0m = fmaxf(t0m, __shfl_xor_sync(0xffffffffu, t0m, 1));
        t0m = fmaxf(t0m, __shfl_xor_sync(0xffffffffu, t0m, 2));
        t1m = fmaxf(t1m, __shfl_xor_sync(0xffffffffu, t1m, 1));
        t1m = fmaxf(t1m, __shfl_xor_sync(0xffffffffu, t1m, 2));
        float mn0 = fmaxf(m0r, t0m), mn1 = fmaxf(m1r, t1m);
        float cr0 = __expf(m0r - mn0), cr1 = __expf(m1r - mn1);
        m0r = mn0; m1r = mn1;

        float ps0 = 0.f, ps1 = 0.f;
#pragma unroll
        for (int nf = 0; nf < 8; nf++) {
            float e0 = __expf(s[nf][0] - mn0), e1 = __expf(s[nf][1] - mn0);
            float e2 = __expf(s[nf][2] - mn1), e3 = __expf(s[nf][3] - mn1);
            ps0 += e0 + e1; ps1 += e2 + e3;
            s[nf][0] = e0; s[nf][1] = e1; s[nf][2] = e2; s[nf][3] = e3;
            o[nf][0] *= cr0; o[nf][1] *= cr0; o[nf][2] *= cr1; o[nf][3] *= cr1;
        }
        ps0 += __shfl_xor_sync(0xffffffffu, ps0, 1);
        ps0 += __shfl_xor_sync(0xffffffffu, ps0, 2);
        ps1 += __shfl_xor_sync(0xffffffffu, ps1, 1);
        ps1 += __shfl_xor_sync(0xffffffffu, ps1, 2);
        l0r = l0r * cr0 + ps0;
        l1r = l1r * cr1 + ps1;

        uint32_t ph[4][4], pl[4][4];
#pragma unroll
        for (int ks = 0; ks < 4; ks++) {
            split2(s[2*ks][0],   s[2*ks][1],   ph[ks][0], pl[ks][0]);
            split2(s[2*ks][2],   s[2*ks][3],   ph[ks][1], pl[ks][1]);
            split2(s[2*ks+1][0], s[2*ks+1][1], ph[ks][2], pl[ks][2]);
            split2(s[2*ks+1][2], s[2*ks+1][3], ph[ks][3], pl[ks][3]);
        }

#pragma unroll
        for (int ks = 0; ks < 4; ks++) {
#pragma unroll
            for (int g = 0; g < 4; g++) {
                const uint32_t va = (uint32_t)((ks * 16 + lane15) * 144 + (g * 16 + lhi8) * 2);
                uint32_t v0,v1,v2,v3, w0,w1,w2,w3;
                LDSM4T(v0,v1,v2,v3, sVh + va);
                LDSM4T(w0,w1,w2,w3, sVl + va);
                MMA16816(o[2*g],   ph[ks], v0, v1);
                MMA16816(o[2*g],   pl[ks], v0, v1);
                MMA16816(o[2*g],   ph[ks], w0, w1);
                MMA16816(o[2*g+1], ph[ks], v2, v3);
                MMA16816(o[2*g+1], pl[ks], v2, v3);
                MMA16816(o[2*g+1], ph[ks], w2, w3);
            }
        }
        __syncthreads();
    }

    // epilogue: y = O / l -> split fp16 (feeds fp16 2-term proj GEMM)
    const float inv0 = 1.f / l0r, inv1 = 1.f / l1r;
    const int row0 = qt0 + wid * 16 + gid;
#pragma unroll
    for (int nf = 0; nf < 8; nf++) {
        const int col = h * 64 + nf * 8 + tig * 2;
        uint32_t hh, ll;
        split2h(o[nf][0] * inv0, o[nf][1] * inv0, hh, ll);
        *(uint32_t*)(g_yh + (size_t)(b * TT + row0) * CC + col) = hh;
        *(uint32_t*)(g_yl + (size_t)(b * TT + row0) * CC + col) = ll;
        split2h(o[nf][2] * inv1, o[nf][3] * inv1, hh, ll);
        *(uint32_t*)(g_yh + (size_t)(b * TT + row0 + 8) * CC + col) = hh;
        *(uint32_t*)(g_yl + (size_t)(b * TT + row0 + 8) * CC + col) = ll;
    }
}

// ---------------- launch ------------------------------------------------------
extern "C" void kernel_launch(void* const* d_in, const int* in_sizes, int n_in,
                              void* d_out, int out_size)
{
    const float* x     = (const float*)d_in[0];
    const float* ve    = (const float*)d_in[1];
    const float* cosb  = (const float*)d_in[2];
    const float* sinb  = (const float*)d_in[3];
    const float* Wq    = (const float*)d_in[4];
    const float* Wk    = (const float*)d_in[5];
    const float* Wv    = (const float*)d_in[6];
    const float* Wproj = (const float*)d_in[7];
    const float* Wgate = (const float*)d_in[8];
    const int*   wptr  = (const int*)d_in[9];

    float* qkvbuf;
    cudaGetSymbolAddress((void**)&qkvbuf, g_qkvbuf);
    __half *xh, *xl, *wch, *wph, *yh, *yl;
    cudaGetSymbolAddress((void**)&xh, g_xh);   cudaGetSymbolAddress((void**)&xl, g_xl);
    cudaGetSymbolAddress((void**)&wch, g_wch); cudaGetSymbolAddress((void**)&wph, g_wph);
    cudaGetSymbolAddress((void**)&yh, g_yh);   cudaGetSymbolAddress((void**)&yl, g_yl);

    cudaFuncSetAttribute(gemm_f16_2t, cudaFuncAttributeMaxDynamicSharedMemorySize, 3 * GSTAGE);
    cudaFuncSetAttribute(attn_mma, cudaFuncAttributeMaxDynamicSharedMemorySize, 92160);

    // conversions
    split_convert_h<<<1024, 256>>>(x, xh, xl, BT * CC);
    convert_h_str<<<512, 256>>>(Wq, wch, CC * 1024, 1024, 2048, 0);
    convert_h_str<<<256, 256>>>(Wk, wch, CC * 512, 512, 2048, 1024);
    convert_h_str<<<256, 256>>>(Wv, wch, CC * 512, 512, 2048, 1536);
    convert_h_str<<<512, 256>>>(Wproj, wph, CC * CC, 1024, 1024, 0);

    // fused QKV projection (fp16 2-term)
    gemm_f16_2t<<<dim3(16, 32), 256, 3 * GSTAGE>>>(xh, xl, wch, qkvbuf, BT, 2048, CC);

    // gate + ve, rope, rmsnorm -> split-bf16 q/k/v
    postproc<<<BT, 256>>>(x, ve, cosb, sinb, Wgate);

    // attention (split-bf16) -> split-fp16 y
    attn_mma<<<dim3(TT / 64, BB * NH), 128, 92160>>>(wptr);

    // output projection (fp16 2-term) -> d_out
    gemm_f16_2t<<<dim3(8, 32), 256, 3 * GSTAGE>>>(yh, yl, wph, (float*)d_out, BT, 1024, CC);
}

// round 8
// speedup vs baseline: 7.8285x; 1.7013x over previous
#include <cuda_runtime.h>
#include <cuda_fp16.h>
#include <cstdint>

// Problem constants
#define BB 2
#define TT 2048
#define CC 1024
#define NH 16
#define NKV 8
#define HD 64
#define BT (BB*TT)          // 4096

// ---------------- scratch (device globals) ----------------------------------
__device__ float g_qkvbuf[BT * 2048];          // fused [q(1024)|k(512)|v(512)]

__device__ __half g_xh[BT * CC];               // x fp16
__device__ __half g_wch[CC * 2048];            // Wq|Wk|Wv fp16 [K,2048]
__device__ __half g_wph[CC * CC];              // Wproj fp16 [K,N]

__device__ __half g_qattn[BB*NH*TT*HD];        // [b,h,t,d] fp16
__device__ __half g_kattn[BB*NKV*TT*HD];       // [b,kh,t,d]
__device__ __half g_vattn[BB*NKV*TT*HD];
__device__ __half g_yattn[BT * CC];            // attn out fp16 [bt, h*d]

// ---------------- PTX helpers ------------------------------------------------
#define LDSM4(r0,r1,r2,r3,addr) \
    asm volatile("ldmatrix.sync.aligned.m8n8.x4.shared.b16 {%0,%1,%2,%3}, [%4];" \
                 : "=r"(r0),"=r"(r1),"=r"(r2),"=r"(r3) : "r"(addr))
#define LDSM4T(r0,r1,r2,r3,addr) \
    asm volatile("ldmatrix.sync.aligned.m8n8.x4.trans.shared.b16 {%0,%1,%2,%3}, [%4];" \
                 : "=r"(r0),"=r"(r1),"=r"(r2),"=r"(r3) : "r"(addr))
#define MMA16816H(d, a, b0, b1) \
    asm volatile("mma.sync.aligned.m16n8k16.row.col.f32.f16.f16.f32 " \
                 "{%0,%1,%2,%3}, {%4,%5,%6,%7}, {%8,%9}, {%0,%1,%2,%3};" \
                 : "+f"(d[0]),"+f"(d[1]),"+f"(d[2]),"+f"(d[3]) \
                 : "r"(a[0]),"r"(a[1]),"r"(a[2]),"r"(a[3]), "r"(b0),"r"(b1))
#define CP16(dst, src) \
    asm volatile("cp.async.cg.shared.global [%0], [%1], 16;" :: "r"(dst), "l"(src))
#define CP_COMMIT asm volatile("cp.async.commit_group;")
#define CP_WAIT(N) asm volatile("cp.async.wait_group %0;" :: "n"(N))

__device__ __forceinline__ uint32_t hpack(__half e0, __half e1) {
    return ((uint32_t)__half_as_ushort(e1) << 16) | (uint32_t)__half_as_ushort(e0);
}
__device__ __forceinline__ uint2 cvt4h(float4 v) {
    return make_uint2(hpack(__float2half(v.x), __float2half(v.y)),
                      hpack(__float2half(v.z), __float2half(v.w)));
}

// ---------------- fused conversion: all fp32 inputs -> fp16 ------------------
// segments (float4 units): x 1048576 | Wq 262144 | Wk 131072 | Wv 131072 | Wp 262144
__global__ __launch_bounds__(256)
void convert_all(const float* __restrict__ x,  const float* __restrict__ Wq,
                 const float* __restrict__ Wk, const float* __restrict__ Wv,
                 const float* __restrict__ Wp)
{
    const int i4 = blockIdx.x * 256 + threadIdx.x;
    if (i4 < 1048576) {
        *(uint2*)(g_xh + (size_t)i4 * 4) = cvt4h(*(const float4*)(x + (size_t)i4 * 4));
    } else if (i4 < 1310720) {
        int j = (i4 - 1048576) * 4;
        int r = j >> 10, c = j & 1023;
        *(uint2*)(g_wch + (size_t)r * 2048 + c) = cvt4h(*(const float4*)(Wq + j));
    } else if (i4 < 1441792) {
        int j = (i4 - 1310720) * 4;
        int r = j >> 9, c = j & 511;
        *(uint2*)(g_wch + (size_t)r * 2048 + 1024 + c) = cvt4h(*(const float4*)(Wk + j));
    } else if (i4 < 1572864) {
        int j = (i4 - 1441792) * 4;
        int r = j >> 9, c = j & 511;
        *(uint2*)(g_wch + (size_t)r * 2048 + 1536 + c) = cvt4h(*(const float4*)(Wv + j));
    } else {
        int j = (i4 - 1572864) * 4;
        *(uint2*)(g_wph + j) = cvt4h(*(const float4*)(Wp + j));
    }
}

// ---------------- GEMM: C = A @ B, fp16 single, fp32 out ---------------------
// BM=128 BN=128 BK=32.  3-stage cp.async pipeline. 256 thr, 8 warps (2x4).
#define GSTAGE 18944
// stage: A@0 (128x40x2=10240), B@10240 (32x136x2=8704)

__global__ __launch_bounds__(256)
void gemm_f16(const __half* __restrict__ Ag, const __half* __restrict__ Bg,
              float* __restrict__ C, int M, int N, int K)
{
    extern __shared__ char sm[];
    const int tid = threadIdx.x;
    const int lane = tid & 31, wid = tid >> 5;
    const int warp_m = wid & 1, warp_n = wid >> 1;
    const int gid = lane >> 2, tig = lane & 3;
    const int lane15 = lane & 15, lhi8 = (lane >> 4) * 8;
    const int m0 = blockIdx.y * 128, n0 = blockIdx.x * 128;
    const uint32_t sb = (uint32_t)__cvta_generic_to_shared(sm);

    const int cc0 = tid * 2;
    const int ar = cc0 >> 2, ac = cc0 & 3;
    const int br = cc0 >> 4, bc = cc0 & 15;

    float acc[4][4][4];
#pragma unroll
    for (int i = 0; i < 4; i++)
#pragma unroll
        for (int j = 0; j < 4; j++)
#pragma unroll
            for (int r = 0; r < 4; r++) acc[i][j][r] = 0.f;

#define GEMM_LOAD(stg, k0) do { \
    uint32_t s_ = sb + (stg) * GSTAGE; \
    const __half* p_; \
    p_ = Ag + (size_t)(m0 + ar) * K + (k0) + ac * 8; \
    CP16(s_ + ar*80 + ac*16, p_); CP16(s_ + ar*80 + ac*16 + 16, p_ + 8); \
    p_ = Bg + (size_t)((k0) + br) * N + n0 + bc * 8; \
    CP16(s_ + 10240 + br*272 + bc*16, p_); CP16(s_ + 10240 + br*272 + bc*16 + 16, p_ + 8); \
    CP_COMMIT; \
} while (0)

    const int ktiles = K >> 5;
    GEMM_LOAD(0, 0);
    GEMM_LOAD(1, 32);

    int stg = 0;
    for (int t = 0; t < ktiles; t++) {
        if (t + 1 < ktiles) CP_WAIT(1); else CP_WAIT(0);
        __syncthreads();
        if (t + 2 < ktiles) {
            int ns = stg + 2; if (ns >= 3) ns -= 3;
            GEMM_LOAD(ns, (t + 2) * 32);
        }

        const uint32_t sA = sb + stg * GSTAGE;
        const uint32_t sB = sA + 10240;

#pragma unroll
        for (int ks = 0; ks < 2; ks++) {
            const uint32_t a_off = (uint32_t)((warp_m * 64 + lane15) * 80 + (ks * 16 + lhi8) * 2);
            const uint32_t b_off = (uint32_t)((ks * 16 + lane15) * 272 + (warp_n * 32 + lhi8) * 2);

            uint32_t a[4][4];
            uint32_t bh[2][4];
#pragma unroll
            for (int mf = 0; mf < 4; mf++)
                LDSM4(a[mf][0],a[mf][1],a[mf][2],a[mf][3], sA + a_off + (uint32_t)(mf * 16 * 80));
#pragma unroll
            for (int p = 0; p < 2; p++)
                LDSM4T(bh[p][0],bh[p][1],bh[p][2],bh[p][3], sB + b_off + (uint32_t)(p * 32));
#pragma unroll
            for (int mf = 0; mf < 4; mf++)
#pragma unroll
                for (int nf = 0; nf < 4; nf++) {
                    const int p = nf >> 1, q = (nf & 1) * 2;
                    MMA16816H(acc[mf][nf], a[mf], bh[p][q], bh[p][q+1]);
                }
        }
        stg++; if (stg == 3) stg = 0;
    }

#pragma unroll
    for (int mf = 0; mf < 4; mf++) {
#pragma unroll
        for (int nf = 0; nf < 4; nf++) {
            const int row = m0 + warp_m * 64 + mf * 16 + gid;
            const int col = n0 + warp_n * 32 + nf * 8 + tig * 2;
            *(float2*)&C[(size_t)row * N + col] = make_float2(acc[mf][nf][0], acc[mf][nf][1]);
            *(float2*)&C[(size_t)(row + 8) * N + col] = make_float2(acc[mf][nf][2], acc[mf][nf][3]);
        }
    }
}

// ---------------- postprocess: gate+ve, RoPE, rmsnorm, fp16 out --------------
__global__ __launch_bounds__(256)
void postproc(const float* __restrict__ x, const float* __restrict__ ve,
              const float* __restrict__ cosb, const float* __restrict__ sinb,
              const float* __restrict__ Wgate)
{
    const int bt = blockIdx.x;
    const int b = bt >> 11, t = bt & (TT - 1);
    const int tid = threadIdx.x;
    const float* qkv = g_qkvbuf + (size_t)bt * 2048;

    __shared__ float gate[NKV];
    if (tid < NKV) {
        float acc = 0.f;
        const float* xr = x + (size_t)bt * CC;
#pragma unroll
        for (int c = 0; c < 32; c++) acc += xr[c] * Wgate[c * NKV + tid];
        gate[tid] = 2.f / (1.f + expf(-acc));
    }
    __syncthreads();

    for (int i = tid; i < NKV * HD; i += 256) {
        int hh = i >> 6, d = i & 63;
        float vv = qkv[1536 + i] + gate[hh] * ve[(size_t)bt * 512 + i];
        g_vattn[(((size_t)b * NKV + hh) * TT + t) * HD + d] = __float2half(vv);
    }

    const int w = tid >> 5, lane = tid & 31;
    const float cs = cosb[t * 32 + lane];
    const float sn = sinb[t * 32 + lane];
    const float eps = 1.1920929e-07f;

#pragma unroll
    for (int qi = 0; qi < 2; qi++) {
        int h = 2 * w + qi;
        const float* qr = qkv + h * HD;
        float x1 = qr[lane], x2 = qr[lane + 32];
        float r1 = x1 * cs + x2 * sn;
        float r2 = -x1 * sn + x2 * cs;
        float ss = r1 * r1 + r2 * r2;
#pragma unroll
        for (int o = 16; o; o >>= 1) ss += __shfl_xor_sync(0xffffffffu, ss, o);
        float sc = rsqrtf(ss * (1.f / 64.f) + eps);
        size_t idx = (((size_t)b * NH + h) * TT + t) * HD;
        g_qattn[idx + lane]      = __float2half(r1 * sc);
        g_qattn[idx + lane + 32] = __float2half(r2 * sc);
    }
    {
        const float* kr = qkv + 1024 + w * HD;
        float x1 = kr[lane], x2 = kr[lane + 32];
        float r1 = x1 * cs + x2 * sn;
        float r2 = -x1 * sn + x2 * cs;
        float ss = r1 * r1 + r2 * r2;
#pragma unroll
        for (int o = 16; o; o >>= 1) ss += __shfl_xor_sync(0xffffffffu, ss, o);
        float sc = rsqrtf(ss * (1.f / 64.f) + eps);
        size_t idx = (((size_t)b * NKV + w) * TT + t) * HD;
        g_kattn[idx + lane]      = __float2half(r1 * sc);
        g_kattn[idx + lane + 32] = __float2half(r2 * sc);
    }
}

// ---------------- tensor-core flash attention (fp16, pipelined) --------------
// BM=64, BN=64, 4 warps. smem: Q@0 (9216), 2 stages {K,V} at 9216+stg*18432.
// Total 46080.
__global__ __launch_bounds__(128)
void attn_mma(const int* __restrict__ wptr)
{
    extern __shared__ char sm[];
    const uint32_t sb = (uint32_t)__cvta_generic_to_shared(sm);
    const uint32_t sQ = sb;

    const int qt0 = (int)(gridDim.x - 1 - blockIdx.x) * 64;   // heavy blocks first
    const int bh = blockIdx.y;
    const int b = bh >> 4, h = bh & 15;
    const int window = *wptr;
    const bool is_local = (h >= 8);
    const int kvh = is_local ? 4 + ((h - 8) >> 1) : (h >> 1);

    const __half* qb = g_qattn + ((size_t)(b * NH + h) * TT) * HD;
    const __half* kb = g_kattn + ((size_t)(b * NKV + kvh) * TT) * HD;
    const __half* vb = g_vattn + ((size_t)(b * NKV + kvh) * TT) * HD;

    const int tid = threadIdx.x;
    const int lane = tid & 31, wid = tid >> 5;
    const int gid = lane >> 2, tig = lane & 3;
    const int lane15 = lane & 15, lhi8 = (lane >> 4) * 8;
    const int krow = (lane & 7) | ((lane & 16) >> 1);
    const int kc8 = lane & 8;

#define ATT_LOAD(stg, ktv) do { \
    uint32_t base_ = sb + 9216 + (stg) * 18432; \
    for (int c = tid; c < 512; c += 128) { \
        int row_ = c >> 3, c8_ = c & 7; \
        size_t g_ = (size_t)((ktv) + row_) * HD + c8_ * 8; \
        uint32_t d_ = base_ + row_ * 144 + c8_ * 16; \
        CP16(d_, kb + g_); CP16(d_ + 9216, vb + g_); \
    } CP_COMMIT; \
} while (0)

    int t0 = 0;
    if (is_local) { int s = qt0 - window; t0 = (s > 0 ? s : 0) & ~63; }
    const int nt = (qt0 - t0) / 64 + 1;

    for (int c = tid; c < 512; c += 128) {
        int row = c >> 3, c8 = c & 7;
        CP16(sQ + row * 144 + c8 * 16, qb + (size_t)(qt0 + row) * HD + c8 * 8);
    }
    CP_COMMIT;
    ATT_LOAD(0, t0);
    CP_WAIT(1);
    __syncthreads();

    uint32_t qf[4][4];
    {
        const uint32_t qa = (uint32_t)((wid * 16 + lane15) * 144 + lhi8 * 2);
#pragma unroll
        for (int ks = 0; ks < 4; ks++)
            LDSM4(qf[ks][0],qf[ks][1],qf[ks][2],qf[ks][3], sQ + qa + ks * 32);
    }

    float o[8][4];
#pragma unroll
    for (int nf = 0; nf < 8; nf++)
#pragma unroll
        for (int r = 0; r < 4; r++) o[nf][r] = 0.f;
    float m0r = -1e30f, m1r = -1e30f, l0r = 0.f, l1r = 0.f;

    const float scale = 0.125f;
    const int i0 = qt0 + wid * 16 + gid, i1 = i0 + 8;

    for (int it = 0; it < nt; it++) {
        const int kt = t0 + it * 64;
        const int stg = it & 1;
        if (it + 1 < nt) { ATT_LOAD(stg ^ 1, kt + 64); CP_WAIT(1); }
        else             { CP_WAIT(0); }
        __syncthreads();

        const uint32_t sK = sb + 9216 + stg * 18432;
        const uint32_t sV = sK + 9216;

        // ---- S = Q K^T
        float s[8][4];
#pragma unroll
        for (int nf = 0; nf < 8; nf++)
#pragma unroll
            for (int r = 0; r < 4; r++) s[nf][r] = 0.f;
#pragma unroll
        for (int ks = 0; ks < 4; ks++) {
#pragma unroll
            for (int g = 0; g < 4; g++) {
                const uint32_t ka = (uint32_t)((g * 16 + krow) * 144 + (ks * 16 + kc8) * 2);
                uint32_t b0,b1,b2,b3;
                LDSM4(b0,b1,b2,b3, sK + ka);
                MMA16816H(s[2*g],   qf[ks], b0, b1);
                MMA16816H(s[2*g+1], qf[ks], b2, b3);
            }
        }

        // ---- mask + scale
#pragma unroll
        for (int nf = 0; nf < 8; nf++) {
            int j0 = kt + nf * 8 + tig * 2, j1 = j0 + 1;
            bool k00 = (j0 <= i0) && (!is_local || j0 >= i0 - window);
            bool k01 = (j1 <= i0) && (!is_local || j1 >= i0 - window);
            bool k10 = (j0 <= i1) && (!is_local || j0 >= i1 - window);
            bool k11 = (j1 <= i1) && (!is_local || j1 >= i1 - window);
            s[nf][0] = k00 ? s[nf][0] * scale : -1e30f;
            s[nf][1] = k01 ? s[nf][1] * scale : -1e30f;
            s[nf][2] = k10 ? s[nf][2] * scale : -1e30f;
            s[nf][3] = k11 ? s[nf][3] * scale : -1e30f;
        }

        // ---- online softmax
        float t0m = -1e30f, t1m = -1e30f;
#pragma unroll
        for (int nf = 0; nf < 8; nf++) {
            t0m = fmaxf(t0m, fmaxf(s[nf][0], s[nf][1]));
            t1m = fmaxf(t1m, fmaxf(s[nf][2], s[nf][3]));
        }
        t0m = fmaxf(t0m, __shfl_xor_sync(0xffffffffu, t0m, 1));
        t0m = fmaxf(t0m, __shfl_xor_sync(0xffffffffu, t0m, 2));
        t1m = fmaxf(t1m, __shfl_xor_sync(0xffffffffu, t1m, 1));
        t1m = fmaxf(t1m, __shfl_xor_sync(0xffffffffu, t1m, 2));
        float mn0 = fmaxf(m0r, t0m), mn1 = fmaxf(m1r, t1m);
        float cr0 = __expf(m0r - mn0), cr1 = __expf(m1r - mn1);
        m0r = mn0; m1r = mn1;

        float ps0 = 0.f, ps1 = 0.f;
#pragma unroll
        for (int nf = 0; nf < 8; nf++) {
            float e0 = __expf(s[nf][0] - mn0), e1 = __expf(s[nf][1] - mn0);
            float e2 = __expf(s[nf][2] - mn1), e3 = __expf(s[nf][3] - mn1);
            ps0 += e0 + e1; ps1 += e2 + e3;
            s[nf][0] = e0; s[nf][1] = e1; s[nf][2] = e2; s[nf][3] = e3;
            o[nf][0] *= cr0; o[nf][1] *= cr0; o[nf][2] *= cr1; o[nf][3] *= cr1;
        }
        ps0 += __shfl_xor_sync(0xffffffffu, ps0, 1);
        ps0 += __shfl_xor_sync(0xffffffffu, ps0, 2);
        ps1 += __shfl_xor_sync(0xffffffffu, ps1, 1);
        ps1 += __shfl_xor_sync(0xffffffffu, ps1, 2);
        l0r = l0r * cr0 + ps0;
        l1r = l1r * cr1 + ps1;

        // ---- pack P (fp16)
        uint32_t ph[4][4];
#pragma unroll
        for (int ks = 0; ks < 4; ks++) {
            ph[ks][0] = hpack(__float2half(s[2*ks][0]),   __float2half(s[2*ks][1]));
            ph[ks][1] = hpack(__float2half(s[2*ks][2]),   __float2half(s[2*ks][3]));
            ph[ks][2] = hpack(__float2half(s[2*ks+1][0]), __float2half(s[2*ks+1][1]));
            ph[ks][3] = hpack(__float2half(s[2*ks+1][2]), __float2half(s[2*ks+1][3]));
        }

        // ---- O += P V
#pragma unroll
        for (int ks = 0; ks < 4; ks++) {
#pragma unroll
            for (int g = 0; g < 4; g++) {
                const uint32_t va = (uint32_t)((ks * 16 + lane15) * 144 + (g * 16 + lhi8) * 2);
                uint32_t v0,v1,v2,v3;
                LDSM4T(v0,v1,v2,v3, sV + va);
                MMA16816H(o[2*g],   ph[ks], v0, v1);
                MMA16816H(o[2*g+1], ph[ks], v2, v3);
            }
        }
        __syncthreads();
    }

    // ---- epilogue: y = O / l -> fp16, layout [bt, h*64+d]
    const float inv0 = 1.f / l0r, inv1 = 1.f / l1r;
    const int row0 = qt0 + wid * 16 + gid;
#pragma unroll
    for (int nf = 0; nf < 8; nf++) {
        const int col = h * 64 + nf * 8 + tig * 2;
        *(uint32_t*)(g_yattn + (size_t)(b * TT + row0) * CC + col) =
            hpack(__float2half(o[nf][0] * inv0), __float2half(o[nf][1] * inv0));
        *(uint32_t*)(g_yattn + (size_t)(b * TT + row0 + 8) * CC + col) =
            hpack(__float2half(o[nf][2] * inv1), __float2half(o[nf][3] * inv1));
    }
}

// ---------------- launch ------------------------------------------------------
extern "C" void kernel_launch(void* const* d_in, const int* in_sizes, int n_in,
                              void* d_out, int out_size)
{
    const float* x     = (const float*)d_in[0];
    const float* ve    = (const float*)d_in[1];
    const float* cosb  = (const float*)d_in[2];
    const float* sinb  = (const float*)d_in[3];
    const float* Wq    = (const float*)d_in[4];
    const float* Wk    = (const float*)d_in[5];
    const float* Wv    = (const float*)d_in[6];
    const float* Wproj = (const float*)d_in[7];
    const float* Wgate = (const float*)d_in[8];
    const int*   wptr  = (const int*)d_in[9];

    float* qkvbuf;
    cudaGetSymbolAddress((void**)&qkvbuf, g_qkvbuf);
    __half *xh, *wch, *wph, *yh;
    cudaGetSymbolAddress((void**)&xh, g_xh);
    cudaGetSymbolAddress((void**)&wch, g_wch);
    cudaGetSymbolAddress((void**)&wph, g_wph);
    cudaGetSymbolAddress((void**)&yh, g_yattn);

    cudaFuncSetAttribute(gemm_f16, cudaFuncAttributeMaxDynamicSharedMemorySize, 3 * GSTAGE);
    cudaFuncSetAttribute(attn_mma, cudaFuncAttributeMaxDynamicSharedMemorySize, 46080);

    // fused conversion (x, Wq, Wk, Wv, Wproj -> fp16)
    convert_all<<<7168, 256>>>(x, Wq, Wk, Wv, Wproj);

    // fused QKV projection (fp16)
    gemm_f16<<<dim3(16, 32), 256, 3 * GSTAGE>>>(xh, wch, qkvbuf, BT, 2048, CC);

    // gate + ve, rope, rmsnorm -> fp16 q/k/v
    postproc<<<BT, 256>>>(x, ve, cosb, sinb, Wgate);

    // attention (fp16) -> fp16 y
    attn_mma<<<dim3(TT / 64, BB * NH), 128, 46080>>>(wptr);

    // output projection (fp16) -> d_out
    gemm_f16<<<dim3(8, 32), 256, 3 * GSTAGE>>>(yh, wph, (float*)d_out, BT, 1024, CC);
}

// round 9
// speedup vs baseline: 8.8235x; 1.1271x over previous
#include <cuda_runtime.h>
#include <cuda_fp16.h>
#include <cstdint>

// Problem constants
#define BB 2
#define TT 2048
#define CC 1024
#define NH 16
#define NKV 8
#define HD 64
#define BT (BB*TT)          // 4096

// ---------------- scratch (device globals) ----------------------------------
__device__ float g_qkvbuf[BT * 2048];          // fused [q(1024)|k(512)|v(512)]

__device__ __half g_xh[BT * CC];               // x fp16
__device__ __half g_wch[CC * 2048];            // Wq|Wk|Wv fp16 [K,2048]
__device__ __half g_wph[CC * CC];              // Wproj fp16 [K,N]

__device__ __half g_qattn[BB*NH*TT*HD];        // [b,h,t,d] fp16 (pre-scaled by 1/8)
__device__ __half g_kattn[BB*NKV*TT*HD];       // [b,kh,t,d]
__device__ __half g_vattn[BB*NKV*TT*HD];
__device__ __half g_yattn[BT * CC];            // attn out fp16 [bt, h*d]

// ---------------- PTX helpers ------------------------------------------------
#define LDSM4(r0,r1,r2,r3,addr) \
    asm volatile("ldmatrix.sync.aligned.m8n8.x4.shared.b16 {%0,%1,%2,%3}, [%4];" \
                 : "=r"(r0),"=r"(r1),"=r"(r2),"=r"(r3) : "r"(addr))
#define LDSM4T(r0,r1,r2,r3,addr) \
    asm volatile("ldmatrix.sync.aligned.m8n8.x4.trans.shared.b16 {%0,%1,%2,%3}, [%4];" \
                 : "=r"(r0),"=r"(r1),"=r"(r2),"=r"(r3) : "r"(addr))
#define MMA16816H(d, a, b0, b1) \
    asm volatile("mma.sync.aligned.m16n8k16.row.col.f32.f16.f16.f32 " \
                 "{%0,%1,%2,%3}, {%4,%5,%6,%7}, {%8,%9}, {%0,%1,%2,%3};" \
                 : "+f"(d[0]),"+f"(d[1]),"+f"(d[2]),"+f"(d[3]) \
                 : "r"(a[0]),"r"(a[1]),"r"(a[2]),"r"(a[3]), "r"(b0),"r"(b1))
#define CP16(dst, src) \
    asm volatile("cp.async.cg.shared.global [%0], [%1], 16;" :: "r"(dst), "l"(src))
#define CP_COMMIT asm volatile("cp.async.commit_group;")
#define CP_WAIT(N) asm volatile("cp.async.wait_group %0;" :: "n"(N))

__device__ __forceinline__ uint32_t hpack(__half e0, __half e1) {
    return ((uint32_t)__half_as_ushort(e1) << 16) | (uint32_t)__half_as_ushort(e0);
}
__device__ __forceinline__ uint2 cvt4h(float4 v) {
    return make_uint2(hpack(__float2half(v.x), __float2half(v.y)),
                      hpack(__float2half(v.z), __float2half(v.w)));
}

// ---------------- fused conversion: all fp32 inputs -> fp16 ------------------
__global__ __launch_bounds__(256)
void convert_all(const float* __restrict__ x,  const float* __restrict__ Wq,
                 const float* __restrict__ Wk, const float* __restrict__ Wv,
                 const float* __restrict__ Wp)
{
    const int i4 = blockIdx.x * 256 + threadIdx.x;
    if (i4 < 1048576) {
        *(uint2*)(g_xh + (size_t)i4 * 4) = cvt4h(*(const float4*)(x + (size_t)i4 * 4));
    } else if (i4 < 1310720) {
        int j = (i4 - 1048576) * 4;
        int r = j >> 10, c = j & 1023;
        *(uint2*)(g_wch + (size_t)r * 2048 + c) = cvt4h(*(const float4*)(Wq + j));
    } else if (i4 < 1441792) {
        int j = (i4 - 1310720) * 4;
        int r = j >> 9, c = j & 511;
        *(uint2*)(g_wch + (size_t)r * 2048 + 1024 + c) = cvt4h(*(const float4*)(Wk + j));
    } else if (i4 < 1572864) {
        int j = (i4 - 1441792) * 4;
        int r = j >> 9, c = j & 511;
        *(uint2*)(g_wch + (size_t)r * 2048 + 1536 + c) = cvt4h(*(const float4*)(Wv + j));
    } else {
        int j = (i4 - 1572864) * 4;
        *(uint2*)(g_wph + j) = cvt4h(*(const float4*)(Wp + j));
    }
}

// ---------------- GEMM: C = A @ B, fp16 single, fp32 out ---------------------
#define GSTAGE 18944
// stage: A@0 (128x40x2=10240), B@10240 (32x136x2=8704)

__global__ __launch_bounds__(256)
void gemm_f16(const __half* __restrict__ Ag, const __half* __restrict__ Bg,
              float* __restrict__ C, int M, int N, int K)
{
    extern __shared__ char sm[];
    const int tid = threadIdx.x;
    const int lane = tid & 31, wid = tid >> 5;
    const int warp_m = wid & 1, warp_n = wid >> 1;
    const int gid = lane >> 2, tig = lane & 3;
    const int lane15 = lane & 15, lhi8 = (lane >> 4) * 8;
    const int m0 = blockIdx.y * 128, n0 = blockIdx.x * 128;
    const uint32_t sb = (uint32_t)__cvta_generic_to_shared(sm);

    const int cc0 = tid * 2;
    const int ar = cc0 >> 2, ac = cc0 & 3;
    const int br = cc0 >> 4, bc = cc0 & 15;

    float acc[4][4][4];
#pragma unroll
    for (int i = 0; i < 4; i++)
#pragma unroll
        for (int j = 0; j < 4; j++)
#pragma unroll
            for (int r = 0; r < 4; r++) acc[i][j][r] = 0.f;

#define GEMM_LOAD(stg, k0) do { \
    uint32_t s_ = sb + (stg) * GSTAGE; \
    const __half* p_; \
    p_ = Ag + (size_t)(m0 + ar) * K + (k0) + ac * 8; \
    CP16(s_ + ar*80 + ac*16, p_); CP16(s_ + ar*80 + ac*16 + 16, p_ + 8); \
    p_ = Bg + (size_t)((k0) + br) * N + n0 + bc * 8; \
    CP16(s_ + 10240 + br*272 + bc*16, p_); CP16(s_ + 10240 + br*272 + bc*16 + 16, p_ + 8); \
    CP_COMMIT; \
} while (0)

    const int ktiles = K >> 5;
    GEMM_LOAD(0, 0);
    GEMM_LOAD(1, 32);

    int stg = 0;
    for (int t = 0; t < ktiles; t++) {
        if (t + 1 < ktiles) CP_WAIT(1); else CP_WAIT(0);
        __syncthreads();
        if (t + 2 < ktiles) {
            int ns = stg + 2; if (ns >= 3) ns -= 3;
            GEMM_LOAD(ns, (t + 2) * 32);
        }

        const uint32_t sA = sb + stg * GSTAGE;
        const uint32_t sB = sA + 10240;

#pragma unroll
        for (int ks = 0; ks < 2; ks++) {
            const uint32_t a_off = (uint32_t)((warp_m * 64 + lane15) * 80 + (ks * 16 + lhi8) * 2);
            const uint32_t b_off = (uint32_t)((ks * 16 + lane15) * 272 + (warp_n * 32 + lhi8) * 2);

            uint32_t a[4][4];
            uint32_t bh[2][4];
#pragma unroll
            for (int mf = 0; mf < 4; mf++)
                LDSM4(a[mf][0],a[mf][1],a[mf][2],a[mf][3], sA + a_off + (uint32_t)(mf * 16 * 80));
#pragma unroll
            for (int p = 0; p < 2; p++)
                LDSM4T(bh[p][0],bh[p][1],bh[p][2],bh[p][3], sB + b_off + (uint32_t)(p * 32));
#pragma unroll
            for (int mf = 0; mf < 4; mf++)
#pragma unroll
                for (int nf = 0; nf < 4; nf++) {
                    const int p = nf >> 1, q = (nf & 1) * 2;
                    MMA16816H(acc[mf][nf], a[mf], bh[p][q], bh[p][q+1]);
                }
        }
        stg++; if (stg == 3) stg = 0;
    }

#pragma unroll
    for (int mf = 0; mf < 4; mf++) {
#pragma unroll
        for (int nf = 0; nf < 4; nf++) {
            const int row = m0 + warp_m * 64 + mf * 16 + gid;
            const int col = n0 + warp_n * 32 + nf * 8 + tig * 2;
            *(float2*)&C[(size_t)row * N + col] = make_float2(acc[mf][nf][0], acc[mf][nf][1]);
            *(float2*)&C[(size_t)(row + 8) * N + col] = make_float2(acc[mf][nf][2], acc[mf][nf][3]);
        }
    }
}

// ---------------- postprocess: gate+ve, RoPE, rmsnorm, fp16 out --------------
// q is pre-scaled by 1/8 (exact power of two) so attention skips score scaling.
__global__ __launch_bounds__(256)
void postproc(const float* __restrict__ x, const float* __restrict__ ve,
              const float* __restrict__ cosb, const float* __restrict__ sinb,
              const float* __restrict__ Wgate)
{
    const int bt = blockIdx.x;
    const int b = bt >> 11, t = bt & (TT - 1);
    const int tid = threadIdx.x;
    const float* qkv = g_qkvbuf + (size_t)bt * 2048;

    __shared__ float gate[NKV];
    if (tid < NKV) {
        float acc = 0.f;
        const float* xr = x + (size_t)bt * CC;
#pragma unroll
        for (int c = 0; c < 32; c++) acc += xr[c] * Wgate[c * NKV + tid];
        gate[tid] = 2.f / (1.f + expf(-acc));
    }
    __syncthreads();

    for (int i = tid; i < NKV * HD; i += 256) {
        int hh = i >> 6, d = i & 63;
        float vv = qkv[1536 + i] + gate[hh] * ve[(size_t)bt * 512 + i];
        g_vattn[(((size_t)b * NKV + hh) * TT + t) * HD + d] = __float2half(vv);
    }

    const int w = tid >> 5, lane = tid & 31;
    const float cs = cosb[t * 32 + lane];
    const float sn = sinb[t * 32 + lane];
    const float eps = 1.1920929e-07f;

#pragma unroll
    for (int qi = 0; qi < 2; qi++) {
        int h = 2 * w + qi;
        const float* qr = qkv + h * HD;
        float x1 = qr[lane], x2 = qr[lane + 32];
        float r1 = x1 * cs + x2 * sn;
        float r2 = -x1 * sn + x2 * cs;
        float ss = r1 * r1 + r2 * r2;
#pragma unroll
        for (int o = 16; o; o >>= 1) ss += __shfl_xor_sync(0xffffffffu, ss, o);
        float sc = rsqrtf(ss * (1.f / 64.f) + eps) * 0.125f;   // fold 1/sqrt(64)
        size_t idx = (((size_t)b * NH + h) * TT + t) * HD;
        g_qattn[idx + lane]      = __float2half(r1 * sc);
        g_qattn[idx + lane + 32] = __float2half(r2 * sc);
    }
    {
        const float* kr = qkv + 1024 + w * HD;
        float x1 = kr[lane], x2 = kr[lane + 32];
        float r1 = x1 * cs + x2 * sn;
        float r2 = -x1 * sn + x2 * cs;
        float ss = r1 * r1 + r2 * r2;
#pragma unroll
        for (int o = 16; o; o >>= 1) ss += __shfl_xor_sync(0xffffffffu, ss, o);
        float sc = rsqrtf(ss * (1.f / 64.f) + eps);
        size_t idx = (((size_t)b * NKV + w) * TT + t) * HD;
        g_kattn[idx + lane]      = __float2half(r1 * sc);
        g_kattn[idx + lane + 32] = __float2half(r2 * sc);
    }
}

// ---------------- tensor-core flash attention (fp16, pipelined) --------------
// BM=64, BN=64, 4 warps. smem: Q@0 (9216), 2 stages {K,V} at 9216+stg*18432.
__global__ __launch_bounds__(128)
void attn_mma(const int* __restrict__ wptr)
{
    extern __shared__ char sm[];
    const uint32_t sb = (uint32_t)__cvta_generic_to_shared(sm);
    const uint32_t sQ = sb;

    const int qt0 = (int)(gridDim.x - 1 - blockIdx.x) * 64;   // heavy blocks first
    const int bh = blockIdx.y;
    const int b = bh >> 4, h = bh & 15;
    const int window = *wptr;
    const bool is_local = (h >= 8);
    const int kvh = is_local ? 4 + ((h - 8) >> 1) : (h >> 1);

    const __half* qb = g_qattn + ((size_t)(b * NH + h) * TT) * HD;
    const __half* kb = g_kattn + ((size_t)(b * NKV + kvh) * TT) * HD;
    const __half* vb = g_vattn + ((size_t)(b * NKV + kvh) * TT) * HD;

    const int tid = threadIdx.x;
    const int lane = tid & 31, wid = tid >> 5;
    const int gid = lane >> 2, tig = lane & 3;
    const int lane15 = lane & 15, lhi8 = (lane >> 4) * 8;
    const int krow = (lane & 7) | ((lane & 16) >> 1);
    const int kc8 = lane & 8;

#define ATT_LOAD(stg, ktv) do { \
    uint32_t base_ = sb + 9216 + (stg) * 18432; \
    for (int c = tid; c < 512; c += 128) { \
        int row_ = c >> 3, c8_ = c & 7; \
        size_t g_ = (size_t)((ktv) + row_) * HD + c8_ * 8; \
        uint32_t d_ = base_ + row_ * 144 + c8_ * 16; \
        CP16(d_, kb + g_); CP16(d_ + 9216, vb + g_); \
    } CP_COMMIT; \
} while (0)

    int t0 = 0;
    if (is_local) { int s = qt0 - window; t0 = (s > 0 ? s : 0) & ~63; }
    const int nt = (qt0 - t0) / 64 + 1;

    for (int c = tid; c < 512; c += 128) {
        int row = c >> 3, c8 = c & 7;
        CP16(sQ + row * 144 + c8 * 16, qb + (size_t)(qt0 + row) * HD + c8 * 8);
    }
    CP_COMMIT;
    ATT_LOAD(0, t0);
    CP_WAIT(1);
    __syncthreads();

    uint32_t qf[4][4];
    {
        const uint32_t qa = (uint32_t)((wid * 16 + lane15) * 144 + lhi8 * 2);
#pragma unroll
        for (int ks = 0; ks < 4; ks++)
            LDSM4(qf[ks][0],qf[ks][1],qf[ks][2],qf[ks][3], sQ + qa + ks * 32);
    }

    float o[8][4];
#pragma unroll
    for (int nf = 0; nf < 8; nf++)
#pragma unroll
        for (int r = 0; r < 4; r++) o[nf][r] = 0.f;
    float m0r = -1e30f, m1r = -1e30f, l0r = 0.f, l1r = 0.f;

    const int i0 = qt0 + wid * 16 + gid, i1 = i0 + 8;

    for (int it = 0; it < nt; it++) {
        const int kt = t0 + it * 64;
        const int stg = it & 1;
        if (it + 1 < nt) { ATT_LOAD(stg ^ 1, kt + 64); CP_WAIT(1); }
        else             { CP_WAIT(0); }
        __syncthreads();

        const uint32_t sK = sb + 9216 + stg * 18432;
        const uint32_t sV = sK + 9216;

        // ---- S = Q K^T   (scores already scaled: q pre-multiplied by 1/8)
        float s[8][4];
#pragma unroll
        for (int nf = 0; nf < 8; nf++)
#pragma unroll
            for (int r = 0; r < 4; r++) s[nf][r] = 0.f;
#pragma unroll
        for (int ks = 0; ks < 4; ks++) {
#pragma unroll
            for (int g = 0; g < 4; g++) {
                const uint32_t ka = (uint32_t)((g * 16 + krow) * 144 + (ks * 16 + kc8) * 2);
                uint32_t b0,b1,b2,b3;
                LDSM4(b0,b1,b2,b3, sK + ka);
                MMA16816H(s[2*g],   qf[ks], b0, b1);
                MMA16816H(s[2*g+1], qf[ks], b2, b3);
            }
        }

        // ---- mask only boundary tiles (causal diagonal / window edge)
        const bool need_mask = (kt + 64 > qt0) ||
                               (is_local && kt + window < qt0 + 64);
        if (need_mask) {
#pragma unroll
            for (int nf = 0; nf < 8; nf++) {
                int j0 = kt + nf * 8 + tig * 2, j1 = j0 + 1;
                bool k00 = (j0 <= i0) && (!is_local || j0 >= i0 - window);
                bool k01 = (j1 <= i0) && (!is_local || j1 >= i0 - window);
                bool k10 = (j0 <= i1) && (!is_local || j0 >= i1 - window);
                bool k11 = (j1 <= i1) && (!is_local || j1 >= i1 - window);
                if (!k00) s[nf][0] = -1e30f;
                if (!k01) s[nf][1] = -1e30f;
                if (!k10) s[nf][2] = -1e30f;
                if (!k11) s[nf][3] = -1e30f;
            }
        }

        // ---- online softmax
        float t0m = -1e30f, t1m = -1e30f;
#pragma unroll
        for (int nf = 0; nf < 8; nf++) {
            t0m = fmaxf(t0m, fmaxf(s[nf][0], s[nf][1]));
            t1m = fmaxf(t1m, fmaxf(s[nf][2], s[nf][3]));
        }
        t0m = fmaxf(t0m, __shfl_xor_sync(0xffffffffu, t0m, 1));
        t0m = fmaxf(t0m, __shfl_xor_sync(0xffffffffu, t0m, 2));
        t1m = fmaxf(t1m, __shfl_xor_sync(0xffffffffu, t1m, 1));
        t1m = fmaxf(t1m, __shfl_xor_sync(0xffffffffu, t1m, 2));
        float mn0 = fmaxf(m0r, t0m), mn1 = fmaxf(m1r, t1m);
        float cr0 = __expf(m0r - mn0), cr1 = __expf(m1r - mn1);
        m0r = mn0; m1r = mn1;

        // rescale o only if any row's max actually grew (exact check: cr==1.0)
        bool upd = (cr0 != 1.f) || (cr1 != 1.f);
        if (__any_sync(0xffffffffu, upd)) {
#pragma unroll
            for (int nf = 0; nf < 8; nf++) {
                o[nf][0] *= cr0; o[nf][1] *= cr0; o[nf][2] *= cr1; o[nf][3] *= cr1;
            }
        }

        float ps0 = 0.f, ps1 = 0.f;
#pragma unroll
        for (int nf = 0; nf < 8; nf++) {
            float e0 = __expf(s[nf][0] - mn0), e1 = __expf(s[nf][1] - mn0);
            float e2 = __expf(s[nf][2] - mn1), e3 = __expf(s[nf][3] - mn1);
            ps0 += e0 + e1; ps1 += e2 + e3;
            s[nf][0] = e0; s[nf][1] = e1; s[nf][2] = e2; s[nf][3] = e3;
        }
        ps0 += __shfl_xor_sync(0xffffffffu, ps0, 1);
        ps0 += __shfl_xor_sync(0xffffffffu, ps0, 2);
        ps1 += __shfl_xor_sync(0xffffffffu, ps1, 1);
        ps1 += __shfl_xor_sync(0xffffffffu, ps1, 2);
        l0r = l0r * cr0 + ps0;
        l1r = l1r * cr1 + ps1;

        // ---- pack P (fp16)
        uint32_t ph[4][4];
#pragma unroll
        for (int ks = 0; ks < 4; ks++) {
            ph[ks][0] = hpack(__float2half(s[2*ks][0]),   __float2half(s[2*ks][1]));
            ph[ks][1] = hpack(__float2half(s[2*ks][2]),   __float2half(s[2*ks][3]));
            ph[ks][2] = hpack(__float2half(s[2*ks+1][0]), __float2half(s[2*ks+1][1]));
            ph[ks][3] = hpack(__float2half(s[2*ks+1][2]), __float2half(s[2*ks+1][3]));
        }

        // ---- O += P V
#pragma unroll
        for (int ks = 0; ks < 4; ks++) {
#pragma unroll
            for (int g = 0; g < 4; g++) {
                const uint32_t va = (uint32_t)((ks * 16 + lane15) * 144 + (g * 16 + lhi8) * 2);
                uint32_t v0,v1,v2,v3;
                LDSM4T(v0,v1,v2,v3, sV + va);
                MMA16816H(o[2*g],   ph[ks], v0, v1);
                MMA16816H(o[2*g+1], ph[ks], v2, v3);
            }
        }
        __syncthreads();
    }

    // ---- epilogue: y = O / l -> fp16, layout [bt, h*64+d]
    const float inv0 = 1.f / l0r, inv1 = 1.f / l1r;
    const int row0 = qt0 + wid * 16 + gid;
#pragma unroll
    for (int nf = 0; nf < 8; nf++) {
        const int col = h * 64 + nf * 8 + tig * 2;
        *(uint32_t*)(g_yattn + (size_t)(b * TT + row0) * CC + col) =
            hpack(__float2half(o[nf][0] * inv0), __float2half(o[nf][1] * inv0));
        *(uint32_t*)(g_yattn + (size_t)(b * TT + row0 + 8) * CC + col) =
            hpack(__float2half(o[nf][2] * inv1), __float2half(o[nf][3] * inv1));
    }
}

// ---------------- launch ------------------------------------------------------
extern "C" void kernel_launch(void* const* d_in, const int* in_sizes, int n_in,
                              void* d_out, int out_size)
{
    const float* x     = (const float*)d_in[0];
    const float* ve    = (const float*)d_in[1];
    const float* cosb  = (const float*)d_in[2];
    const float* sinb  = (const float*)d_in[3];
    const float* Wq    = (const float*)d_in[4];
    const float* Wk    = (const float*)d_in[5];
    const float* Wv    = (const float*)d_in[6];
    const float* Wproj = (const float*)d_in[7];
    const float* Wgate = (const float*)d_in[8];
    const int*   wptr  = (const int*)d_in[9];

    float* qkvbuf;
    cudaGetSymbolAddress((void**)&qkvbuf, g_qkvbuf);
    __half *xh, *wch, *wph, *yh;
    cudaGetSymbolAddress((void**)&xh, g_xh);
    cudaGetSymbolAddress((void**)&wch, g_wch);
    cudaGetSymbolAddress((void**)&wph, g_wph);
    cudaGetSymbolAddress((void**)&yh, g_yattn);

    cudaFuncSetAttribute(gemm_f16, cudaFuncAttributeMaxDynamicSharedMemorySize, 3 * GSTAGE);
    cudaFuncSetAttribute(attn_mma, cudaFuncAttributeMaxDynamicSharedMemorySize, 46080);

    // fused conversion (x, Wq, Wk, Wv, Wproj -> fp16)
    convert_all<<<7168, 256>>>(x, Wq, Wk, Wv, Wproj);

    // fused QKV projection (fp16)
    gemm_f16<<<dim3(16, 32), 256, 3 * GSTAGE>>>(xh, wch, qkvbuf, BT, 2048, CC);

    // gate + ve, rope, rmsnorm -> fp16 q/k/v (q pre-scaled)
    postproc<<<BT, 256>>>(x, ve, cosb, sinb, Wgate);

    // attention (fp16) -> fp16 y
    attn_mma<<<dim3(TT / 64, BB * NH), 128, 46080>>>(wptr);

    // output projection (fp16) -> d_out
    gemm_f16<<<dim3(8, 32), 256, 3 * GSTAGE>>>(yh, wph, (float*)d_out, BT, 1024, CC);
}

// round 10
// speedup vs baseline: 9.0295x; 1.0234x over previous
#include <cuda_runtime.h>
#include <cuda_fp16.h>
#include <cstdint>

// Problem constants
#define BB 2
#define TT 2048
#define CC 1024
#define NH 16
#define NKV 8
#define HD 64
#define BT (BB*TT)          // 4096

// ---------------- scratch (device globals) ----------------------------------
__device__ float g_qkvbuf[BT * 2048];          // fused [q(1024)|k(512)|v(512)]

__device__ __half g_xh[BT * CC];               // x fp16
__device__ __half g_wch[CC * 2048];            // Wq|Wk|Wv fp16 [K,2048]
__device__ __half g_wph[CC * CC];              // Wproj fp16 [K,N]

__device__ __half g_qattn[BB*NH*TT*HD];        // [b,h,t,d] fp16 (pre-scaled by log2e/8)
__device__ __half g_kattn[BB*NKV*TT*HD];       // [b,kh,t,d]
__device__ __half g_vattn[BB*NKV*TT*HD];
__device__ __half g_yattn[BT * CC];            // attn out fp16 [bt, h*d]

// ---------------- PTX helpers ------------------------------------------------
#define LDSM4(r0,r1,r2,r3,addr) \
    asm volatile("ldmatrix.sync.aligned.m8n8.x4.shared.b16 {%0,%1,%2,%3}, [%4];" \
                 : "=r"(r0),"=r"(r1),"=r"(r2),"=r"(r3) : "r"(addr))
#define LDSM4T(r0,r1,r2,r3,addr) \
    asm volatile("ldmatrix.sync.aligned.m8n8.x4.trans.shared.b16 {%0,%1,%2,%3}, [%4];" \
                 : "=r"(r0),"=r"(r1),"=r"(r2),"=r"(r3) : "r"(addr))
#define MMA16816H(d, a, b0, b1) \
    asm volatile("mma.sync.aligned.m16n8k16.row.col.f32.f16.f16.f32 " \
                 "{%0,%1,%2,%3}, {%4,%5,%6,%7}, {%8,%9}, {%0,%1,%2,%3};" \
                 : "+f"(d[0]),"+f"(d[1]),"+f"(d[2]),"+f"(d[3]) \
                 : "r"(a[0]),"r"(a[1]),"r"(a[2]),"r"(a[3]), "r"(b0),"r"(b1))
#define CP16(dst, src) \
    asm volatile("cp.async.cg.shared.global [%0], [%1], 16;" :: "r"(dst), "l"(src))
#define CP_COMMIT asm volatile("cp.async.commit_group;")
#define CP_WAIT(N) asm volatile("cp.async.wait_group %0;" :: "n"(N))
// pack two f32 -> one f16x2 register (lo = first arg)
#define CVTF16X2(r, lo, hi) \
    asm("cvt.rn.f16x2.f32 %0, %1, %2;" : "=r"(r) : "f"(hi), "f"(lo))

__device__ __forceinline__ uint32_t hpack(__half e0, __half e1) {
    return ((uint32_t)__half_as_ushort(e1) << 16) | (uint32_t)__half_as_ushort(e0);
}
__device__ __forceinline__ uint2 cvt4h(float4 v) {
    uint32_t a, b;
    CVTF16X2(a, v.x, v.y);
    CVTF16X2(b, v.z, v.w);
    return make_uint2(a, b);
}

// ---------------- fused conversion: all fp32 inputs -> fp16 ------------------
__global__ __launch_bounds__(256)
void convert_all(const float* __restrict__ x,  const float* __restrict__ Wq,
                 const float* __restrict__ Wk, const float* __restrict__ Wv,
                 const float* __restrict__ Wp)
{
    const int i4 = blockIdx.x * 256 + threadIdx.x;
    if (i4 < 1048576) {
        *(uint2*)(g_xh + (size_t)i4 * 4) = cvt4h(*(const float4*)(x + (size_t)i4 * 4));
    } else if (i4 < 1310720) {
        int j = (i4 - 1048576) * 4;
        int r = j >> 10, c = j & 1023;
        *(uint2*)(g_wch + (size_t)r * 2048 + c) = cvt4h(*(const float4*)(Wq + j));
    } else if (i4 < 1441792) {
        int j = (i4 - 1310720) * 4;
        int r = j >> 9, c = j & 511;
        *(uint2*)(g_wch + (size_t)r * 2048 + 1024 + c) = cvt4h(*(const float4*)(Wk + j));
    } else if (i4 < 1572864) {
        int j = (i4 - 1441792) * 4;
        int r = j >> 9, c = j & 511;
        *(uint2*)(g_wch + (size_t)r * 2048 + 1536 + c) = cvt4h(*(const float4*)(Wv + j));
    } else {
        int j = (i4 - 1572864) * 4;
        *(uint2*)(g_wph + j) = cvt4h(*(const float4*)(Wp + j));
    }
}

// ---------------- GEMM: C = A @ B, fp16 single, fp32 out ---------------------
#define GSTAGE 18944
// stage: A@0 (128x40x2=10240), B@10240 (32x136x2=8704)

__global__ __launch_bounds__(256)
void gemm_f16(const __half* __restrict__ Ag, const __half* __restrict__ Bg,
              float* __restrict__ C, int M, int N, int K)
{
    extern __shared__ char sm[];
    const int tid = threadIdx.x;
    const int lane = tid & 31, wid = tid >> 5;
    const int warp_m = wid & 1, warp_n = wid >> 1;
    const int gid = lane >> 2, tig = lane & 3;
    const int lane15 = lane & 15, lhi8 = (lane >> 4) * 8;
    const int m0 = blockIdx.y * 128, n0 = blockIdx.x * 128;
    const uint32_t sb = (uint32_t)__cvta_generic_to_shared(sm);

    const int cc0 = tid * 2;
    const int ar = cc0 >> 2, ac = cc0 & 3;
    const int br = cc0 >> 4, bc = cc0 & 15;

    float acc[4][4][4];
#pragma unroll
    for (int i = 0; i < 4; i++)
#pragma unroll
        for (int j = 0; j < 4; j++)
#pragma unroll
            for (int r = 0; r < 4; r++) acc[i][j][r] = 0.f;

#define GEMM_LOAD(stg, k0) do { \
    uint32_t s_ = sb + (stg) * GSTAGE; \
    const __half* p_; \
    p_ = Ag + (size_t)(m0 + ar) * K + (k0) + ac * 8; \
    CP16(s_ + ar*80 + ac*16, p_); CP16(s_ + ar*80 + ac*16 + 16, p_ + 8); \
    p_ = Bg + (size_t)((k0) + br) * N + n0 + bc * 8; \
    CP16(s_ + 10240 + br*272 + bc*16, p_); CP16(s_ + 10240 + br*272 + bc*16 + 16, p_ + 8); \
    CP_COMMIT; \
} while (0)

    const int ktiles = K >> 5;
    GEMM_LOAD(0, 0);
    GEMM_LOAD(1, 32);

    int stg = 0;
    for (int t = 0; t < ktiles; t++) {
        if (t + 1 < ktiles) CP_WAIT(1); else CP_WAIT(0);
        __syncthreads();
        if (t + 2 < ktiles) {
            int ns = stg + 2; if (ns >= 3) ns -= 3;
            GEMM_LOAD(ns, (t + 2) * 32);
        }

        const uint32_t sA = sb + stg * GSTAGE;
        const uint32_t sB = sA + 10240;

#pragma unroll
        for (int ks = 0; ks < 2; ks++) {
            const uint32_t a_off = (uint32_t)((warp_m * 64 + lane15) * 80 + (ks * 16 + lhi8) * 2);
            const uint32_t b_off = (uint32_t)((ks * 16 + lane15) * 272 + (warp_n * 32 + lhi8) * 2);

            uint32_t a[4][4];
            uint32_t bh[2][4];
#pragma unroll
            for (int mf = 0; mf < 4; mf++)
                LDSM4(a[mf][0],a[mf][1],a[mf][2],a[mf][3], sA + a_off + (uint32_t)(mf * 16 * 80));
#pragma unroll
            for (int p = 0; p < 2; p++)
                LDSM4T(bh[p][0],bh[p][1],bh[p][2],bh[p][3], sB + b_off + (uint32_t)(p * 32));
#pragma unroll
            for (int mf = 0; mf < 4; mf++)
#pragma unroll
                for (int nf = 0; nf < 4; nf++) {
                    const int p = nf >> 1, q = (nf & 1) * 2;
                    MMA16816H(acc[mf][nf], a[mf], bh[p][q], bh[p][q+1]);
                }
        }
        stg++; if (stg == 3) stg = 0;
    }

#pragma unroll
    for (int mf = 0; mf < 4; mf++) {
#pragma unroll
        for (int nf = 0; nf < 4; nf++) {
            const int row = m0 + warp_m * 64 + mf * 16 + gid;
            const int col = n0 + warp_n * 32 + nf * 8 + tig * 2;
            *(float2*)&C[(size_t)row * N + col] = make_float2(acc[mf][nf][0], acc[mf][nf][1]);
            *(float2*)&C[(size_t)(row + 8) * N + col] = make_float2(acc[mf][nf][2], acc[mf][nf][3]);
        }
    }
}

// ---------------- postprocess: gate+ve, RoPE, rmsnorm, fp16 out --------------
// q pre-scaled by log2e/8 so attention scores are already in the exp2 domain
// with the 1/sqrt(64) factor folded in.
__global__ __launch_bounds__(256)
void postproc(const float* __restrict__ x, const float* __restrict__ ve,
              const float* __restrict__ cosb, const float* __restrict__ sinb,
              const float* __restrict__ Wgate)
{
    const int bt = blockIdx.x;
    const int b = bt >> 11, t = bt & (TT - 1);
    const int tid = threadIdx.x;
    const float* qkv = g_qkvbuf + (size_t)bt * 2048;

    __shared__ float gate[NKV];
    if (tid < NKV) {
        float acc = 0.f;
        const float* xr = x + (size_t)bt * CC;
#pragma unroll
        for (int c = 0; c < 32; c++) acc += xr[c] * Wgate[c * NKV + tid];
        gate[tid] = 2.f / (1.f + expf(-acc));
    }
    __syncthreads();

    for (int i = tid; i < NKV * HD; i += 256) {
        int hh = i >> 6, d = i & 63;
        float vv = qkv[1536 + i] + gate[hh] * ve[(size_t)bt * 512 + i];
        g_vattn[(((size_t)b * NKV + hh) * TT + t) * HD + d] = __float2half(vv);
    }

    const int w = tid >> 5, lane = tid & 31;
    const float cs = cosb[t * 32 + lane];
    const float sn = sinb[t * 32 + lane];
    const float eps = 1.1920929e-07f;
    const float QSCALE = 0.125f * 1.4426950408889634f;   // (1/sqrt(64)) * log2(e)

#pragma unroll
    for (int qi = 0; qi < 2; qi++) {
        int h = 2 * w + qi;
        const float* qr = qkv + h * HD;
        float x1 = qr[lane], x2 = qr[lane + 32];
        float r1 = x1 * cs + x2 * sn;
        float r2 = -x1 * sn + x2 * cs;
        float ss = r1 * r1 + r2 * r2;
#pragma unroll
        for (int o = 16; o; o >>= 1) ss += __shfl_xor_sync(0xffffffffu, ss, o);
        float sc = rsqrtf(ss * (1.f / 64.f) + eps) * QSCALE;
        size_t idx = (((size_t)b * NH + h) * TT + t) * HD;
        g_qattn[idx + lane]      = __float2half(r1 * sc);
        g_qattn[idx + lane + 32] = __float2half(r2 * sc);
    }
    {
        const float* kr = qkv + 1024 + w * HD;
        float x1 = kr[lane], x2 = kr[lane + 32];
        float r1 = x1 * cs + x2 * sn;
        float r2 = -x1 * sn + x2 * cs;
        float ss = r1 * r1 + r2 * r2;
#pragma unroll
        for (int o = 16; o; o >>= 1) ss += __shfl_xor_sync(0xffffffffu, ss, o);
        float sc = rsqrtf(ss * (1.f / 64.f) + eps);
        size_t idx = (((size_t)b * NKV + w) * TT + t) * HD;
        g_kattn[idx + lane]      = __float2half(r1 * sc);
        g_kattn[idx + lane + 32] = __float2half(r2 * sc);
    }
}

// ---------------- tensor-core flash attention (fp16, exp2 softmax) -----------
// BM=64, BN=64, 4 warps. smem: Q@0 (9216), 2 stages {K,V} at 9216+stg*18432.
__global__ __launch_bounds__(128)
void attn_mma(const int* __restrict__ wptr)
{
    extern __shared__ char sm[];
    const uint32_t sb = (uint32_t)__cvta_generic_to_shared(sm);
    const uint32_t sQ = sb;

    const int qt0 = (int)(gridDim.x - 1 - blockIdx.x) * 64;   // heavy blocks first
    const int bh = blockIdx.y;
    const int b = bh >> 4, h = bh & 15;
    const int window = *wptr;
    const bool is_local = (h >= 8);
    const int kvh = is_local ? 4 + ((h - 8) >> 1) : (h >> 1);

    const __half* qb = g_qattn + ((size_t)(b * NH + h) * TT) * HD;
    const __half* kb = g_kattn + ((size_t)(b * NKV + kvh) * TT) * HD;
    const __half* vb = g_vattn + ((size_t)(b * NKV + kvh) * TT) * HD;

    const int tid = threadIdx.x;
    const int lane = tid & 31, wid = tid >> 5;
    const int gid = lane >> 2, tig = lane & 3;
    const int lane15 = lane & 15, lhi8 = (lane >> 4) * 8;
    const int krow = (lane & 7) | ((lane & 16) >> 1);
    const int kc8 = lane & 8;

#define ATT_LOAD(stg, ktv) do { \
    uint32_t base_ = sb + 9216 + (stg) * 18432; \
    for (int c = tid; c < 512; c += 128) { \
        int row_ = c >> 3, c8_ = c & 7; \
        size_t g_ = (size_t)((ktv) + row_) * HD + c8_ * 8; \
        uint32_t d_ = base_ + row_ * 144 + c8_ * 16; \
        CP16(d_, kb + g_); CP16(d_ + 9216, vb + g_); \
    } CP_COMMIT; \
} while (0)

    int t0 = 0;
    if (is_local) { int s = qt0 - window; t0 = (s > 0 ? s : 0) & ~63; }
    const int nt = (qt0 - t0) / 64 + 1;

    for (int c = tid; c < 512; c += 128) {
        int row = c >> 3, c8 = c & 7;
        CP16(sQ + row * 144 + c8 * 16, qb + (size_t)(qt0 + row) * HD + c8 * 8);
    }
    CP_COMMIT;
    ATT_LOAD(0, t0);
    CP_WAIT(1);
    __syncthreads();

    uint32_t qf[4][4];
    {
        const uint32_t qa = (uint32_t)((wid * 16 + lane15) * 144 + lhi8 * 2);
#pragma unroll
        for (int ks = 0; ks < 4; ks++)
            LDSM4(qf[ks][0],qf[ks][1],qf[ks][2],qf[ks][3], sQ + qa + ks * 32);
    }

    float o[8][4];
#pragma unroll
    for (int nf = 0; nf < 8; nf++)
#pragma unroll
        for (int r = 0; r < 4; r++) o[nf][r] = 0.f;
    float m0r = -1e30f, m1r = -1e30f, l0r = 0.f, l1r = 0.f;

    const int i0 = qt0 + wid * 16 + gid, i1 = i0 + 8;

    for (int it = 0; it < nt; it++) {
        const int kt = t0 + it * 64;
        const int stg = it & 1;
        if (it + 1 < nt) { ATT_LOAD(stg ^ 1, kt + 64); CP_WAIT(1); }
        else             { CP_WAIT(0); }
        __syncthreads();

        const uint32_t sK = sb + 9216 + stg * 18432;
        const uint32_t sV = sK + 9216;

        // ---- S = Q K^T   (scores in exp2 domain, pre-scaled)
        float s[8][4];
#pragma unroll
        for (int nf = 0; nf < 8; nf++)
#pragma unroll
            for (int r = 0; r < 4; r++) s[nf][r] = 0.f;
#pragma unroll
        for (int ks = 0; ks < 4; ks++) {
#pragma unroll
            for (int g = 0; g < 4; g++) {
                const uint32_t ka = (uint32_t)((g * 16 + krow) * 144 + (ks * 16 + kc8) * 2);
                uint32_t b0,b1,b2,b3;
                LDSM4(b0,b1,b2,b3, sK + ka);
                MMA16816H(s[2*g],   qf[ks], b0, b1);
                MMA16816H(s[2*g+1], qf[ks], b2, b3);
            }
        }

        // ---- mask only boundary tiles
        const bool need_mask = (kt + 64 > qt0) ||
                               (is_local && kt + window < qt0 + 64);
        if (need_mask) {
#pragma unroll
            for (int nf = 0; nf < 8; nf++) {
                int j0 = kt + nf * 8 + tig * 2, j1 = j0 + 1;
                bool k00 = (j0 <= i0) && (!is_local || j0 >= i0 - window);
                bool k01 = (j1 <= i0) && (!is_local || j1 >= i0 - window);
                bool k10 = (j0 <= i1) && (!is_local || j0 >= i1 - window);
                bool k11 = (j1 <= i1) && (!is_local || j1 >= i1 - window);
                if (!k00) s[nf][0] = -1e30f;
                if (!k01) s[nf][1] = -1e30f;
                if (!k10) s[nf][2] = -1e30f;
                if (!k11) s[nf][3] = -1e30f;
            }
        }

        // ---- online softmax (exp2 domain)
        float t0m = -1e30f, t1m = -1e30f;
#pragma unroll
        for (int nf = 0; nf < 8; nf++) {
            t0m = fmaxf(t0m, fmaxf(s[nf][0], s[nf][1]));
            t1m = fmaxf(t1m, fmaxf(s[nf][2], s[nf][3]));
        }
        t0m = fmaxf(t0m, __shfl_xor_sync(0xffffffffu, t0m, 1));
        t0m = fmaxf(t0m, __shfl_xor_sync(0xffffffffu, t0m, 2));
        t1m = fmaxf(t1m, __shfl_xor_sync(0xffffffffu, t1m, 1));
        t1m = fmaxf(t1m, __shfl_xor_sync(0xffffffffu, t1m, 2));
        float mn0 = fmaxf(m0r, t0m), mn1 = fmaxf(m1r, t1m);
        float cr0 = exp2f(m0r - mn0), cr1 = exp2f(m1r - mn1);
        m0r = mn0; m1r = mn1;

        // rescale o only if any row's max actually grew
        bool upd = (cr0 != 1.f) || (cr1 != 1.f);
        if (__any_sync(0xffffffffu, upd)) {
#pragma unroll
            for (int nf = 0; nf < 8; nf++) {
                o[nf][0] *= cr0; o[nf][1] *= cr0; o[nf][2] *= cr1; o[nf][3] *= cr1;
            }
        }

        // exp2 + packed fp16 P + partial sums, in one pass
        uint32_t pp0[8], pp1[8];
        float ps0 = 0.f, ps1 = 0.f;
#pragma unroll
        for (int nf = 0; nf < 8; nf++) {
            float e0 = exp2f(s[nf][0] - mn0), e1 = exp2f(s[nf][1] - mn0);
            float e2 = exp2f(s[nf][2] - mn1), e3 = exp2f(s[nf][3] - mn1);
            ps0 += e0 + e1; ps1 += e2 + e3;
            CVTF16X2(pp0[nf], e0, e1);
            CVTF16X2(pp1[nf], e2, e3);
        }
        ps0 += __shfl_xor_sync(0xffffffffu, ps0, 1);
        ps0 += __shfl_xor_sync(0xffffffffu, ps0, 2);
        ps1 += __shfl_xor_sync(0xffffffffu, ps1, 1);
        ps1 += __shfl_xor_sync(0xffffffffu, ps1, 2);
        l0r = l0r * cr0 + ps0;
        l1r = l1r * cr1 + ps1;

        // ---- O += P V
#pragma unroll
        for (int ks = 0; ks < 4; ks++) {
            uint32_t pf[4] = { pp0[2*ks], pp1[2*ks], pp0[2*ks+1], pp1[2*ks+1] };
#pragma unroll
            for (int g = 0; g < 4; g++) {
                const uint32_t va = (uint32_t)((ks * 16 + lane15) * 144 + (g * 16 + lhi8) * 2);
                uint32_t v0,v1,v2,v3;
                LDSM4T(v0,v1,v2,v3, sV + va);
                MMA16816H(o[2*g],   pf, v0, v1);
                MMA16816H(o[2*g+1], pf, v2, v3);
            }
        }
        __syncthreads();
    }

    // ---- epilogue: y = O / l -> fp16, layout [bt, h*64+d]
    const float inv0 = 1.f / l0r, inv1 = 1.f / l1r;
    const int row0 = qt0 + wid * 16 + gid;
#pragma unroll
    for (int nf = 0; nf < 8; nf++) {
        const int col = h * 64 + nf * 8 + tig * 2;
        uint32_t u0, u1;
        CVTF16X2(u0, o[nf][0] * inv0, o[nf][1] * inv0);
        CVTF16X2(u1, o[nf][2] * inv1, o[nf][3] * inv1);
        *(uint32_t*)(g_yattn + (size_t)(b * TT + row0) * CC + col) = u0;
        *(uint32_t*)(g_yattn + (size_t)(b * TT + row0 + 8) * CC + col) = u1;
    }
}

// ---------------- launch ------------------------------------------------------
extern "C" void kernel_launch(void* const* d_in, const int* in_sizes, int n_in,
                              void* d_out, int out_size)
{
    const float* x     = (const float*)d_in[0];
    const float* ve    = (const float*)d_in[1];
    const float* cosb  = (const float*)d_in[2];
    const float* sinb  = (const float*)d_in[3];
    const float* Wq    = (const float*)d_in[4];
    const float* Wk    = (const float*)d_in[5];
    const float* Wv    = (const float*)d_in[6];
    const float* Wproj = (const float*)d_in[7];
    const float* Wgate = (const float*)d_in[8];
    const int*   wptr  = (const int*)d_in[9];

    float* qkvbuf;
    cudaGetSymbolAddress((void**)&qkvbuf, g_qkvbuf);
    __half *xh, *wch, *wph, *yh;
    cudaGetSymbolAddress((void**)&xh, g_xh);
    cudaGetSymbolAddress((void**)&wch, g_wch);
    cudaGetSymbolAddress((void**)&wph, g_wph);
    cudaGetSymbolAddress((void**)&yh, g_yattn);

    cudaFuncSetAttribute(gemm_f16, cudaFuncAttributeMaxDynamicSharedMemorySize, 3 * GSTAGE);
    cudaFuncSetAttribute(attn_mma, cudaFuncAttributeMaxDynamicSharedMemorySize, 46080);

    // fused conversion (x, Wq, Wk, Wv, Wproj -> fp16)
    convert_all<<<7168, 256>>>(x, Wq, Wk, Wv, Wproj);

    // fused QKV projection (fp16)
    gemm_f16<<<dim3(16, 32), 256, 3 * GSTAGE>>>(xh, wch, qkvbuf, BT, 2048, CC);

    // gate + ve, rope, rmsnorm -> fp16 q/k/v (q pre-scaled, exp2 domain)
    postproc<<<BT, 256>>>(x, ve, cosb, sinb, Wgate);

    // attention (fp16) -> fp16 y
    attn_mma<<<dim3(TT / 64, BB * NH), 128, 46080>>>(wptr);

    // output projection (fp16) -> d_out
    gemm_f16<<<dim3(8, 32), 256, 3 * GSTAGE>>>(yh, wph, (float*)d_out, BT, 1024, CC);
}

// round 11
// speedup vs baseline: 9.3044x; 1.0304x over previous
#include <cuda_runtime.h>
#include <cuda_fp16.h>
#include <cstdint>

// Problem constants
#define BB 2
#define TT 2048
#define CC 1024
#define NH 16
#define NKV 8
#define HD 64
#define BT (BB*TT)          // 4096

// ---------------- scratch (device globals) ----------------------------------
__device__ float g_qkvbuf[BT * 2048];          // fused [q(1024)|k(512)|v(512)]

__device__ __half g_xh[BT * CC];               // x fp16
__device__ __half g_wch[CC * 2048];            // Wq|Wk|Wv fp16 [K,2048]
__device__ __half g_wph[CC * CC];              // Wproj fp16 [K,N]

__device__ __half g_qattn[BB*NH*TT*HD];        // [b,h,t,d] fp16 (pre-scaled by log2e/8)
__device__ __half g_kattn[BB*NKV*TT*HD];       // [b,kh,t,d]
__device__ __half g_vattn[BB*NKV*TT*HD];
__device__ __half g_yattn[BT * CC];            // attn out fp16 [bt, h*d]

// ---------------- PTX helpers ------------------------------------------------
#define LDSM4(r0,r1,r2,r3,addr) \
    asm volatile("ldmatrix.sync.aligned.m8n8.x4.shared.b16 {%0,%1,%2,%3}, [%4];" \
                 : "=r"(r0),"=r"(r1),"=r"(r2),"=r"(r3) : "r"(addr))
#define LDSM4T(r0,r1,r2,r3,addr) \
    asm volatile("ldmatrix.sync.aligned.m8n8.x4.trans.shared.b16 {%0,%1,%2,%3}, [%4];" \
                 : "=r"(r0),"=r"(r1),"=r"(r2),"=r"(r3) : "r"(addr))
#define MMA16816H(d, a, b0, b1) \
    asm volatile("mma.sync.aligned.m16n8k16.row.col.f32.f16.f16.f32 " \
                 "{%0,%1,%2,%3}, {%4,%5,%6,%7}, {%8,%9}, {%0,%1,%2,%3};" \
                 : "+f"(d[0]),"+f"(d[1]),"+f"(d[2]),"+f"(d[3]) \
                 : "r"(a[0]),"r"(a[1]),"r"(a[2]),"r"(a[3]), "r"(b0),"r"(b1))
#define CP16(dst, src) \
    asm volatile("cp.async.cg.shared.global [%0], [%1], 16;" :: "r"(dst), "l"(src))
#define CP_COMMIT asm volatile("cp.async.commit_group;")
#define CP_WAIT(N) asm volatile("cp.async.wait_group %0;" :: "n"(N))
// pack two f32 -> one f16x2 register (lo = first arg)
#define CVTF16X2(r, lo, hi) \
    asm("cvt.rn.f16x2.f32 %0, %1, %2;" : "=r"(r) : "f"(hi), "f"(lo))
// packed fp16 exp2
#define HEX2(r, a) \
    asm("ex2.approx.f16x2 %0, %1;" : "=r"(r) : "r"(a))

__device__ __forceinline__ uint32_t hpack(__half e0, __half e1) {
    return ((uint32_t)__half_as_ushort(e1) << 16) | (uint32_t)__half_as_ushort(e0);
}
__device__ __forceinline__ uint2 cvt4h(float4 v) {
    uint32_t a, b;
    CVTF16X2(a, v.x, v.y);
    CVTF16X2(b, v.z, v.w);
    return make_uint2(a, b);
}

// ---------------- fused conversion: all fp32 inputs -> fp16 ------------------
__global__ __launch_bounds__(256)
void convert_all(const float* __restrict__ x,  const float* __restrict__ Wq,
                 const float* __restrict__ Wk, const float* __restrict__ Wv,
                 const float* __restrict__ Wp)
{
    const int i4 = blockIdx.x * 256 + threadIdx.x;
    if (i4 < 1048576) {
        *(uint2*)(g_xh + (size_t)i4 * 4) = cvt4h(*(const float4*)(x + (size_t)i4 * 4));
    } else if (i4 < 1310720) {
        int j = (i4 - 1048576) * 4;
        int r = j >> 10, c = j & 1023;
        *(uint2*)(g_wch + (size_t)r * 2048 + c) = cvt4h(*(const float4*)(Wq + j));
    } else if (i4 < 1441792) {
        int j = (i4 - 1310720) * 4;
        int r = j >> 9, c = j & 511;
        *(uint2*)(g_wch + (size_t)r * 2048 + 1024 + c) = cvt4h(*(const float4*)(Wk + j));
    } else if (i4 < 1572864) {
        int j = (i4 - 1441792) * 4;
        int r = j >> 9, c = j & 511;
        *(uint2*)(g_wch + (size_t)r * 2048 + 1536 + c) = cvt4h(*(const float4*)(Wv + j));
    } else {
        int j = (i4 - 1572864) * 4;
        *(uint2*)(g_wph + j) = cvt4h(*(const float4*)(Wp + j));
    }
}

// ---------------- GEMM: C = A @ B, fp16 single, fp32 out ---------------------
#define GSTAGE 18944
// stage: A@0 (128x40x2=10240), B@10240 (32x136x2=8704)

__global__ __launch_bounds__(256)
void gemm_f16(const __half* __restrict__ Ag, const __half* __restrict__ Bg,
              float* __restrict__ C, int M, int N, int K)
{
    extern __shared__ char sm[];
    const int tid = threadIdx.x;
    const int lane = tid & 31, wid = tid >> 5;
    const int warp_m = wid & 1, warp_n = wid >> 1;
    const int gid = lane >> 2, tig = lane & 3;
    const int lane15 = lane & 15, lhi8 = (lane >> 4) * 8;
    const int m0 = blockIdx.y * 128, n0 = blockIdx.x * 128;
    const uint32_t sb = (uint32_t)__cvta_generic_to_shared(sm);

    const int cc0 = tid * 2;
    const int ar = cc0 >> 2, ac = cc0 & 3;
    const int br = cc0 >> 4, bc = cc0 & 15;

    float acc[4][4][4];
#pragma unroll
    for (int i = 0; i < 4; i++)
#pragma unroll
        for (int j = 0; j < 4; j++)
#pragma unroll
            for (int r = 0; r < 4; r++) acc[i][j][r] = 0.f;

#define GEMM_LOAD(stg, k0) do { \
    uint32_t s_ = sb + (stg) * GSTAGE; \
    const __half* p_; \
    p_ = Ag + (size_t)(m0 + ar) * K + (k0) + ac * 8; \
    CP16(s_ + ar*80 + ac*16, p_); CP16(s_ + ar*80 + ac*16 + 16, p_ + 8); \
    p_ = Bg + (size_t)((k0) + br) * N + n0 + bc * 8; \
    CP16(s_ + 10240 + br*272 + bc*16, p_); CP16(s_ + 10240 + br*272 + bc*16 + 16, p_ + 8); \
    CP_COMMIT; \
} while (0)

    const int ktiles = K >> 5;
    GEMM_LOAD(0, 0);
    GEMM_LOAD(1, 32);

    int stg = 0;
    for (int t = 0; t < ktiles; t++) {
        if (t + 1 < ktiles) CP_WAIT(1); else CP_WAIT(0);
        __syncthreads();
        if (t + 2 < ktiles) {
            int ns = stg + 2; if (ns >= 3) ns -= 3;
            GEMM_LOAD(ns, (t + 2) * 32);
        }

        const uint32_t sA = sb + stg * GSTAGE;
        const uint32_t sB = sA + 10240;

#pragma unroll
        for (int ks = 0; ks < 2; ks++) {
            const uint32_t a_off = (uint32_t)((warp_m * 64 + lane15) * 80 + (ks * 16 + lhi8) * 2);
            const uint32_t b_off = (uint32_t)((ks * 16 + lane15) * 272 + (warp_n * 32 + lhi8) * 2);

            uint32_t a[4][4];
            uint32_t bh[2][4];
#pragma unroll
            for (int mf = 0; mf < 4; mf++)
                LDSM4(a[mf][0],a[mf][1],a[mf][2],a[mf][3], sA + a_off + (uint32_t)(mf * 16 * 80));
#pragma unroll
            for (int p = 0; p < 2; p++)
                LDSM4T(bh[p][0],bh[p][1],bh[p][2],bh[p][3], sB + b_off + (uint32_t)(p * 32));
#pragma unroll
            for (int mf = 0; mf < 4; mf++)
#pragma unroll
                for (int nf = 0; nf < 4; nf++) {
                    const int p = nf >> 1, q = (nf & 1) * 2;
                    MMA16816H(acc[mf][nf], a[mf], bh[p][q], bh[p][q+1]);
                }
        }
        stg++; if (stg == 3) stg = 0;
    }

#pragma unroll
    for (int mf = 0; mf < 4; mf++) {
#pragma unroll
        for (int nf = 0; nf < 4; nf++) {
            const int row = m0 + warp_m * 64 + mf * 16 + gid;
            const int col = n0 + warp_n * 32 + nf * 8 + tig * 2;
            *(float2*)&C[(size_t)row * N + col] = make_float2(acc[mf][nf][0], acc[mf][nf][1]);
            *(float2*)&C[(size_t)(row + 8) * N + col] = make_float2(acc[mf][nf][2], acc[mf][nf][3]);
        }
    }
}

// ---------------- postprocess: gate+ve, RoPE, rmsnorm, fp16 out --------------
// q pre-scaled by log2e/8 so attention scores are already in the exp2 domain.
__global__ __launch_bounds__(256)
void postproc(const float* __restrict__ x, const float* __restrict__ ve,
              const float* __restrict__ cosb, const float* __restrict__ sinb,
              const float* __restrict__ Wgate)
{
    const int bt = blockIdx.x;
    const int b = bt >> 11, t = bt & (TT - 1);
    const int tid = threadIdx.x;
    const float* qkv = g_qkvbuf + (size_t)bt * 2048;

    __shared__ float gate[NKV];
    if (tid < NKV) {
        float acc = 0.f;
        const float* xr = x + (size_t)bt * CC;
#pragma unroll
        for (int c = 0; c < 32; c++) acc += xr[c] * Wgate[c * NKV + tid];
        gate[tid] = 2.f / (1.f + expf(-acc));
    }
    __syncthreads();

    for (int i = tid; i < NKV * HD; i += 256) {
        int hh = i >> 6, d = i & 63;
        float vv = qkv[1536 + i] + gate[hh] * ve[(size_t)bt * 512 + i];
        g_vattn[(((size_t)b * NKV + hh) * TT + t) * HD + d] = __float2half(vv);
    }

    const int w = tid >> 5, lane = tid & 31;
    const float cs = cosb[t * 32 + lane];
    const float sn = sinb[t * 32 + lane];
    const float eps = 1.1920929e-07f;
    const float QSCALE = 0.125f * 1.4426950408889634f;   // (1/sqrt(64)) * log2(e)

#pragma unroll
    for (int qi = 0; qi < 2; qi++) {
        int h = 2 * w + qi;
        const float* qr = qkv + h * HD;
        float x1 = qr[lane], x2 = qr[lane + 32];
        float r1 = x1 * cs + x2 * sn;
        float r2 = -x1 * sn + x2 * cs;
        float ss = r1 * r1 + r2 * r2;
#pragma unroll
        for (int o = 16; o; o >>= 1) ss += __shfl_xor_sync(0xffffffffu, ss, o);
        float sc = rsqrtf(ss * (1.f / 64.f) + eps) * QSCALE;
        size_t idx = (((size_t)b * NH + h) * TT + t) * HD;
        g_qattn[idx + lane]      = __float2half(r1 * sc);
        g_qattn[idx + lane + 32] = __float2half(r2 * sc);
    }
    {
        const float* kr = qkv + 1024 + w * HD;
        float x1 = kr[lane], x2 = kr[lane + 32];
        float r1 = x1 * cs + x2 * sn;
        float r2 = -x1 * sn + x2 * cs;
        float ss = r1 * r1 + r2 * r2;
#pragma unroll
        for (int o = 16; o; o >>= 1) ss += __shfl_xor_sync(0xffffffffu, ss, o);
        float sc = rsqrtf(ss * (1.f / 64.f) + eps);
        size_t idx = (((size_t)b * NKV + w) * TT + t) * HD;
        g_kattn[idx + lane]      = __float2half(r1 * sc);
        g_kattn[idx + lane + 32] = __float2half(r2 * sc);
    }
}

// ---------------- tensor-core flash attention (fp16, exp2, l-via-MMA) --------
// BM=64, BN=64, 4 warps. smem: Q@0 (9216), 2 stages {K,V} at 9216+stg*18432,
// ones block (16x16 fp16) @46080.  Total 46592.
__global__ __launch_bounds__(128)
void attn_mma(const int* __restrict__ wptr)
{
    extern __shared__ char sm[];
    const uint32_t sb = (uint32_t)__cvta_generic_to_shared(sm);
    const uint32_t sQ = sb;
    const uint32_t sOnes = sb + 46080;

    const int qt0 = (int)(gridDim.x - 1 - blockIdx.x) * 64;   // heavy blocks first
    const int bh = blockIdx.y;
    const int b = bh >> 4, h = bh & 15;
    const int window = *wptr;
    const bool is_local = (h >= 8);
    const int kvh = is_local ? 4 + ((h - 8) >> 1) : (h >> 1);

    const __half* qb = g_qattn + ((size_t)(b * NH + h) * TT) * HD;
    const __half* kb = g_kattn + ((size_t)(b * NKV + kvh) * TT) * HD;
    const __half* vb = g_vattn + ((size_t)(b * NKV + kvh) * TT) * HD;

    const int tid = threadIdx.x;
    const int lane = tid & 31, wid = tid >> 5;
    const int gid = lane >> 2, tig = lane & 3;
    const int lane15 = lane & 15, lhi8 = (lane >> 4) * 8;
    const int krow = (lane & 7) | ((lane & 16) >> 1);
    const int kc8 = lane & 8;

#define ATT_LOAD(stg, ktv) do { \
    uint32_t base_ = sb + 9216 + (stg) * 18432; \
    for (int c = tid; c < 512; c += 128) { \
        int row_ = c >> 3, c8_ = c & 7; \
        size_t g_ = (size_t)((ktv) + row_) * HD + c8_ * 8; \
        uint32_t d_ = base_ + row_ * 144 + c8_ * 16; \
        CP16(d_, kb + g_); CP16(d_ + 9216, vb + g_); \
    } CP_COMMIT; \
} while (0)

    int t0 = 0;
    if (is_local) { int s = qt0 - window; t0 = (s > 0 ? s : 0) & ~63; }
    const int nt = (qt0 - t0) / 64 + 1;

    // ones block: 16 rows x 16 cols fp16, col 0 = 1.0
    if (tid < 128) {
        int k = tid >> 3, c2 = (tid & 7) * 2;
        uint32_t v = (c2 == 0) ? 0x00003C00u : 0u;   // (1.0h, 0h) or (0,0)
        asm volatile("st.shared.b32 [%0], %1;" :: "r"(sOnes + k * 32 + c2 * 2), "r"(v));
    }

    for (int c = tid; c < 512; c += 128) {
        int row = c >> 3, c8 = c & 7;
        CP16(sQ + row * 144 + c8 * 16, qb + (size_t)(qt0 + row) * HD + c8 * 8);
    }
    CP_COMMIT;
    ATT_LOAD(0, t0);
    CP_WAIT(1);
    __syncthreads();

    uint32_t qf[4][4];
    {
        const uint32_t qa = (uint32_t)((wid * 16 + lane15) * 144 + lhi8 * 2);
#pragma unroll
        for (int ks = 0; ks < 4; ks++)
            LDSM4(qf[ks][0],qf[ks][1],qf[ks][2],qf[ks][3], sQ + qa + ks * 32);
    }
    // ones B-fragment (n=8, k=16), loaded once
    uint32_t ob0, ob1, ob2, ob3;
    LDSM4T(ob0, ob1, ob2, ob3, sOnes + (uint32_t)(lane15 * 32 + lhi8 * 2));
    (void)ob2; (void)ob3;

    float o[8][4];
#pragma unroll
    for (int nf = 0; nf < 8; nf++)
#pragma unroll
        for (int r = 0; r < 4; r++) o[nf][r] = 0.f;
    float ol[4] = {0.f, 0.f, 0.f, 0.f};      // col 0 = row sum l
    float m0r = -1e30f, m1r = -1e30f;

    const int i0 = qt0 + wid * 16 + gid, i1 = i0 + 8;

    for (int it = 0; it < nt; it++) {
        const int kt = t0 + it * 64;
        const int stg = it & 1;
        if (it + 1 < nt) { ATT_LOAD(stg ^ 1, kt + 64); CP_WAIT(1); }
        else             { CP_WAIT(0); }
        __syncthreads();

        const uint32_t sK = sb + 9216 + stg * 18432;
        const uint32_t sV = sK + 9216;

        // ---- S = Q K^T   (scores in exp2 domain, pre-scaled)
        float s[8][4];
#pragma unroll
        for (int nf = 0; nf < 8; nf++)
#pragma unroll
            for (int r = 0; r < 4; r++) s[nf][r] = 0.f;
#pragma unroll
        for (int ks = 0; ks < 4; ks++) {
#pragma unroll
            for (int g = 0; g < 4; g++) {
                const uint32_t ka = (uint32_t)((g * 16 + krow) * 144 + (ks * 16 + kc8) * 2);
                uint32_t b0,b1,b2,b3;
                LDSM4(b0,b1,b2,b3, sK + ka);
                MMA16816H(s[2*g],   qf[ks], b0, b1);
                MMA16816H(s[2*g+1], qf[ks], b2, b3);
            }
        }

        // ---- mask only boundary tiles
        const bool need_mask = (kt + 64 > qt0) ||
                               (is_local && kt + window < qt0 + 64);
        if (need_mask) {
#pragma unroll
            for (int nf = 0; nf < 8; nf++) {
                int j0 = kt + nf * 8 + tig * 2, j1 = j0 + 1;
                bool k00 = (j0 <= i0) && (!is_local || j0 >= i0 - window);
                bool k01 = (j1 <= i0) && (!is_local || j1 >= i0 - window);
                bool k10 = (j0 <= i1) && (!is_local || j0 >= i1 - window);
                bool k11 = (j1 <= i1) && (!is_local || j1 >= i1 - window);
                if (!k00) s[nf][0] = -1e30f;
                if (!k01) s[nf][1] = -1e30f;
                if (!k10) s[nf][2] = -1e30f;
                if (!k11) s[nf][3] = -1e30f;
            }
        }

        // ---- running max
        float t0m = -1e30f, t1m = -1e30f;
#pragma unroll
        for (int nf = 0; nf < 8; nf++) {
            t0m = fmaxf(t0m, fmaxf(s[nf][0], s[nf][1]));
            t1m = fmaxf(t1m, fmaxf(s[nf][2], s[nf][3]));
        }
        t0m = fmaxf(t0m, __shfl_xor_sync(0xffffffffu, t0m, 1));
        t0m = fmaxf(t0m, __shfl_xor_sync(0xffffffffu, t0m, 2));
        t1m = fmaxf(t1m, __shfl_xor_sync(0xffffffffu, t1m, 1));
        t1m = fmaxf(t1m, __shfl_xor_sync(0xffffffffu, t1m, 2));
        float mn0 = fmaxf(m0r, t0m), mn1 = fmaxf(m1r, t1m);
        float cr0 = exp2f(m0r - mn0), cr1 = exp2f(m1r - mn1);
        m0r = mn0; m1r = mn1;

        // rescale O and l only if any row's max actually grew
        bool upd = (cr0 != 1.f) || (cr1 != 1.f);
        if (__any_sync(0xffffffffu, upd)) {
#pragma unroll
            for (int nf = 0; nf < 8; nf++) {
                o[nf][0] *= cr0; o[nf][1] *= cr0; o[nf][2] *= cr1; o[nf][3] *= cr1;
            }
            ol[0] *= cr0; ol[1] *= cr0; ol[2] *= cr1; ol[3] *= cr1;
        }

        // d = s - m (f32), pack to f16x2, exp2 in fp16 -> packed P directly
        uint32_t pp0[8], pp1[8];
#pragma unroll
        for (int nf = 0; nf < 8; nf++) {
            uint32_t d0, d1;
            CVTF16X2(d0, s[nf][0] - mn0, s[nf][1] - mn0);
            CVTF16X2(d1, s[nf][2] - mn1, s[nf][3] - mn1);
            HEX2(pp0[nf], d0);
            HEX2(pp1[nf], d1);
        }

        // ---- O += P V   and   l += P · ones
#pragma unroll
        for (int ks = 0; ks < 4; ks++) {
            uint32_t pf[4] = { pp0[2*ks], pp1[2*ks], pp0[2*ks+1], pp1[2*ks+1] };
#pragma unroll
            for (int g = 0; g < 4; g++) {
                const uint32_t va = (uint32_t)((ks * 16 + lane15) * 144 + (g * 16 + lhi8) * 2);
                uint32_t v0,v1,v2,v3;
                LDSM4T(v0,v1,v2,v3, sV + va);
                MMA16816H(o[2*g],   pf, v0, v1);
                MMA16816H(o[2*g+1], pf, v2, v3);
            }
            MMA16816H(ol, pf, ob0, ob1);
        }
        __syncthreads();
    }

    // ---- epilogue: fetch l (col 0 lives in tig==0 lanes), y = O / l -> fp16
    const float l0 = __shfl_sync(0xffffffffu, ol[0], lane & ~3);
    const float l1 = __shfl_sync(0xffffffffu, ol[2], lane & ~3);
    const float inv0 = 1.f / l0, inv1 = 1.f / l1;
    const int row0 = qt0 + wid * 16 + gid;
#pragma unroll
    for (int nf = 0; nf < 8; nf++) {
        const int col = h * 64 + nf * 8 + tig * 2;
        uint32_t u0, u1;
        CVTF16X2(u0, o[nf][0] * inv0, o[nf][1] * inv0);
        CVTF16X2(u1, o[nf][2] * inv1, o[nf][3] * inv1);
        *(uint32_t*)(g_yattn + (size_t)(b * TT + row0) * CC + col) = u0;
        *(uint32_t*)(g_yattn + (size_t)(b * TT + row0 + 8) * CC + col) = u1;
    }
}

// ---------------- launch ------------------------------------------------------
extern "C" void kernel_launch(void* const* d_in, const int* in_sizes, int n_in,
                              void* d_out, int out_size)
{
    const float* x     = (const float*)d_in[0];
    const float* ve    = (const float*)d_in[1];
    const float* cosb  = (const float*)d_in[2];
    const float* sinb  = (const float*)d_in[3];
    const float* Wq    = (const float*)d_in[4];
    const float* Wk    = (const float*)d_in[5];
    const float* Wv    = (const float*)d_in[6];
    const float* Wproj = (const float*)d_in[7];
    const float* Wgate = (const float*)d_in[8];
    const int*   wptr  = (const int*)d_in[9];

    float* qkvbuf;
    cudaGetSymbolAddress((void**)&qkvbuf, g_qkvbuf);
    __half *xh, *wch, *wph, *yh;
    cudaGetSymbolAddress((void**)&xh, g_xh);
    cudaGetSymbolAddress((void**)&wch, g_wch);
    cudaGetSymbolAddress((void**)&wph, g_wph);
    cudaGetSymbolAddress((void**)&yh, g_yattn);

    cudaFuncSetAttribute(gemm_f16, cudaFuncAttributeMaxDynamicSharedMemorySize, 3 * GSTAGE);
    cudaFuncSetAttribute(attn_mma, cudaFuncAttributeMaxDynamicSharedMemorySize, 46592);

    // fused conversion (x, Wq, Wk, Wv, Wproj -> fp16)
    convert_all<<<7168, 256>>>(x, Wq, Wk, Wv, Wproj);

    // fused QKV projection (fp16)
    gemm_f16<<<dim3(16, 32), 256, 3 * GSTAGE>>>(xh, wch, qkvbuf, BT, 2048, CC);

    // gate + ve, rope, rmsnorm -> fp16 q/k/v (q pre-scaled, exp2 domain)
    postproc<<<BT, 256>>>(x, ve, cosb, sinb, Wgate);

    // attention (fp16) -> fp16 y
    attn_mma<<<dim3(TT / 64, BB * NH), 128, 46592>>>(wptr);

    // output projection (fp16) -> d_out
    gemm_f16<<<dim3(8, 32), 256, 3 * GSTAGE>>>(yh, wph, (float*)d_out, BT, 1024, CC);
}